// round 1
// baseline (speedup 1.0000x reference)
#include <cuda_runtime.h>
#include <cuda_bf16.h>
#include <cstdint>

// Problem constants (shapes fixed by the reference)
#define NMAX   100000
#define EMAX   600000
#define HID    128
#define FIN    128
#define ZDIM   64
#define KDIM   256   // HIDDEN + F_IN

// ---------------- static device scratch (no allocations allowed) -------------
__device__ float g_h   [(size_t)NMAX * HID];   // post-softmax, sender-scaled h
__device__ float g_agg [(size_t)NMAX * HID];   // scatter accumulator
__device__ int   g_sdeg[NMAX];
__device__ int   g_rdeg[NMAX];

// ---------------- degree kernels ---------------------------------------------
__global__ void zero_deg_kernel(int* sdeg, int* rdeg, int n) {
    int t = blockIdx.x * blockDim.x + threadIdx.x;
    if (t < n) { sdeg[t] = 0; rdeg[t] = 0; }
}

__global__ void count_deg_kernel(const int* __restrict__ snd, const int* __restrict__ rcv,
                                 int* sdeg, int* rdeg, int E) {
    int t = blockIdx.x * blockDim.x + threadIdx.x;
    if (t < E) {
        atomicAdd(&sdeg[snd[t]], 1);
        atomicAdd(&rdeg[rcv[t]], 1);
    }
}

// ---------------- zero float buffer ------------------------------------------
__global__ void zero_f4_kernel(float4* a, int n4) {
    int t = blockIdx.x * blockDim.x + threadIdx.x;
    if (t < n4) a[t] = make_float4(0.f, 0.f, 0.f, 0.f);
}

// ---------------- fused dense + relu + softmax + degree scale ----------------
// H[i,:] = softmax(relu(X'[i,:] @ W + b)) * rsqrt(max(out_deg[i],1))
// where X'[i,:] = X[i,:] * rsqrt(max(in_deg[i],1)) if in_deg != nullptr.
// Block: 128 threads (thread j = output column j), ROWS=16 rows per block.
__global__ __launch_bounds__(128) void gc_dense_kernel(
    const float* __restrict__ X, const int* __restrict__ in_deg,
    const float* __restrict__ W, const float* __restrict__ b,
    const int* __restrict__ out_deg, float* __restrict__ H, int n)
{
    extern __shared__ float sm[];
    float* Wsh = sm;               // 128*128
    float* xsh = sm + HID * HID;   // 16*128
    const int ROWS = 16;
    const int j = threadIdx.x;
    const int row0 = blockIdx.x * ROWS;

    // Stage W (64KB) into shared
    #pragma unroll 8
    for (int idx = j; idx < HID * HID; idx += 128) Wsh[idx] = W[idx];

    // Stage input rows (with optional receiver-degree in-scale)
    #pragma unroll
    for (int r = 0; r < ROWS; ++r) {
        int i = row0 + r;
        float v = 0.f;
        if (i < n) {
            v = X[(size_t)i * HID + j];
            if (in_deg) v *= rsqrtf(fmaxf((float)in_deg[i], 1.f));
        }
        xsh[r * HID + j] = v;
    }
    __syncthreads();

    float acc[ROWS];
    #pragma unroll
    for (int r = 0; r < ROWS; ++r) acc[r] = 0.f;

    for (int k = 0; k < HID; k += 4) {
        float w0 = Wsh[(k + 0) * HID + j];
        float w1 = Wsh[(k + 1) * HID + j];
        float w2 = Wsh[(k + 2) * HID + j];
        float w3 = Wsh[(k + 3) * HID + j];
        #pragma unroll
        for (int r = 0; r < ROWS; ++r) {
            const float4 x4 = *reinterpret_cast<const float4*>(&xsh[r * HID + k]);
            acc[r] = fmaf(x4.x, w0, acc[r]);
            acc[r] = fmaf(x4.y, w1, acc[r]);
            acc[r] = fmaf(x4.z, w2, acc[r]);
            acc[r] = fmaf(x4.w, w3, acc[r]);
        }
    }
    __syncthreads();

    // relu(acc + b) back into xsh (inputs no longer needed)
    const float bj = b[j];
    #pragma unroll
    for (int r = 0; r < ROWS; ++r)
        xsh[r * HID + j] = fmaxf(acc[r] + bj, 0.f);
    __syncthreads();

    // Softmax per row + sender-degree out-scale. 4 warps, 4 rows each.
    const int warp = j >> 5, lane = j & 31;
    #pragma unroll
    for (int rr = 0; rr < 4; ++rr) {
        int r = warp * 4 + rr;
        int i = row0 + r;
        if (i >= n) continue;
        float4 v = reinterpret_cast<const float4*>(xsh + r * HID)[lane];
        float mx = fmaxf(fmaxf(v.x, v.y), fmaxf(v.z, v.w));
        #pragma unroll
        for (int o = 16; o; o >>= 1) mx = fmaxf(mx, __shfl_xor_sync(0xffffffffu, mx, o));
        v.x = __expf(v.x - mx); v.y = __expf(v.y - mx);
        v.z = __expf(v.z - mx); v.w = __expf(v.w - mx);
        float sum = v.x + v.y + v.z + v.w;
        #pragma unroll
        for (int o = 16; o; o >>= 1) sum += __shfl_xor_sync(0xffffffffu, sum, o);
        float s = rsqrtf(fmaxf((float)out_deg[i], 1.f)) / sum;
        v.x *= s; v.y *= s; v.z *= s; v.w *= s;
        reinterpret_cast<float4*>(H + (size_t)i * HID)[lane] = v;
    }
}

// ---------------- edge scatter-add (warp per edge, vector red) ----------------
__global__ __launch_bounds__(256) void scatter_kernel(
    const float4* __restrict__ H, const int* __restrict__ snd,
    const int* __restrict__ rcv, float* __restrict__ A, int E)
{
    int gw = (blockIdx.x * blockDim.x + threadIdx.x) >> 5;
    int lane = threadIdx.x & 31;
    if (gw >= E) return;
    int s = __ldg(&snd[gw]);
    int r = __ldg(&rcv[gw]);
    float4 v = H[(size_t)s * 32 + lane];
    float* dst = A + (size_t)r * HID + lane * 4;
    asm volatile("red.global.add.v4.f32 [%0], {%1,%2,%3,%4};"
                 :: "l"(dst), "f"(v.x), "f"(v.y), "f"(v.z), "f"(v.w) : "memory");
}

// ---------------- final: concat + two dense heads -----------------------------
// x[i,:] = [agg[i,:]*rsqrt(max(rdeg,1)), nodes[i,:]]  (256)
// mu = x @ Wmu + bmu ; ls = x @ Wls + bls  -> out[0:N*64]=mu, out[N*64:]=ls
// Block: 256 threads. tid&127 = output column (0..63 mu, 64..127 ls),
// tid>>7 picks which half of the 32-row tile this thread computes.
__global__ __launch_bounds__(256) void final_kernel(
    const float* __restrict__ Hagg, const int* __restrict__ rdeg,
    const float* __restrict__ nodes,
    const float* __restrict__ Wmu, const float* __restrict__ bmu,
    const float* __restrict__ Wls, const float* __restrict__ bls,
    float* __restrict__ out, int n)
{
    extern __shared__ float sm[];
    float* Wsh = sm;                 // 256*128
    float* xsh = sm + KDIM * 128;    // 32*256
    const int ROWS = 32;
    const int tid = threadIdx.x;
    const int j = tid & 127;
    const int half = tid >> 7;
    const int row0 = blockIdx.x * ROWS;

    // Stage combined weight [256 x 128]: cols 0..63 = Wmu, 64..127 = Wls
    for (int idx = tid; idx < KDIM * 128; idx += 256) {
        int k = idx >> 7, c = idx & 127;
        Wsh[idx] = (c < 64) ? Wmu[k * 64 + c] : Wls[k * 64 + (c - 64)];
    }
    // Stage concatenated inputs
    for (int idx = tid; idx < ROWS * KDIM; idx += 256) {
        int r = idx >> 8, k = idx & 255;
        int i = row0 + r;
        float v = 0.f;
        if (i < n) {
            if (k < HID)
                v = Hagg[(size_t)i * HID + k] * rsqrtf(fmaxf((float)rdeg[i], 1.f));
            else
                v = nodes[(size_t)i * FIN + (k - HID)];
        }
        xsh[idx] = v;
    }
    __syncthreads();

    float acc[16];
    #pragma unroll
    for (int r = 0; r < 16; ++r) acc[r] = 0.f;
    const int rbase = half * 16;

    for (int k = 0; k < KDIM; k += 4) {
        float w0 = Wsh[(k + 0) * 128 + j];
        float w1 = Wsh[(k + 1) * 128 + j];
        float w2 = Wsh[(k + 2) * 128 + j];
        float w3 = Wsh[(k + 3) * 128 + j];
        #pragma unroll
        for (int r = 0; r < 16; ++r) {
            const float4 x4 = *reinterpret_cast<const float4*>(&xsh[(rbase + r) * KDIM + k]);
            acc[r] = fmaf(x4.x, w0, acc[r]);
            acc[r] = fmaf(x4.y, w1, acc[r]);
            acc[r] = fmaf(x4.z, w2, acc[r]);
            acc[r] = fmaf(x4.w, w3, acc[r]);
        }
    }

    const float bias = (j < 64) ? bmu[j] : bls[j - 64];
    const size_t base = (j < 64) ? 0 : ((size_t)n * ZDIM);
    const int c = (j < 64) ? j : j - 64;
    #pragma unroll
    for (int r = 0; r < 16; ++r) {
        int i = row0 + rbase + r;
        if (i < n) out[base + (size_t)i * ZDIM + c] = acc[r] + bias;
    }
}

// ---------------- launch ------------------------------------------------------
extern "C" void kernel_launch(void* const* d_in, const int* in_sizes, int n_in,
                              void* d_out, int out_size)
{
    const float* nodes = (const float*)d_in[0];
    const int*   snd   = (const int*)d_in[1];
    const int*   rcv   = (const int*)d_in[2];
    const float* W0    = (const float*)d_in[3];
    const float* b0    = (const float*)d_in[4];
    const float* W1    = (const float*)d_in[5];
    const float* b1    = (const float*)d_in[6];
    const float* Wmu   = (const float*)d_in[7];
    const float* bmu   = (const float*)d_in[8];
    const float* Wls   = (const float*)d_in[9];
    const float* bls   = (const float*)d_in[10];
    float* out = (float*)d_out;

    const int n = in_sizes[0] / FIN;   // 100000
    const int E = in_sizes[1];         // 600000

    float *h, *agg;
    int *sdeg, *rdeg;
    cudaGetSymbolAddress((void**)&h,    g_h);
    cudaGetSymbolAddress((void**)&agg,  g_agg);
    cudaGetSymbolAddress((void**)&sdeg, g_sdeg);
    cudaGetSymbolAddress((void**)&rdeg, g_rdeg);

    const int DENSE_SMEM = (HID * HID + 16 * HID) * (int)sizeof(float);        // 73728
    const int FINAL_SMEM = (KDIM * 128 + 32 * KDIM) * (int)sizeof(float);      // 163840
    cudaFuncSetAttribute(gc_dense_kernel, cudaFuncAttributeMaxDynamicSharedMemorySize, DENSE_SMEM);
    cudaFuncSetAttribute(final_kernel,    cudaFuncAttributeMaxDynamicSharedMemorySize, FINAL_SMEM);

    // degrees
    zero_deg_kernel<<<(n + 255) / 256, 256>>>(sdeg, rdeg, n);
    count_deg_kernel<<<(E + 255) / 256, 256>>>(snd, rcv, sdeg, rdeg, E);

    const int denseBlocks = (n + 15) / 16;
    const int zeroBlocks  = (n * (HID / 4) + 255) / 256;
    const int scatBlocks  = (E * 32 + 255) / 256;

    // layer 1
    gc_dense_kernel<<<denseBlocks, 128, DENSE_SMEM>>>(nodes, nullptr, W0, b0, sdeg, h, n);
    zero_f4_kernel<<<zeroBlocks, 256>>>((float4*)agg, n * (HID / 4));
    scatter_kernel<<<scatBlocks, 256>>>((const float4*)h, snd, rcv, agg, E);

    // layer 2
    gc_dense_kernel<<<denseBlocks, 128, DENSE_SMEM>>>(agg, rdeg, W1, b1, sdeg, h, n);
    zero_f4_kernel<<<zeroBlocks, 256>>>((float4*)agg, n * (HID / 4));
    scatter_kernel<<<scatBlocks, 256>>>((const float4*)h, snd, rcv, agg, E);

    // heads
    final_kernel<<<(n + 31) / 32, 256, FINAL_SMEM>>>(agg, rdeg, nodes,
                                                     Wmu, bmu, Wls, bls, out, n);
}

// round 2
// speedup vs baseline: 1.4842x; 1.4842x over previous
#include <cuda_runtime.h>
#include <cuda_bf16.h>
#include <cstdint>

#define NMAX   100000
#define EMAX   600000
#define HID    128
#define FIN    128
#define ZDIM   64
#define KDIM   256

// ---------------- static device scratch --------------------------------------
__device__ float g_h   [(size_t)NMAX * HID];
__device__ float g_agg [(size_t)NMAX * HID];
__device__ int   g_sdeg[NMAX];
__device__ int   g_rdeg[NMAX];

// ---------------- packed f32x2 helpers ----------------------------------------
__device__ __forceinline__ void fma2(unsigned long long& d,
                                     unsigned long long a,
                                     unsigned long long b) {
    asm("fma.rn.f32x2 %0, %1, %2, %0;" : "+l"(d) : "l"(a), "l"(b));
}
__device__ __forceinline__ unsigned long long pack2(float x, float y) {
    unsigned long long r;
    asm("mov.b64 %0, {%1, %2};" : "=l"(r) : "f"(x), "f"(y));
    return r;
}
__device__ __forceinline__ void unpack2(unsigned long long p, float& x, float& y) {
    asm("mov.b64 {%0, %1}, %2;" : "=f"(x), "=f"(y) : "l"(p));
}

// ---------------- small utility kernels ---------------------------------------
__global__ void zero_deg_kernel(int* sdeg, int* rdeg, int n) {
    int t = blockIdx.x * blockDim.x + threadIdx.x;
    if (t < n) { sdeg[t] = 0; rdeg[t] = 0; }
}
__global__ void count_deg_kernel(const int* __restrict__ snd, const int* __restrict__ rcv,
                                 int* sdeg, int* rdeg, int E) {
    int t = blockIdx.x * blockDim.x + threadIdx.x;
    if (t < E) {
        atomicAdd(&sdeg[snd[t]], 1);
        atomicAdd(&rdeg[rcv[t]], 1);
    }
}
__global__ void zero_f4_kernel(float4* a, int n4) {
    int t = blockIdx.x * blockDim.x + threadIdx.x;
    if (t < n4) a[t] = make_float4(0.f, 0.f, 0.f, 0.f);
}

// ---------------- fused dense + relu + softmax + degree scale -----------------
// Persistent: weights staged once per block, loop over 64-row tiles.
// H[i,:] = softmax(relu((X[i,:]*in_scale) @ W + b)) * rsqrt(max(out_deg[i],1))
// 256 threads: j2 = tid&63 -> cols (2j2, 2j2+1); rg = tid>>6 -> rows rg*16..+15.
// x staged k-major with stride 68 (row pairs = one 64-bit lane for FFMA2).
#define XSTRIDE 68
__global__ __launch_bounds__(256, 2) void gc_dense_kernel(
    const float* __restrict__ X, const int* __restrict__ in_deg,
    const float* __restrict__ W, const float* __restrict__ b,
    const int* __restrict__ out_deg, float* __restrict__ H,
    int n, int tiles)
{
    extern __shared__ float sm[];
    float* Wsh    = sm;                       // 128*128 = 16384
    float* xsh    = sm + HID * HID;           // 128*68  = 8704 (reused as xout 64*128)
    float* sscale = xsh + HID * XSTRIDE;      // 64

    const int tid  = threadIdx.x;
    const int j2   = tid & 63;
    const int rg   = tid >> 6;
    const int rbase = rg * 16;
    const int warp = tid >> 5, lane = tid & 31;

    // stage W once (float4, coalesced)
    for (int idx = tid; idx < HID * HID / 4; idx += 256)
        ((float4*)Wsh)[idx] = ((const float4*)W)[idx];

    const float b0v = b[2 * j2];
    const float b1v = b[2 * j2 + 1];

    for (int t = blockIdx.x; t < tiles; t += gridDim.x) {
        const int row0 = t * 64;
        __syncthreads();   // xsh free from previous tile (and W staged, first iter)

        if (tid < 64) {
            int i = row0 + tid;
            float s = 1.f;
            if (in_deg != nullptr && i < n) s = rsqrtf(fmaxf((float)in_deg[i], 1.f));
            sscale[tid] = s;
        }
        __syncthreads();

        // stage x tile (k-major transpose, stride 68)
        for (int idx = tid; idx < 64 * HID; idx += 256) {
            int k = idx & 127, r = idx >> 7;
            int i = row0 + r;
            float v = 0.f;
            if (i < n) v = X[(size_t)i * HID + k] * sscale[r];
            xsh[k * XSTRIDE + r] = v;
        }
        __syncthreads();

        unsigned long long acc[16];
        #pragma unroll
        for (int q = 0; q < 16; ++q) acc[q] = 0ull;

        #pragma unroll 4
        for (int k = 0; k < HID; ++k) {
            float2 w2 = *(const float2*)(Wsh + k * HID + 2 * j2);
            unsigned long long wa = pack2(w2.x, w2.x);
            unsigned long long wb = pack2(w2.y, w2.y);
            const float* xb = xsh + k * XSTRIDE + rbase;
            #pragma unroll
            for (int q = 0; q < 4; ++q) {
                ulonglong2 xp = *(const ulonglong2*)(xb + 4 * q);
                fma2(acc[q * 4 + 0], xp.x, wa);
                fma2(acc[q * 4 + 1], xp.x, wb);
                fma2(acc[q * 4 + 2], xp.y, wa);
                fma2(acc[q * 4 + 3], xp.y, wb);
            }
        }
        __syncthreads();   // all reads of xsh done before reuse as xout

        // relu(acc + b) -> xout row-major [64][128]
        #pragma unroll
        for (int q = 0; q < 4; ++q) {
            float c0e, c0o, c1e, c1o;
            unpack2(acc[q * 4 + 0], c0e, c0o);
            unpack2(acc[q * 4 + 1], c1e, c1o);
            int r = rbase + 4 * q;
            *(float2*)(xsh + r * HID + 2 * j2) =
                make_float2(fmaxf(c0e + b0v, 0.f), fmaxf(c1e + b1v, 0.f));
            *(float2*)(xsh + (r + 1) * HID + 2 * j2) =
                make_float2(fmaxf(c0o + b0v, 0.f), fmaxf(c1o + b1v, 0.f));
            unpack2(acc[q * 4 + 2], c0e, c0o);
            unpack2(acc[q * 4 + 3], c1e, c1o);
            *(float2*)(xsh + (r + 2) * HID + 2 * j2) =
                make_float2(fmaxf(c0e + b0v, 0.f), fmaxf(c1e + b1v, 0.f));
            *(float2*)(xsh + (r + 3) * HID + 2 * j2) =
                make_float2(fmaxf(c0o + b0v, 0.f), fmaxf(c1o + b1v, 0.f));
        }
        __syncthreads();

        // softmax + out-degree scale: 8 warps x 8 rows
        #pragma unroll
        for (int rr = 0; rr < 8; ++rr) {
            int r = warp * 8 + rr;
            int i = row0 + r;
            if (i >= n) continue;
            float4 v = ((const float4*)(xsh + r * HID))[lane];
            float mx = fmaxf(fmaxf(v.x, v.y), fmaxf(v.z, v.w));
            #pragma unroll
            for (int o = 16; o; o >>= 1) mx = fmaxf(mx, __shfl_xor_sync(0xffffffffu, mx, o));
            v.x = __expf(v.x - mx); v.y = __expf(v.y - mx);
            v.z = __expf(v.z - mx); v.w = __expf(v.w - mx);
            float sum = v.x + v.y + v.z + v.w;
            #pragma unroll
            for (int o = 16; o; o >>= 1) sum += __shfl_xor_sync(0xffffffffu, sum, o);
            float s = rsqrtf(fmaxf((float)out_deg[i], 1.f)) / sum;
            v.x *= s; v.y *= s; v.z *= s; v.w *= s;
            ((float4*)(H + (size_t)i * HID))[lane] = v;
        }
    }
}

// ---------------- edge scatter-add (warp per edge, vector red) ----------------
__global__ __launch_bounds__(256) void scatter_kernel(
    const float4* __restrict__ H, const int* __restrict__ snd,
    const int* __restrict__ rcv, float* __restrict__ A, int E)
{
    int gw = (blockIdx.x * blockDim.x + threadIdx.x) >> 5;
    int lane = threadIdx.x & 31;
    if (gw >= E) return;
    int s = __ldg(&snd[gw]);
    int r = __ldg(&rcv[gw]);
    float4 v = H[(size_t)s * 32 + lane];
    float* dst = A + (size_t)r * HID + lane * 4;
    asm volatile("red.global.add.v4.f32 [%0], {%1,%2,%3,%4};"
                 :: "l"(dst), "f"(v.x), "f"(v.y), "f"(v.z), "f"(v.w) : "memory");
}

// ---------------- final: concat + two dense heads (persistent, FFMA2) ---------
// x[i,:] = [agg[i,:]*rsqrt(max(rdeg,1)), nodes[i,:]] (256)
// combined W [256][128]: cols 0..63 Wmu, 64..127 Wls.
// 256 threads: j2 cols (2j2,2j2+1), rg rows rg*16..+15, tile = 64 rows.
__global__ __launch_bounds__(256, 1) void final_kernel(
    const float* __restrict__ Hagg, const int* __restrict__ rdeg,
    const float* __restrict__ nodes,
    const float* __restrict__ Wmu, const float* __restrict__ bmu,
    const float* __restrict__ Wls, const float* __restrict__ bls,
    float* __restrict__ out, int n, int tiles)
{
    extern __shared__ float sm[];
    float* Wsh    = sm;                         // 256*128 = 32768
    float* xsh    = sm + KDIM * HID;            // 256*68  = 17408
    float* sscale = xsh + KDIM * XSTRIDE;       // 64

    const int tid  = threadIdx.x;
    const int j2   = tid & 63;
    const int rg   = tid >> 6;
    const int rbase = rg * 16;

    // stage combined weights once
    for (int idx = tid; idx < KDIM * HID; idx += 256) {
        int k = idx >> 7, c = idx & 127;
        Wsh[idx] = (c < 64) ? Wmu[k * 64 + c] : Wls[k * 64 + (c - 64)];
    }

    const int   cbase = 2 * j2;                       // combined col of first output
    const bool  is_mu = (cbase < 64);
    const int   cc0   = is_mu ? cbase : cbase - 64;
    const float bias0 = is_mu ? bmu[cc0] : bls[cc0];
    const float bias1 = is_mu ? bmu[cc0 + 1] : bls[cc0 + 1];
    const size_t obase = is_mu ? 0 : (size_t)n * ZDIM;

    for (int t = blockIdx.x; t < tiles; t += gridDim.x) {
        const int row0 = t * 64;
        __syncthreads();

        if (tid < 64) {
            int i = row0 + tid;
            sscale[tid] = (i < n) ? rsqrtf(fmaxf((float)rdeg[i], 1.f)) : 1.f;
        }
        __syncthreads();

        for (int idx = tid; idx < 64 * KDIM; idx += 256) {
            int k = idx & 255, r = idx >> 8;
            int i = row0 + r;
            float v = 0.f;
            if (i < n)
                v = (k < HID) ? Hagg[(size_t)i * HID + k] * sscale[r]
                              : nodes[(size_t)i * FIN + (k - HID)];
            xsh[k * XSTRIDE + r] = v;
        }
        __syncthreads();

        unsigned long long acc[16];
        #pragma unroll
        for (int q = 0; q < 16; ++q) acc[q] = 0ull;

        #pragma unroll 4
        for (int k = 0; k < KDIM; ++k) {
            float2 w2 = *(const float2*)(Wsh + k * HID + 2 * j2);
            unsigned long long wa = pack2(w2.x, w2.x);
            unsigned long long wb = pack2(w2.y, w2.y);
            const float* xb = xsh + k * XSTRIDE + rbase;
            #pragma unroll
            for (int q = 0; q < 4; ++q) {
                ulonglong2 xp = *(const ulonglong2*)(xb + 4 * q);
                fma2(acc[q * 4 + 0], xp.x, wa);
                fma2(acc[q * 4 + 1], xp.x, wb);
                fma2(acc[q * 4 + 2], xp.y, wa);
                fma2(acc[q * 4 + 3], xp.y, wb);
            }
        }

        // write outputs directly to global
        #pragma unroll
        for (int q = 0; q < 4; ++q) {
            float c0e, c0o, c1e, c1o;
            int r = rbase + 4 * q;
            unpack2(acc[q * 4 + 0], c0e, c0o);
            unpack2(acc[q * 4 + 1], c1e, c1o);
            if (row0 + r < n)
                *(float2*)(out + obase + (size_t)(row0 + r) * ZDIM + cc0) =
                    make_float2(c0e + bias0, c1e + bias1);
            if (row0 + r + 1 < n)
                *(float2*)(out + obase + (size_t)(row0 + r + 1) * ZDIM + cc0) =
                    make_float2(c0o + bias0, c1o + bias1);
            unpack2(acc[q * 4 + 2], c0e, c0o);
            unpack2(acc[q * 4 + 3], c1e, c1o);
            if (row0 + r + 2 < n)
                *(float2*)(out + obase + (size_t)(row0 + r + 2) * ZDIM + cc0) =
                    make_float2(c0e + bias0, c1e + bias1);
            if (row0 + r + 3 < n)
                *(float2*)(out + obase + (size_t)(row0 + r + 3) * ZDIM + cc0) =
                    make_float2(c0o + bias0, c1o + bias1);
        }
    }
}

// ---------------- launch ------------------------------------------------------
extern "C" void kernel_launch(void* const* d_in, const int* in_sizes, int n_in,
                              void* d_out, int out_size)
{
    const float* nodes = (const float*)d_in[0];
    const int*   snd   = (const int*)d_in[1];
    const int*   rcv   = (const int*)d_in[2];
    const float* W0    = (const float*)d_in[3];
    const float* b0    = (const float*)d_in[4];
    const float* W1    = (const float*)d_in[5];
    const float* b1    = (const float*)d_in[6];
    const float* Wmu   = (const float*)d_in[7];
    const float* bmu   = (const float*)d_in[8];
    const float* Wls   = (const float*)d_in[9];
    const float* bls   = (const float*)d_in[10];
    float* out = (float*)d_out;

    const int n = in_sizes[0] / FIN;
    const int E = in_sizes[1];

    float *h, *agg;
    int *sdeg, *rdeg;
    cudaGetSymbolAddress((void**)&h,    g_h);
    cudaGetSymbolAddress((void**)&agg,  g_agg);
    cudaGetSymbolAddress((void**)&sdeg, g_sdeg);
    cudaGetSymbolAddress((void**)&rdeg, g_rdeg);

    const int DENSE_SMEM = (HID * HID + HID * XSTRIDE + 64) * (int)sizeof(float);   // 100,608
    const int FINAL_SMEM = (KDIM * HID + KDIM * XSTRIDE + 64) * (int)sizeof(float); // 200,960
    cudaFuncSetAttribute(gc_dense_kernel, cudaFuncAttributeMaxDynamicSharedMemorySize, DENSE_SMEM);
    cudaFuncSetAttribute(final_kernel,    cudaFuncAttributeMaxDynamicSharedMemorySize, FINAL_SMEM);

    const int tiles = (n + 63) / 64;
    const int denseGrid = tiles < 296 ? tiles : 296;
    const int finalGrid = tiles < 148 ? tiles : 148;
    const int zeroBlocks = (n * (HID / 4) + 255) / 256;
    const int scatBlocks = (E * 32 + 255) / 256;

    // degrees
    zero_deg_kernel<<<(n + 255) / 256, 256>>>(sdeg, rdeg, n);
    count_deg_kernel<<<(E + 255) / 256, 256>>>(snd, rcv, sdeg, rdeg, E);

    // layer 1
    gc_dense_kernel<<<denseGrid, 256, DENSE_SMEM>>>(nodes, nullptr, W0, b0, sdeg, h, n, tiles);
    zero_f4_kernel<<<zeroBlocks, 256>>>((float4*)agg, n * (HID / 4));
    scatter_kernel<<<scatBlocks, 256>>>((const float4*)h, snd, rcv, agg, E);

    // layer 2
    gc_dense_kernel<<<denseGrid, 256, DENSE_SMEM>>>(agg, rdeg, W1, b1, sdeg, h, n, tiles);
    zero_f4_kernel<<<zeroBlocks, 256>>>((float4*)agg, n * (HID / 4));
    scatter_kernel<<<scatBlocks, 256>>>((const float4*)h, snd, rcv, agg, E);

    // heads
    final_kernel<<<finalGrid, 256, FINAL_SMEM>>>(agg, rdeg, nodes,
                                                 Wmu, bmu, Wls, bls, out, n, tiles);
}

// round 3
// speedup vs baseline: 1.5501x; 1.0444x over previous
#include <cuda_runtime.h>
#include <cuda_bf16.h>
#include <cstdint>

#define NMAX   100000
#define EMAX   600000
#define HID    128
#define FIN    128
#define ZDIM   64
#define KDIM   256

// ---------------- static device scratch --------------------------------------
__device__ float g_h   [(size_t)NMAX * HID];
__device__ float g_agg [(size_t)NMAX * HID];
__device__ int   g_sdeg[NMAX];
__device__ int   g_rdeg[NMAX];
__device__ int   g_offs[NMAX + 1];
__device__ int   g_cursor[NMAX];
__device__ int   g_csr[EMAX];

// ---------------- packed f32x2 helpers ----------------------------------------
__device__ __forceinline__ void fma2(unsigned long long& d,
                                     unsigned long long a,
                                     unsigned long long b) {
    asm("fma.rn.f32x2 %0, %1, %2, %0;" : "+l"(d) : "l"(a), "l"(b));
}
__device__ __forceinline__ unsigned long long pack2(float x, float y) {
    unsigned long long r;
    asm("mov.b64 %0, {%1, %2};" : "=l"(r) : "f"(x), "f"(y));
    return r;
}
__device__ __forceinline__ void unpack2(unsigned long long p, float& x, float& y) {
    asm("mov.b64 {%0, %1}, %2;" : "=f"(x), "=f"(y) : "l"(p));
}

// ---------------- degree / CSR build kernels -----------------------------------
__global__ void zero_deg_kernel(int* sdeg, int* rdeg, int n) {
    int t = blockIdx.x * blockDim.x + threadIdx.x;
    if (t < n) { sdeg[t] = 0; rdeg[t] = 0; }
}
__global__ void count_deg_kernel(const int* __restrict__ snd, const int* __restrict__ rcv,
                                 int* sdeg, int* rdeg, int E) {
    int t = blockIdx.x * blockDim.x + threadIdx.x;
    if (t < E) {
        atomicAdd(&sdeg[snd[t]], 1);
        atomicAdd(&rdeg[rcv[t]], 1);
    }
}

// Single-block exclusive scan of rdeg -> offs (and cursor copy). 1024 threads,
// 4096 elements per chunk.
__global__ __launch_bounds__(1024) void scan_kernel(
    const int* __restrict__ deg, int* __restrict__ offs, int* __restrict__ cursor, int n)
{
    __shared__ int warpsum[32];
    __shared__ int carry_sh;
    const int tid = threadIdx.x, lane = tid & 31, warp = tid >> 5;
    int carry = 0;

    for (int base = 0; base < n; base += 4096) {
        int idx = base + tid * 4;
        int4 v = make_int4(0, 0, 0, 0);
        if (idx + 3 < n) v = *(const int4*)(deg + idx);
        else {
            if (idx     < n) v.x = deg[idx];
            if (idx + 1 < n) v.y = deg[idx + 1];
            if (idx + 2 < n) v.z = deg[idx + 2];
        }
        int s0 = v.x, s1 = s0 + v.y, s2 = s1 + v.z, s3 = s2 + v.w;
        int inc = s3;
        #pragma unroll
        for (int o = 1; o < 32; o <<= 1) {
            int t = __shfl_up_sync(0xffffffffu, inc, o);
            if (lane >= o) inc += t;
        }
        if (lane == 31) warpsum[warp] = inc;
        __syncthreads();
        if (warp == 0) {
            int w = warpsum[lane];
            int wi = w;
            #pragma unroll
            for (int o = 1; o < 32; o <<= 1) {
                int t = __shfl_up_sync(0xffffffffu, wi, o);
                if (lane >= o) wi += t;
            }
            warpsum[lane] = wi - w;   // exclusive
        }
        __syncthreads();
        int texcl = carry + warpsum[warp] + inc - s3;
        int4 o4 = make_int4(texcl, texcl + s0, texcl + s1, texcl + s2);
        if (idx + 3 < n) {
            *(int4*)(offs + idx)   = o4;
            *(int4*)(cursor + idx) = o4;
        } else {
            if (idx     < n) { offs[idx]     = o4.x; cursor[idx]     = o4.x; }
            if (idx + 1 < n) { offs[idx + 1] = o4.y; cursor[idx + 1] = o4.y; }
            if (idx + 2 < n) { offs[idx + 2] = o4.z; cursor[idx + 2] = o4.z; }
        }
        if (tid == 1023) carry_sh = texcl + s3;
        __syncthreads();
        carry = carry_sh;
    }
    if (tid == 0) offs[n] = carry;
}

__global__ void fill_kernel(const int* __restrict__ snd, const int* __restrict__ rcv,
                            int* cursor, int* __restrict__ csr, int E)
{
    int t = blockIdx.x * blockDim.x + threadIdx.x;
    if (t < E) {
        int r = rcv[t];
        int p = atomicAdd(&cursor[r], 1);
        csr[p] = snd[t];
    }
}

// ---------------- fused dense + relu + softmax + degree scale -----------------
#define XSTRIDE 68
__global__ __launch_bounds__(256, 2) void gc_dense_kernel(
    const float* __restrict__ X, const int* __restrict__ in_deg,
    const float* __restrict__ W, const float* __restrict__ b,
    const int* __restrict__ out_deg, float* __restrict__ H,
    int n, int tiles)
{
    extern __shared__ float sm[];
    float* Wsh    = sm;                       // 128*128
    float* xsh    = sm + HID * HID;           // 128*68 (reused as xout 64*128)
    float* sscale = xsh + HID * XSTRIDE;      // 64

    const int tid  = threadIdx.x;
    const int j2   = tid & 63;
    const int rg   = tid >> 6;
    const int rbase = rg * 16;
    const int warp = tid >> 5, lane = tid & 31;

    for (int idx = tid; idx < HID * HID / 4; idx += 256)
        ((float4*)Wsh)[idx] = ((const float4*)W)[idx];

    const float b0v = b[2 * j2];
    const float b1v = b[2 * j2 + 1];

    for (int t = blockIdx.x; t < tiles; t += gridDim.x) {
        const int row0 = t * 64;
        __syncthreads();

        if (tid < 64) {
            int i = row0 + tid;
            float s = 1.f;
            if (in_deg != nullptr && i < n) s = rsqrtf(fmaxf((float)in_deg[i], 1.f));
            sscale[tid] = s;
        }
        __syncthreads();

        for (int idx = tid; idx < 64 * HID; idx += 256) {
            int k = idx & 127, r = idx >> 7;
            int i = row0 + r;
            float v = 0.f;
            if (i < n) v = X[(size_t)i * HID + k] * sscale[r];
            xsh[k * XSTRIDE + r] = v;
        }
        __syncthreads();

        unsigned long long acc[16];
        #pragma unroll
        for (int q = 0; q < 16; ++q) acc[q] = 0ull;

        #pragma unroll 4
        for (int k = 0; k < HID; ++k) {
            float2 w2 = *(const float2*)(Wsh + k * HID + 2 * j2);
            unsigned long long wa = pack2(w2.x, w2.x);
            unsigned long long wb = pack2(w2.y, w2.y);
            const float* xb = xsh + k * XSTRIDE + rbase;
            #pragma unroll
            for (int q = 0; q < 4; ++q) {
                ulonglong2 xp = *(const ulonglong2*)(xb + 4 * q);
                fma2(acc[q * 4 + 0], xp.x, wa);
                fma2(acc[q * 4 + 1], xp.x, wb);
                fma2(acc[q * 4 + 2], xp.y, wa);
                fma2(acc[q * 4 + 3], xp.y, wb);
            }
        }
        __syncthreads();

        #pragma unroll
        for (int q = 0; q < 4; ++q) {
            float c0e, c0o, c1e, c1o;
            unpack2(acc[q * 4 + 0], c0e, c0o);
            unpack2(acc[q * 4 + 1], c1e, c1o);
            int r = rbase + 4 * q;
            *(float2*)(xsh + r * HID + 2 * j2) =
                make_float2(fmaxf(c0e + b0v, 0.f), fmaxf(c1e + b1v, 0.f));
            *(float2*)(xsh + (r + 1) * HID + 2 * j2) =
                make_float2(fmaxf(c0o + b0v, 0.f), fmaxf(c1o + b1v, 0.f));
            unpack2(acc[q * 4 + 2], c0e, c0o);
            unpack2(acc[q * 4 + 3], c1e, c1o);
            *(float2*)(xsh + (r + 2) * HID + 2 * j2) =
                make_float2(fmaxf(c0e + b0v, 0.f), fmaxf(c1e + b1v, 0.f));
            *(float2*)(xsh + (r + 3) * HID + 2 * j2) =
                make_float2(fmaxf(c0o + b0v, 0.f), fmaxf(c1o + b1v, 0.f));
        }
        __syncthreads();

        #pragma unroll
        for (int rr = 0; rr < 8; ++rr) {
            int r = warp * 8 + rr;
            int i = row0 + r;
            if (i >= n) continue;
            float4 v = ((const float4*)(xsh + r * HID))[lane];
            float mx = fmaxf(fmaxf(v.x, v.y), fmaxf(v.z, v.w));
            #pragma unroll
            for (int o = 16; o; o >>= 1) mx = fmaxf(mx, __shfl_xor_sync(0xffffffffu, mx, o));
            v.x = __expf(v.x - mx); v.y = __expf(v.y - mx);
            v.z = __expf(v.z - mx); v.w = __expf(v.w - mx);
            float sum = v.x + v.y + v.z + v.w;
            #pragma unroll
            for (int o = 16; o; o >>= 1) sum += __shfl_xor_sync(0xffffffffu, sum, o);
            float s = rsqrtf(fmaxf((float)out_deg[i], 1.f)) / sum;
            v.x *= s; v.y *= s; v.z *= s; v.w *= s;
            ((float4*)(H + (size_t)i * HID))[lane] = v;
        }
    }
}

// ---------------- CSR gather-aggregate (warp per receiver) --------------------
__global__ __launch_bounds__(256) void gather_kernel(
    const float4* __restrict__ H, const int* __restrict__ offs,
    const int* __restrict__ csr, float4* __restrict__ A, int n)
{
    int w = (blockIdx.x * blockDim.x + threadIdx.x) >> 5;
    int lane = threadIdx.x & 31;
    if (w >= n) return;
    int beg = __ldg(&offs[w]);
    int end = __ldg(&offs[w + 1]);
    float4 acc = make_float4(0.f, 0.f, 0.f, 0.f);
    int e = beg;
    for (; e + 1 < end; e += 2) {
        int s0 = __ldg(&csr[e]);
        int s1 = __ldg(&csr[e + 1]);
        float4 a = H[(size_t)s0 * 32 + lane];
        float4 c = H[(size_t)s1 * 32 + lane];
        acc.x += a.x + c.x; acc.y += a.y + c.y;
        acc.z += a.z + c.z; acc.w += a.w + c.w;
    }
    if (e < end) {
        int s = __ldg(&csr[e]);
        float4 a = H[(size_t)s * 32 + lane];
        acc.x += a.x; acc.y += a.y; acc.z += a.z; acc.w += a.w;
    }
    A[(size_t)w * 32 + lane] = acc;
}

// ---------------- final: concat + two dense heads (persistent, FFMA2) ---------
__global__ __launch_bounds__(256, 1) void final_kernel(
    const float* __restrict__ Hagg, const int* __restrict__ rdeg,
    const float* __restrict__ nodes,
    const float* __restrict__ Wmu, const float* __restrict__ bmu,
    const float* __restrict__ Wls, const float* __restrict__ bls,
    float* __restrict__ out, int n, int tiles)
{
    extern __shared__ float sm[];
    float* Wsh    = sm;                         // 256*128
    float* xsh    = sm + KDIM * HID;            // 256*68
    float* sscale = xsh + KDIM * XSTRIDE;       // 64

    const int tid  = threadIdx.x;
    const int j2   = tid & 63;
    const int rg   = tid >> 6;
    const int rbase = rg * 16;

    for (int idx = tid; idx < KDIM * HID; idx += 256) {
        int k = idx >> 7, c = idx & 127;
        Wsh[idx] = (c < 64) ? Wmu[k * 64 + c] : Wls[k * 64 + (c - 64)];
    }

    const int   cbase = 2 * j2;
    const bool  is_mu = (cbase < 64);
    const int   cc0   = is_mu ? cbase : cbase - 64;
    const float bias0 = is_mu ? bmu[cc0] : bls[cc0];
    const float bias1 = is_mu ? bmu[cc0 + 1] : bls[cc0 + 1];
    const size_t obase = is_mu ? 0 : (size_t)n * ZDIM;

    for (int t = blockIdx.x; t < tiles; t += gridDim.x) {
        const int row0 = t * 64;
        __syncthreads();

        if (tid < 64) {
            int i = row0 + tid;
            sscale[tid] = (i < n) ? rsqrtf(fmaxf((float)rdeg[i], 1.f)) : 1.f;
        }
        __syncthreads();

        for (int idx = tid; idx < 64 * KDIM; idx += 256) {
            int k = idx & 255, r = idx >> 8;
            int i = row0 + r;
            float v = 0.f;
            if (i < n)
                v = (k < HID) ? Hagg[(size_t)i * HID + k] * sscale[r]
                              : nodes[(size_t)i * FIN + (k - HID)];
            xsh[k * XSTRIDE + r] = v;
        }
        __syncthreads();

        unsigned long long acc[16];
        #pragma unroll
        for (int q = 0; q < 16; ++q) acc[q] = 0ull;

        #pragma unroll 4
        for (int k = 0; k < KDIM; ++k) {
            float2 w2 = *(const float2*)(Wsh + k * HID + 2 * j2);
            unsigned long long wa = pack2(w2.x, w2.x);
            unsigned long long wb = pack2(w2.y, w2.y);
            const float* xb = xsh + k * XSTRIDE + rbase;
            #pragma unroll
            for (int q = 0; q < 4; ++q) {
                ulonglong2 xp = *(const ulonglong2*)(xb + 4 * q);
                fma2(acc[q * 4 + 0], xp.x, wa);
                fma2(acc[q * 4 + 1], xp.x, wb);
                fma2(acc[q * 4 + 2], xp.y, wa);
                fma2(acc[q * 4 + 3], xp.y, wb);
            }
        }

        #pragma unroll
        for (int q = 0; q < 4; ++q) {
            float c0e, c0o, c1e, c1o;
            int r = rbase + 4 * q;
            unpack2(acc[q * 4 + 0], c0e, c0o);
            unpack2(acc[q * 4 + 1], c1e, c1o);
            if (row0 + r < n)
                *(float2*)(out + obase + (size_t)(row0 + r) * ZDIM + cc0) =
                    make_float2(c0e + bias0, c1e + bias1);
            if (row0 + r + 1 < n)
                *(float2*)(out + obase + (size_t)(row0 + r + 1) * ZDIM + cc0) =
                    make_float2(c0o + bias0, c1o + bias1);
            unpack2(acc[q * 4 + 2], c0e, c0o);
            unpack2(acc[q * 4 + 3], c1e, c1o);
            if (row0 + r + 2 < n)
                *(float2*)(out + obase + (size_t)(row0 + r + 2) * ZDIM + cc0) =
                    make_float2(c0e + bias0, c1e + bias1);
            if (row0 + r + 3 < n)
                *(float2*)(out + obase + (size_t)(row0 + r + 3) * ZDIM + cc0) =
                    make_float2(c0o + bias0, c1o + bias1);
        }
    }
}

// ---------------- launch ------------------------------------------------------
extern "C" void kernel_launch(void* const* d_in, const int* in_sizes, int n_in,
                              void* d_out, int out_size)
{
    const float* nodes = (const float*)d_in[0];
    const int*   snd   = (const int*)d_in[1];
    const int*   rcv   = (const int*)d_in[2];
    const float* W0    = (const float*)d_in[3];
    const float* b0    = (const float*)d_in[4];
    const float* W1    = (const float*)d_in[5];
    const float* b1    = (const float*)d_in[6];
    const float* Wmu   = (const float*)d_in[7];
    const float* bmu   = (const float*)d_in[8];
    const float* Wls   = (const float*)d_in[9];
    const float* bls   = (const float*)d_in[10];
    float* out = (float*)d_out;

    const int n = in_sizes[0] / FIN;
    const int E = in_sizes[1];

    float *h, *agg;
    int *sdeg, *rdeg, *offs, *cursor, *csr;
    cudaGetSymbolAddress((void**)&h,      g_h);
    cudaGetSymbolAddress((void**)&agg,    g_agg);
    cudaGetSymbolAddress((void**)&sdeg,   g_sdeg);
    cudaGetSymbolAddress((void**)&rdeg,   g_rdeg);
    cudaGetSymbolAddress((void**)&offs,   g_offs);
    cudaGetSymbolAddress((void**)&cursor, g_cursor);
    cudaGetSymbolAddress((void**)&csr,    g_csr);

    const int DENSE_SMEM = (HID * HID + HID * XSTRIDE + 64) * (int)sizeof(float);
    const int FINAL_SMEM = (KDIM * HID + KDIM * XSTRIDE + 64) * (int)sizeof(float);
    cudaFuncSetAttribute(gc_dense_kernel, cudaFuncAttributeMaxDynamicSharedMemorySize, DENSE_SMEM);
    cudaFuncSetAttribute(final_kernel,    cudaFuncAttributeMaxDynamicSharedMemorySize, FINAL_SMEM);

    const int tiles = (n + 63) / 64;
    const int denseGrid = tiles < 296 ? tiles : 296;
    const int finalGrid = tiles < 148 ? tiles : 148;
    const int gatherBlocks = (n * 32 + 255) / 256;

    // CSR build (degrees + offsets + edge lists)
    zero_deg_kernel<<<(n + 255) / 256, 256>>>(sdeg, rdeg, n);
    count_deg_kernel<<<(E + 255) / 256, 256>>>(snd, rcv, sdeg, rdeg, E);
    scan_kernel<<<1, 1024>>>(rdeg, offs, cursor, n);
    fill_kernel<<<(E + 255) / 256, 256>>>(snd, rcv, cursor, csr, E);

    // layer 1
    gc_dense_kernel<<<denseGrid, 256, DENSE_SMEM>>>(nodes, nullptr, W0, b0, sdeg, h, n, tiles);
    gather_kernel<<<gatherBlocks, 256>>>((const float4*)h, offs, csr, (float4*)agg, n);

    // layer 2
    gc_dense_kernel<<<denseGrid, 256, DENSE_SMEM>>>(agg, rdeg, W1, b1, sdeg, h, n, tiles);
    gather_kernel<<<gatherBlocks, 256>>>((const float4*)h, offs, csr, (float4*)agg, n);

    // heads
    final_kernel<<<finalGrid, 256, FINAL_SMEM>>>(agg, rdeg, nodes,
                                                 Wmu, bmu, Wls, bls, out, n, tiles);
}

// round 4
// speedup vs baseline: 2.0982x; 1.3536x over previous
#include <cuda_runtime.h>
#include <cuda_bf16.h>
#include <cstdint>

#define NMAX   100000
#define EMAX   600000
#define HID    128
#define FIN    128
#define ZDIM   64
#define KDIM   256
#define XSTRIDE 68

// ---------------- static device scratch --------------------------------------
__device__ float g_h   [(size_t)NMAX * HID];
__device__ int   g_sdeg[NMAX];
__device__ int   g_rdeg[NMAX];
__device__ int   g_offs[NMAX + 1];
__device__ int   g_cursor[NMAX];
__device__ int   g_csr[EMAX];

// ---------------- packed f32x2 helpers ----------------------------------------
__device__ __forceinline__ void fma2(unsigned long long& d,
                                     unsigned long long a,
                                     unsigned long long b) {
    asm("fma.rn.f32x2 %0, %1, %2, %0;" : "+l"(d) : "l"(a), "l"(b));
}
__device__ __forceinline__ void add2(unsigned long long& d, unsigned long long a) {
    asm("add.rn.f32x2 %0, %0, %1;" : "+l"(d) : "l"(a));
}
__device__ __forceinline__ void mul2(unsigned long long& d, unsigned long long a) {
    asm("mul.rn.f32x2 %0, %0, %1;" : "+l"(d) : "l"(a));
}
__device__ __forceinline__ unsigned long long pack2(float x, float y) {
    unsigned long long r;
    asm("mov.b64 %0, {%1, %2};" : "=l"(r) : "f"(x), "f"(y));
    return r;
}
__device__ __forceinline__ void unpack2(unsigned long long p, float& x, float& y) {
    asm("mov.b64 {%0, %1}, %2;" : "=f"(x), "=f"(y) : "l"(p));
}

// ---------------- degree / CSR build kernels -----------------------------------
__global__ void zero_deg_kernel(int* sdeg, int* rdeg, int n) {
    int t = blockIdx.x * blockDim.x + threadIdx.x;
    if (t < n) { sdeg[t] = 0; rdeg[t] = 0; }
}
__global__ void count_deg_kernel(const int* __restrict__ snd, const int* __restrict__ rcv,
                                 int* sdeg, int* rdeg, int E) {
    int t = blockIdx.x * blockDim.x + threadIdx.x;
    if (t < E) {
        atomicAdd(&sdeg[snd[t]], 1);
        atomicAdd(&rdeg[rcv[t]], 1);
    }
}

// Single-block exclusive scan of rdeg -> offs (and cursor copy).
__global__ __launch_bounds__(1024) void scan_kernel(
    const int* __restrict__ deg, int* __restrict__ offs, int* __restrict__ cursor, int n)
{
    __shared__ int warpsum[32];
    __shared__ int carry_sh;
    const int tid = threadIdx.x, lane = tid & 31, warp = tid >> 5;
    int carry = 0;

    for (int base = 0; base < n; base += 4096) {
        int idx = base + tid * 4;
        int4 v = make_int4(0, 0, 0, 0);
        if (idx + 3 < n) v = *(const int4*)(deg + idx);
        else {
            if (idx     < n) v.x = deg[idx];
            if (idx + 1 < n) v.y = deg[idx + 1];
            if (idx + 2 < n) v.z = deg[idx + 2];
        }
        int s0 = v.x, s1 = s0 + v.y, s2 = s1 + v.z, s3 = s2 + v.w;
        int inc = s3;
        #pragma unroll
        for (int o = 1; o < 32; o <<= 1) {
            int t = __shfl_up_sync(0xffffffffu, inc, o);
            if (lane >= o) inc += t;
        }
        if (lane == 31) warpsum[warp] = inc;
        __syncthreads();
        if (warp == 0) {
            int w = warpsum[lane];
            int wi = w;
            #pragma unroll
            for (int o = 1; o < 32; o <<= 1) {
                int t = __shfl_up_sync(0xffffffffu, wi, o);
                if (lane >= o) wi += t;
            }
            warpsum[lane] = wi - w;
        }
        __syncthreads();
        int texcl = carry + warpsum[warp] + inc - s3;
        int4 o4 = make_int4(texcl, texcl + s0, texcl + s1, texcl + s2);
        if (idx + 3 < n) {
            *(int4*)(offs + idx)   = o4;
            *(int4*)(cursor + idx) = o4;
        } else {
            if (idx     < n) { offs[idx]     = o4.x; cursor[idx]     = o4.x; }
            if (idx + 1 < n) { offs[idx + 1] = o4.y; cursor[idx + 1] = o4.y; }
            if (idx + 2 < n) { offs[idx + 2] = o4.z; cursor[idx + 2] = o4.z; }
        }
        if (tid == 1023) carry_sh = texcl + s3;
        __syncthreads();
        carry = carry_sh;
    }
    if (tid == 0) offs[n] = carry;
}

__global__ void fill_kernel(const int* __restrict__ snd, const int* __restrict__ rcv,
                            int* cursor, int* __restrict__ csr, int E)
{
    int t = blockIdx.x * blockDim.x + threadIdx.x;
    if (t < E) {
        int r = rcv[t];
        int p = atomicAdd(&cursor[r], 1);
        csr[p] = snd[t];
    }
}

// ---------------- fused gather + transpose-stage into shared -------------------
// Aggregates CSR sender rows of H (row = 128 floats) for 64 tile rows, scales by
// rsqrt(max(deg,1)), writes k-major into xsh[(kofs+k)*XSTRIDE + r].
// warp covers rows warp*8 .. warp*8+7 (lane>>2), lane&3 covers 32 contiguous cols.
__device__ __forceinline__ void stage_gather(
    const ulonglong2* __restrict__ H2, const int* __restrict__ offs,
    const int* __restrict__ csr, float* xsh,
    int row0, int n, int warp, int lane, int kofs)
{
    const int r_sub = lane >> 2;
    const int cseg  = lane & 3;
    const int r = warp * 8 + r_sub;
    const int i = row0 + r;

    unsigned long long acc2[16];
    #pragma unroll
    for (int q = 0; q < 16; ++q) acc2[q] = 0ull;

    if (i < n) {
        int beg = __ldg(&offs[i]);
        int end = __ldg(&offs[i + 1]);
        for (int e = beg; e < end; ++e) {
            int s = __ldg(&csr[e]);
            const ulonglong2* hp = H2 + (size_t)s * 32 + cseg * 8;
            #pragma unroll
            for (int q = 0; q < 8; ++q) {
                ulonglong2 v = hp[q];
                add2(acc2[2 * q],     v.x);
                add2(acc2[2 * q + 1], v.y);
            }
        }
        float scl = rsqrtf(fmaxf((float)(end - beg), 1.f));
        unsigned long long s2 = pack2(scl, scl);
        #pragma unroll
        for (int q = 0; q < 16; ++q) mul2(acc2[q], s2);
    }

    #pragma unroll
    for (int q = 0; q < 16; ++q) {
        float x0, x1;
        unpack2(acc2[q], x0, x1);
        int k = kofs + cseg * 32 + 2 * q;
        xsh[(size_t)k * XSTRIDE + r]       = x0;
        xsh[(size_t)(k + 1) * XSTRIDE + r] = x1;
    }
}

// ---------------- fused dense + relu + softmax + degree scale -----------------
// If csr != null: input rows are gathered on the fly (X = h buffer).
__global__ __launch_bounds__(256, 2) void gc_dense_kernel(
    const float* __restrict__ X,
    const int* __restrict__ offs, const int* __restrict__ csr,
    const float* __restrict__ W, const float* __restrict__ b,
    const int* __restrict__ out_deg, float* __restrict__ H,
    int n, int tiles)
{
    extern __shared__ float sm[];
    float* Wsh = sm;                 // 128*128
    float* xsh = sm + HID * HID;     // 128*68 (reused as xout 64*128)

    const int tid  = threadIdx.x;
    const int j2   = tid & 63;
    const int rg   = tid >> 6;
    const int rbase = rg * 16;
    const int warp = tid >> 5, lane = tid & 31;

    for (int idx = tid; idx < HID * HID / 4; idx += 256)
        ((float4*)Wsh)[idx] = ((const float4*)W)[idx];

    const float b0v = b[2 * j2];
    const float b1v = b[2 * j2 + 1];

    for (int t = blockIdx.x; t < tiles; t += gridDim.x) {
        const int row0 = t * 64;
        __syncthreads();

        if (csr) {
            stage_gather((const ulonglong2*)X, offs, csr, xsh, row0, n, warp, lane, 0);
        } else {
            for (int idx = tid; idx < 64 * HID; idx += 256) {
                int k = idx & 127, r = idx >> 7;
                int i = row0 + r;
                xsh[k * XSTRIDE + r] = (i < n) ? X[(size_t)i * HID + k] : 0.f;
            }
        }
        __syncthreads();

        unsigned long long acc[16];
        #pragma unroll
        for (int q = 0; q < 16; ++q) acc[q] = 0ull;

        #pragma unroll 4
        for (int k = 0; k < HID; ++k) {
            float2 w2 = *(const float2*)(Wsh + k * HID + 2 * j2);
            unsigned long long wa = pack2(w2.x, w2.x);
            unsigned long long wb = pack2(w2.y, w2.y);
            const float* xb = xsh + k * XSTRIDE + rbase;
            #pragma unroll
            for (int q = 0; q < 4; ++q) {
                ulonglong2 xp = *(const ulonglong2*)(xb + 4 * q);
                fma2(acc[q * 4 + 0], xp.x, wa);
                fma2(acc[q * 4 + 1], xp.x, wb);
                fma2(acc[q * 4 + 2], xp.y, wa);
                fma2(acc[q * 4 + 3], xp.y, wb);
            }
        }
        __syncthreads();

        #pragma unroll
        for (int q = 0; q < 4; ++q) {
            float c0e, c0o, c1e, c1o;
            unpack2(acc[q * 4 + 0], c0e, c0o);
            unpack2(acc[q * 4 + 1], c1e, c1o);
            int r = rbase + 4 * q;
            *(float2*)(xsh + r * HID + 2 * j2) =
                make_float2(fmaxf(c0e + b0v, 0.f), fmaxf(c1e + b1v, 0.f));
            *(float2*)(xsh + (r + 1) * HID + 2 * j2) =
                make_float2(fmaxf(c0o + b0v, 0.f), fmaxf(c1o + b1v, 0.f));
            unpack2(acc[q * 4 + 2], c0e, c0o);
            unpack2(acc[q * 4 + 3], c1e, c1o);
            *(float2*)(xsh + (r + 2) * HID + 2 * j2) =
                make_float2(fmaxf(c0e + b0v, 0.f), fmaxf(c1e + b1v, 0.f));
            *(float2*)(xsh + (r + 3) * HID + 2 * j2) =
                make_float2(fmaxf(c0o + b0v, 0.f), fmaxf(c1o + b1v, 0.f));
        }
        __syncthreads();

        #pragma unroll
        for (int rr = 0; rr < 8; ++rr) {
            int r = warp * 8 + rr;
            int i = row0 + r;
            if (i >= n) continue;
            float4 v = ((const float4*)(xsh + r * HID))[lane];
            float mx = fmaxf(fmaxf(v.x, v.y), fmaxf(v.z, v.w));
            #pragma unroll
            for (int o = 16; o; o >>= 1) mx = fmaxf(mx, __shfl_xor_sync(0xffffffffu, mx, o));
            v.x = __expf(v.x - mx); v.y = __expf(v.y - mx);
            v.z = __expf(v.z - mx); v.w = __expf(v.w - mx);
            float sum = v.x + v.y + v.z + v.w;
            #pragma unroll
            for (int o = 16; o; o >>= 1) sum += __shfl_xor_sync(0xffffffffu, sum, o);
            float s = rsqrtf(fmaxf((float)out_deg[i], 1.f)) / sum;
            v.x *= s; v.y *= s; v.z *= s; v.w *= s;
            ((float4*)(H + (size_t)i * HID))[lane] = v;
        }
    }
}

// ---------------- final: fused gather + concat + two dense heads ---------------
__global__ __launch_bounds__(256, 1) void final_kernel(
    const float* __restrict__ Hprev,
    const int* __restrict__ offs, const int* __restrict__ csr,
    const float* __restrict__ nodes,
    const float* __restrict__ Wmu, const float* __restrict__ bmu,
    const float* __restrict__ Wls, const float* __restrict__ bls,
    float* __restrict__ out, int n, int tiles)
{
    extern __shared__ float sm[];
    float* Wsh = sm;                  // 256*128
    float* xsh = sm + KDIM * HID;     // 256*68

    const int tid  = threadIdx.x;
    const int j2   = tid & 63;
    const int rg   = tid >> 6;
    const int rbase = rg * 16;
    const int warp = tid >> 5, lane = tid & 31;

    for (int idx = tid; idx < KDIM * HID; idx += 256) {
        int k = idx >> 7, c = idx & 127;
        Wsh[idx] = (c < 64) ? Wmu[k * 64 + c] : Wls[k * 64 + (c - 64)];
    }

    const int   cbase = 2 * j2;
    const bool  is_mu = (cbase < 64);
    const int   cc0   = is_mu ? cbase : cbase - 64;
    const float bias0 = is_mu ? bmu[cc0] : bls[cc0];
    const float bias1 = is_mu ? bmu[cc0 + 1] : bls[cc0 + 1];
    const size_t obase = is_mu ? 0 : (size_t)n * ZDIM;

    for (int t = blockIdx.x; t < tiles; t += gridDim.x) {
        const int row0 = t * 64;
        __syncthreads();

        // k < 128: gathered+scaled h; k >= 128: raw node features
        stage_gather((const ulonglong2*)Hprev, offs, csr, xsh, row0, n, warp, lane, 0);
        for (int idx = tid; idx < 64 * FIN; idx += 256) {
            int k = idx & 127, r = idx >> 7;
            int i = row0 + r;
            xsh[(size_t)(HID + k) * XSTRIDE + r] =
                (i < n) ? nodes[(size_t)i * FIN + k] : 0.f;
        }
        __syncthreads();

        unsigned long long acc[16];
        #pragma unroll
        for (int q = 0; q < 16; ++q) acc[q] = 0ull;

        #pragma unroll 4
        for (int k = 0; k < KDIM; ++k) {
            float2 w2 = *(const float2*)(Wsh + k * HID + 2 * j2);
            unsigned long long wa = pack2(w2.x, w2.x);
            unsigned long long wb = pack2(w2.y, w2.y);
            const float* xb = xsh + k * XSTRIDE + rbase;
            #pragma unroll
            for (int q = 0; q < 4; ++q) {
                ulonglong2 xp = *(const ulonglong2*)(xb + 4 * q);
                fma2(acc[q * 4 + 0], xp.x, wa);
                fma2(acc[q * 4 + 1], xp.x, wb);
                fma2(acc[q * 4 + 2], xp.y, wa);
                fma2(acc[q * 4 + 3], xp.y, wb);
            }
        }

        #pragma unroll
        for (int q = 0; q < 4; ++q) {
            float c0e, c0o, c1e, c1o;
            int r = rbase + 4 * q;
            unpack2(acc[q * 4 + 0], c0e, c0o);
            unpack2(acc[q * 4 + 1], c1e, c1o);
            if (row0 + r < n)
                *(float2*)(out + obase + (size_t)(row0 + r) * ZDIM + cc0) =
                    make_float2(c0e + bias0, c1e + bias1);
            if (row0 + r + 1 < n)
                *(float2*)(out + obase + (size_t)(row0 + r + 1) * ZDIM + cc0) =
                    make_float2(c0o + bias0, c1o + bias1);
            unpack2(acc[q * 4 + 2], c0e, c0o);
            unpack2(acc[q * 4 + 3], c1e, c1o);
            if (row0 + r + 2 < n)
                *(float2*)(out + obase + (size_t)(row0 + r + 2) * ZDIM + cc0) =
                    make_float2(c0e + bias0, c1e + bias1);
            if (row0 + r + 3 < n)
                *(float2*)(out + obase + (size_t)(row0 + r + 3) * ZDIM + cc0) =
                    make_float2(c0o + bias0, c1o + bias1);
        }
    }
}

// ---------------- launch ------------------------------------------------------
extern "C" void kernel_launch(void* const* d_in, const int* in_sizes, int n_in,
                              void* d_out, int out_size)
{
    const float* nodes = (const float*)d_in[0];
    const int*   snd   = (const int*)d_in[1];
    const int*   rcv   = (const int*)d_in[2];
    const float* W0    = (const float*)d_in[3];
    const float* b0    = (const float*)d_in[4];
    const float* W1    = (const float*)d_in[5];
    const float* b1    = (const float*)d_in[6];
    const float* Wmu   = (const float*)d_in[7];
    const float* bmu   = (const float*)d_in[8];
    const float* Wls   = (const float*)d_in[9];
    const float* bls   = (const float*)d_in[10];
    float* out = (float*)d_out;

    const int n = in_sizes[0] / FIN;
    const int E = in_sizes[1];

    float *h;
    int *sdeg, *rdeg, *offs, *cursor, *csr;
    cudaGetSymbolAddress((void**)&h,      g_h);
    cudaGetSymbolAddress((void**)&sdeg,   g_sdeg);
    cudaGetSymbolAddress((void**)&rdeg,   g_rdeg);
    cudaGetSymbolAddress((void**)&offs,   g_offs);
    cudaGetSymbolAddress((void**)&cursor, g_cursor);
    cudaGetSymbolAddress((void**)&csr,    g_csr);

    const int DENSE_SMEM = (HID * HID + HID * XSTRIDE) * (int)sizeof(float);
    const int FINAL_SMEM = (KDIM * HID + KDIM * XSTRIDE) * (int)sizeof(float);
    cudaFuncSetAttribute(gc_dense_kernel, cudaFuncAttributeMaxDynamicSharedMemorySize, DENSE_SMEM);
    cudaFuncSetAttribute(final_kernel,    cudaFuncAttributeMaxDynamicSharedMemorySize, FINAL_SMEM);

    const int tiles = (n + 63) / 64;
    const int denseGrid = tiles < 296 ? tiles : 296;
    const int finalGrid = tiles < 148 ? tiles : 148;

    // 0..2: degrees + scan (launch order chosen so the dense GEMM is the
    // profiled launch at index 3)
    zero_deg_kernel<<<(n + 255) / 256, 256>>>(sdeg, rdeg, n);
    count_deg_kernel<<<(E + 255) / 256, 256>>>(snd, rcv, sdeg, rdeg, E);
    scan_kernel<<<1, 1024>>>(rdeg, offs, cursor, n);

    // 3: layer-1 dense (coalesced staging, no gather)
    gc_dense_kernel<<<denseGrid, 256, DENSE_SMEM>>>(nodes, nullptr, nullptr,
                                                    W0, b0, sdeg, h, n, tiles);
    // 4: CSR fill
    fill_kernel<<<(E + 255) / 256, 256>>>(snd, rcv, cursor, csr, E);

    // 5: layer-2 dense with fused gather
    gc_dense_kernel<<<denseGrid, 256, DENSE_SMEM>>>(h, offs, csr,
                                                    W1, b1, sdeg, h, n, tiles);

    // 6: final heads with fused gather + concat
    final_kernel<<<finalGrid, 256, FINAL_SMEM>>>(h, offs, csr, nodes,
                                                 Wmu, bmu, Wls, bls, out, n, tiles);
}

// round 7
// speedup vs baseline: 2.1321x; 1.0162x over previous
#include <cuda_runtime.h>
#include <cuda_bf16.h>
#include <cstdint>

#define NMAX   100000
#define EMAX   600000
#define HID    128
#define FIN    128
#define ZDIM   64
#define KDIM   256
#define TILE_M 128
#define XSTRIDE 68
#define PKB    272    // padded bf16 row pitch (136 bf16)

// ---------------- static device scratch --------------------------------------
__device__ float g_h [(size_t)NMAX * HID];
__device__ float g_h2[(size_t)NMAX * HID];
__device__ int   g_sdeg[NMAX];
__device__ int   g_rdeg[NMAX];
__device__ int   g_offs[NMAX + 1];
__device__ int   g_cursor[NMAX];
__device__ int   g_csr[EMAX];
__device__ __align__(16) uint8_t g_w0p[2][128 * PKB];   // padded bf16 W0 [n][k], hi/lo

// ---------------- FFMA2 helpers -------------------------------------------------
__device__ __forceinline__ void fma2(unsigned long long& d,
                                     unsigned long long a,
                                     unsigned long long b) {
    asm("fma.rn.f32x2 %0, %1, %2, %0;" : "+l"(d) : "l"(a), "l"(b));
}
__device__ __forceinline__ unsigned long long pack2(float x, float y) {
    unsigned long long r;
    asm("mov.b64 %0, {%1, %2};" : "=l"(r) : "f"(x), "f"(y));
    return r;
}
__device__ __forceinline__ void unpack2(unsigned long long p, float& x, float& y) {
    asm("mov.b64 {%0, %1}, %2;" : "=f"(x), "=f"(y) : "l"(p));
}

// ---------------- MMA helpers ----------------------------------------------------
__device__ __forceinline__ uint32_t smem_u32(const void* p) {
    uint32_t a;
    asm("{ .reg .u64 t; cvta.to.shared.u64 t, %1; cvt.u32.u64 %0, t; }" : "=r"(a) : "l"(p));
    return a;
}
__device__ __forceinline__ void ldsm4(uint32_t* r, uint32_t addr) {
    asm volatile("ldmatrix.sync.aligned.m8n8.x4.shared.b16 {%0,%1,%2,%3}, [%4];"
                 : "=r"(r[0]), "=r"(r[1]), "=r"(r[2]), "=r"(r[3]) : "r"(addr) : "memory");
}
__device__ __forceinline__ void mma_bf16(float* c, const uint32_t* a,
                                         uint32_t b0, uint32_t b1) {
    asm volatile(
        "mma.sync.aligned.m16n8k16.row.col.f32.bf16.bf16.f32 "
        "{%0,%1,%2,%3}, {%4,%5,%6,%7}, {%8,%9}, {%0,%1,%2,%3};"
        : "+f"(c[0]), "+f"(c[1]), "+f"(c[2]), "+f"(c[3])
        : "r"(a[0]), "r"(a[1]), "r"(a[2]), "r"(a[3]), "r"(b0), "r"(b1));
}
__device__ __forceinline__ uint32_t bf2u(__nv_bfloat162 v) {
    return *reinterpret_cast<uint32_t*>(&v);
}

// ---------------- degree / CSR build ----------------------------------------------
__global__ void zero_deg_kernel(int* sdeg, int* rdeg, int n) {
    int t = blockIdx.x * blockDim.x + threadIdx.x;
    if (t < n) { sdeg[t] = 0; rdeg[t] = 0; }
}
__global__ void count_deg_kernel(const int* __restrict__ snd, const int* __restrict__ rcv,
                                 int* sdeg, int* rdeg, int E) {
    int t = blockIdx.x * blockDim.x + threadIdx.x;
    if (t < E) {
        atomicAdd(&sdeg[snd[t]], 1);
        atomicAdd(&rdeg[rcv[t]], 1);
    }
}
__global__ __launch_bounds__(1024) void scan_kernel(
    const int* __restrict__ deg, int* __restrict__ offs, int* __restrict__ cursor, int n)
{
    __shared__ int warpsum[32];
    __shared__ int carry_sh;
    const int tid = threadIdx.x, lane = tid & 31, warp = tid >> 5;
    int carry = 0;
    for (int base = 0; base < n; base += 4096) {
        int idx = base + tid * 4;
        int4 v = make_int4(0, 0, 0, 0);
        if (idx + 3 < n) v = *(const int4*)(deg + idx);
        else {
            if (idx     < n) v.x = deg[idx];
            if (idx + 1 < n) v.y = deg[idx + 1];
            if (idx + 2 < n) v.z = deg[idx + 2];
        }
        int s0 = v.x, s1 = s0 + v.y, s2 = s1 + v.z, s3 = s2 + v.w;
        int inc = s3;
        #pragma unroll
        for (int o = 1; o < 32; o <<= 1) {
            int t = __shfl_up_sync(0xffffffffu, inc, o);
            if (lane >= o) inc += t;
        }
        if (lane == 31) warpsum[warp] = inc;
        __syncthreads();
        if (warp == 0) {
            int w = warpsum[lane];
            int wi = w;
            #pragma unroll
            for (int o = 1; o < 32; o <<= 1) {
                int t = __shfl_up_sync(0xffffffffu, wi, o);
                if (lane >= o) wi += t;
            }
            warpsum[lane] = wi - w;
        }
        __syncthreads();
        int texcl = carry + warpsum[warp] + inc - s3;
        int4 o4 = make_int4(texcl, texcl + s0, texcl + s1, texcl + s2);
        if (idx + 3 < n) {
            *(int4*)(offs + idx)   = o4;
            *(int4*)(cursor + idx) = o4;
        } else {
            if (idx     < n) { offs[idx]     = o4.x; cursor[idx]     = o4.x; }
            if (idx + 1 < n) { offs[idx + 1] = o4.y; cursor[idx + 1] = o4.y; }
            if (idx + 2 < n) { offs[idx + 2] = o4.z; cursor[idx + 2] = o4.z; }
        }
        if (tid == 1023) carry_sh = texcl + s3;
        __syncthreads();
        carry = carry_sh;
    }
    if (tid == 0) offs[n] = carry;
}
__global__ void fill_kernel(const int* __restrict__ snd, const int* __restrict__ rcv,
                            int* cursor, int* __restrict__ csr, int E)
{
    int t = blockIdx.x * blockDim.x + threadIdx.x;
    if (t < E) {
        int r = rcv[t];
        int p = atomicAdd(&cursor[r], 1);
        csr[p] = snd[t];
    }
}

// ---------------- W0 prep: fp32 -> bf16 hi/lo, [n][k] padded ----------------------
__global__ void prep_w_kernel(const float* __restrict__ W0)
{
    int idx = blockIdx.x * blockDim.x + threadIdx.x;
    if (idx >= 16384) return;
    int k = idx >> 7, nn = idx & 127;
    float v = W0[idx];
    __nv_bfloat16 h = __float2bfloat16(v);
    __nv_bfloat16 l = __float2bfloat16(v - __bfloat162float(h));
    *(__nv_bfloat16*)(g_w0p[0] + nn * PKB + k * 2) = h;
    *(__nv_bfloat16*)(g_w0p[1] + nn * PKB + k * 2) = l;
}

// ================= layer-1 dense via mma.sync (the bisected component) ============
__device__ __forceinline__ void stage_rows_mma(
    const float4* __restrict__ X4, uint8_t* a_hi, uint8_t* a_lo,
    int row0, int n, int wid, int lane)
{
    #pragma unroll 4
    for (int rr = 0; rr < 16; ++rr) {
        int r = wid * 16 + rr;
        int i = row0 + r;
        float4 v = make_float4(0.f, 0.f, 0.f, 0.f);
        if (i < n) v = X4[(size_t)i * 32 + lane];
        __nv_bfloat162 h01 = __floats2bfloat162_rn(v.x, v.y);
        __nv_bfloat162 h23 = __floats2bfloat162_rn(v.z, v.w);
        float2 f01 = __bfloat1622float2(h01);
        float2 f23 = __bfloat1622float2(h23);
        __nv_bfloat162 l01 = __floats2bfloat162_rn(v.x - f01.x, v.y - f01.y);
        __nv_bfloat162 l23 = __floats2bfloat162_rn(v.z - f23.x, v.w - f23.y);
        uint32_t off = (uint32_t)r * PKB + lane * 8;
        *(uint2*)(a_hi + off) = make_uint2(bf2u(h01), bf2u(h23));
        *(uint2*)(a_lo + off) = make_uint2(bf2u(l01), bf2u(l23));
    }
}

__device__ __forceinline__ void mma_block(
    float acc[2][8][4], uint32_t aH, uint32_t aL, uint32_t bH, uint32_t bL)
{
    #pragma unroll
    for (int k16 = 0; k16 < 8; ++k16) {
        const uint32_t kb = k16 * 32;
        uint32_t ah0[4], ah1[4], al0[4], al1[4];
        ldsm4(ah0, aH + kb);
        ldsm4(ah1, aH + 16 * PKB + kb);
        ldsm4(al0, aL + kb);
        ldsm4(al1, aL + 16 * PKB + kb);
        #pragma unroll
        for (int nf16 = 0; nf16 < 4; ++nf16) {
            uint32_t bh[4], bl[4];
            ldsm4(bh, bH + nf16 * 16 * PKB + kb);
            ldsm4(bl, bL + nf16 * 16 * PKB + kb);
            const int nf = nf16 * 2;
            mma_bf16(acc[0][nf],     ah0, bh[0], bh[1]);
            mma_bf16(acc[0][nf],     ah0, bl[0], bl[1]);
            mma_bf16(acc[0][nf],     al0, bh[0], bh[1]);
            mma_bf16(acc[0][nf + 1], ah0, bh[2], bh[3]);
            mma_bf16(acc[0][nf + 1], ah0, bl[2], bl[3]);
            mma_bf16(acc[0][nf + 1], al0, bh[2], bh[3]);
            mma_bf16(acc[1][nf],     ah1, bh[0], bh[1]);
            mma_bf16(acc[1][nf],     ah1, bl[0], bl[1]);
            mma_bf16(acc[1][nf],     al1, bh[0], bh[1]);
            mma_bf16(acc[1][nf + 1], ah1, bh[2], bh[3]);
            mma_bf16(acc[1][nf + 1], ah1, bl[2], bl[3]);
            mma_bf16(acc[1][nf + 1], al1, bh[2], bh[3]);
        }
    }
}

// smem: a_hi 0, a_lo 34816, b_hi 69632, b_lo 104448, bias 139264,
//       red1 139776, red2 140800 -> 141824
#define MMA_SMEM 141824
__global__ __launch_bounds__(256, 1) void mma_dense1_kernel(
    const float4* __restrict__ X4,
    const uint8_t* __restrict__ whi, const uint8_t* __restrict__ wlo,
    const float* __restrict__ bias, const int* __restrict__ sdeg,
    float* __restrict__ Hout, int n, int tiles)
{
    extern __shared__ uint8_t sm[];
    uint8_t* a_hi = sm;
    uint8_t* a_lo = sm + 34816;
    float* bias_sm = (float*)(sm + 139264);
    float* red1    = (float*)(sm + 139776);
    float* red2    = (float*)(sm + 140800);

    const int tid = threadIdx.x, wid = tid >> 5, lane = tid & 31;
    const int mrow = (wid & 3) * 32;
    const int ch   = wid >> 2;
    const int ncol = ch * 64;
    const int q2   = (lane & 3) * 2;

    for (int idx = tid; idx < 2176; idx += 256) {
        ((uint4*)(sm + 69632))[idx]  = ((const uint4*)whi)[idx];
        ((uint4*)(sm + 104448))[idx] = ((const uint4*)wlo)[idx];
    }
    if (tid < 128) bias_sm[tid] = bias[tid];
    __syncthreads();

    float brg[16];
    #pragma unroll
    for (int nf = 0; nf < 8; ++nf) {
        brg[2 * nf]     = bias_sm[ncol + nf * 8 + q2];
        brg[2 * nf + 1] = bias_sm[ncol + nf * 8 + q2 + 1];
    }
    int rl[4];
    #pragma unroll
    for (int ri = 0; ri < 4; ++ri)
        rl[ri] = mrow + (ri >> 1) * 16 + (ri & 1) * 8 + (lane >> 2);

    const uint32_t smb  = smem_u32(sm);
    const uint32_t aoff = (lane & 15) * PKB + (lane >> 4) * 16;
    const uint32_t boff = ((lane >> 4) * 8 + (lane & 7)) * PKB + ((lane >> 3) & 1) * 16;
    const uint32_t aH = smb + mrow * PKB + aoff;
    const uint32_t aL = smb + 34816 + mrow * PKB + aoff;
    const uint32_t bH = smb + 69632 + ncol * PKB + boff;
    const uint32_t bL = smb + 104448 + ncol * PKB + boff;

    for (int t = blockIdx.x; t < tiles; t += gridDim.x) {
        const int row0 = t * TILE_M;
        __syncthreads();
        stage_rows_mma(X4, a_hi, a_lo, row0, n, wid, lane);
        __syncthreads();

        float acc[2][8][4];
        #pragma unroll
        for (int a = 0; a < 2; ++a)
            #pragma unroll
            for (int b = 0; b < 8; ++b)
                #pragma unroll
                for (int c = 0; c < 4; ++c) acc[a][b][c] = 0.f;

        mma_block(acc, aH, aL, bH, bL);

        float rmax[4];
        #pragma unroll
        for (int ri = 0; ri < 4; ++ri) {
            const int mt = ri >> 1, h8 = (ri & 1) * 2;
            float m = -3.4e38f;
            #pragma unroll
            for (int nf = 0; nf < 8; ++nf) {
                float x0 = fmaxf(acc[mt][nf][h8]     + brg[2 * nf],     0.f);
                float x1 = fmaxf(acc[mt][nf][h8 + 1] + brg[2 * nf + 1], 0.f);
                acc[mt][nf][h8] = x0; acc[mt][nf][h8 + 1] = x1;
                m = fmaxf(m, fmaxf(x0, x1));
            }
            m = fmaxf(m, __shfl_xor_sync(0xffffffffu, m, 1));
            m = fmaxf(m, __shfl_xor_sync(0xffffffffu, m, 2));
            rmax[ri] = m;
            red1[ch * 128 + rl[ri]] = m;
        }
        __syncthreads();
        #pragma unroll
        for (int ri = 0; ri < 4; ++ri) {
            const int mt = ri >> 1, h8 = (ri & 1) * 2;
            float m = fmaxf(rmax[ri], red1[(ch ^ 1) * 128 + rl[ri]]);
            float s = 0.f;
            #pragma unroll
            for (int nf = 0; nf < 8; ++nf) {
                float v0 = __expf(acc[mt][nf][h8] - m);
                float v1 = __expf(acc[mt][nf][h8 + 1] - m);
                acc[mt][nf][h8] = v0; acc[mt][nf][h8 + 1] = v1;
                s += v0 + v1;
            }
            s += __shfl_xor_sync(0xffffffffu, s, 1);
            s += __shfl_xor_sync(0xffffffffu, s, 2);
            red2[ch * 128 + rl[ri]] = s;
        }
        __syncthreads();
        #pragma unroll
        for (int ri = 0; ri < 4; ++ri) {
            const int mt = ri >> 1, h8 = (ri & 1) * 2;
            const int i = row0 + rl[ri];
            if (i >= n) continue;
            float s = red2[rl[ri]] + red2[128 + rl[ri]];
            float scl = rsqrtf(fmaxf((float)__ldg(&sdeg[i]), 1.f)) / s;
            float* op = Hout + (size_t)i * HID + ncol;
            #pragma unroll
            for (int nf = 0; nf < 8; ++nf)
                *(float2*)(op + nf * 8 + q2) =
                    make_float2(acc[mt][nf][h8] * scl, acc[mt][nf][h8 + 1] * scl);
        }
    }
}

// ================= proven FFMA2 kernels (round 4) ==================================
__device__ __forceinline__ void stage_gather_f2(
    const ulonglong2* __restrict__ H2, const int* __restrict__ offs,
    const int* __restrict__ csr, float* xsh,
    int row0, int n, int warp, int lane, int kofs)
{
    const int r_sub = lane >> 2;
    const int cseg  = lane & 3;
    const int r = warp * 8 + r_sub;
    const int i = row0 + r;

    unsigned long long acc2[16];
    #pragma unroll
    for (int q = 0; q < 16; ++q) acc2[q] = 0ull;

    if (i < n) {
        int beg = __ldg(&offs[i]);
        int end = __ldg(&offs[i + 1]);
        for (int e = beg; e < end; ++e) {
            int s = __ldg(&csr[e]);
            const ulonglong2* hp = H2 + (size_t)s * 32 + cseg * 8;
            #pragma unroll
            for (int q = 0; q < 8; ++q) {
                ulonglong2 v = hp[q];
                asm("add.rn.f32x2 %0, %0, %1;" : "+l"(acc2[2 * q])     : "l"(v.x));
                asm("add.rn.f32x2 %0, %0, %1;" : "+l"(acc2[2 * q + 1]) : "l"(v.y));
            }
        }
        float scl = rsqrtf(fmaxf((float)(end - beg), 1.f));
        unsigned long long s2 = pack2(scl, scl);
        #pragma unroll
        for (int q = 0; q < 16; ++q)
            asm("mul.rn.f32x2 %0, %0, %1;" : "+l"(acc2[q]) : "l"(s2));
    }

    #pragma unroll
    for (int q = 0; q < 16; ++q) {
        float x0, x1;
        unpack2(acc2[q], x0, x1);
        int k = kofs + cseg * 32 + 2 * q;
        xsh[(size_t)k * XSTRIDE + r]       = x0;
        xsh[(size_t)(k + 1) * XSTRIDE + r] = x1;
    }
}

#define DENSE_SMEM ((HID * HID + HID * XSTRIDE) * 4)
__global__ __launch_bounds__(256, 2) void gc_dense_kernel(
    const float* __restrict__ X,
    const int* __restrict__ offs, const int* __restrict__ csr,
    const float* __restrict__ W, const float* __restrict__ b,
    const int* __restrict__ out_deg, float* __restrict__ H,
    int n, int tiles)
{
    extern __shared__ float smf[];
    float* Wsh = smf;
    float* xsh = smf + HID * HID;

    const int tid  = threadIdx.x;
    const int j2   = tid & 63;
    const int rg   = tid >> 6;
    const int rbase = rg * 16;
    const int warp = tid >> 5, lane = tid & 31;

    for (int idx = tid; idx < HID * HID / 4; idx += 256)
        ((float4*)Wsh)[idx] = ((const float4*)W)[idx];

    const float b0v = b[2 * j2];
    const float b1v = b[2 * j2 + 1];

    for (int t = blockIdx.x; t < tiles; t += gridDim.x) {
        const int row0 = t * 64;
        __syncthreads();

        if (csr) {
            stage_gather_f2((const ulonglong2*)X, offs, csr, xsh, row0, n, warp, lane, 0);
        } else {
            for (int idx = tid; idx < 64 * HID; idx += 256) {
                int k = idx & 127, r = idx >> 7;
                int i = row0 + r;
                xsh[k * XSTRIDE + r] = (i < n) ? X[(size_t)i * HID + k] : 0.f;
            }
        }
        __syncthreads();

        unsigned long long acc[16];
        #pragma unroll
        for (int q = 0; q < 16; ++q) acc[q] = 0ull;

        #pragma unroll 4
        for (int k = 0; k < HID; ++k) {
            float2 w2 = *(const float2*)(Wsh + k * HID + 2 * j2);
            unsigned long long wa = pack2(w2.x, w2.x);
            unsigned long long wb = pack2(w2.y, w2.y);
            const float* xb = xsh + k * XSTRIDE + rbase;
            #pragma unroll
            for (int q = 0; q < 4; ++q) {
                ulonglong2 xp = *(const ulonglong2*)(xb + 4 * q);
                fma2(acc[q * 4 + 0], xp.x, wa);
                fma2(acc[q * 4 + 1], xp.x, wb);
                fma2(acc[q * 4 + 2], xp.y, wa);
                fma2(acc[q * 4 + 3], xp.y, wb);
            }
        }
        __syncthreads();

        #pragma unroll
        for (int q = 0; q < 4; ++q) {
            float c0e, c0o, c1e, c1o;
            unpack2(acc[q * 4 + 0], c0e, c0o);
            unpack2(acc[q * 4 + 1], c1e, c1o);
            int r = rbase + 4 * q;
            *(float2*)(xsh + r * HID + 2 * j2) =
                make_float2(fmaxf(c0e + b0v, 0.f), fmaxf(c1e + b1v, 0.f));
            *(float2*)(xsh + (r + 1) * HID + 2 * j2) =
                make_float2(fmaxf(c0o + b0v, 0.f), fmaxf(c1o + b1v, 0.f));
            unpack2(acc[q * 4 + 2], c0e, c0o);
            unpack2(acc[q * 4 + 3], c1e, c1o);
            *(float2*)(xsh + (r + 2) * HID + 2 * j2) =
                make_float2(fmaxf(c0e + b0v, 0.f), fmaxf(c1e + b1v, 0.f));
            *(float2*)(xsh + (r + 3) * HID + 2 * j2) =
                make_float2(fmaxf(c0o + b0v, 0.f), fmaxf(c1o + b1v, 0.f));
        }
        __syncthreads();

        #pragma unroll
        for (int rr = 0; rr < 8; ++rr) {
            int r = warp * 8 + rr;
            int i = row0 + r;
            if (i >= n) continue;
            float4 v = ((const float4*)(xsh + r * HID))[lane];
            float mx = fmaxf(fmaxf(v.x, v.y), fmaxf(v.z, v.w));
            #pragma unroll
            for (int o = 16; o; o >>= 1) mx = fmaxf(mx, __shfl_xor_sync(0xffffffffu, mx, o));
            v.x = __expf(v.x - mx); v.y = __expf(v.y - mx);
            v.z = __expf(v.z - mx); v.w = __expf(v.w - mx);
            float sum = v.x + v.y + v.z + v.w;
            #pragma unroll
            for (int o = 16; o; o >>= 1) sum += __shfl_xor_sync(0xffffffffu, sum, o);
            float s = rsqrtf(fmaxf((float)out_deg[i], 1.f)) / sum;
            v.x *= s; v.y *= s; v.z *= s; v.w *= s;
            ((float4*)(H + (size_t)i * HID))[lane] = v;
        }
    }
}

#define FINAL_SMEM ((KDIM * HID + KDIM * XSTRIDE) * 4)
__global__ __launch_bounds__(256, 1) void final_kernel(
    const float* __restrict__ Hprev,
    const int* __restrict__ offs, const int* __restrict__ csr,
    const float* __restrict__ nodes,
    const float* __restrict__ Wmu, const float* __restrict__ bmu,
    const float* __restrict__ Wls, const float* __restrict__ bls,
    float* __restrict__ out, int n, int tiles)
{
    extern __shared__ float smf[];
    float* Wsh = smf;
    float* xsh = smf + KDIM * HID;

    const int tid  = threadIdx.x;
    const int j2   = tid & 63;
    const int rg   = tid >> 6;
    const int rbase = rg * 16;
    const int warp = tid >> 5, lane = tid & 31;

    for (int idx = tid; idx < KDIM * HID; idx += 256) {
        int k = idx >> 7, c = idx & 127;
        Wsh[idx] = (c < 64) ? Wmu[k * 64 + c] : Wls[k * 64 + (c - 64)];
    }

    const int   cbase = 2 * j2;
    const bool  is_mu = (cbase < 64);
    const int   cc0   = is_mu ? cbase : cbase - 64;
    const float bias0 = is_mu ? bmu[cc0] : bls[cc0];
    const float bias1 = is_mu ? bmu[cc0 + 1] : bls[cc0 + 1];
    const size_t obase = is_mu ? 0 : (size_t)n * ZDIM;

    for (int t = blockIdx.x; t < tiles; t += gridDim.x) {
        const int row0 = t * 64;
        __syncthreads();

        stage_gather_f2((const ulonglong2*)Hprev, offs, csr, xsh, row0, n, warp, lane, 0);
        for (int idx = tid; idx < 64 * FIN; idx += 256) {
            int k = idx & 127, r = idx >> 7;
            int i = row0 + r;
            xsh[(size_t)(HID + k) * XSTRIDE + r] =
                (i < n) ? nodes[(size_t)i * FIN + k] : 0.f;
        }
        __syncthreads();

        unsigned long long acc[16];
        #pragma unroll
        for (int q = 0; q < 16; ++q) acc[q] = 0ull;

        #pragma unroll 4
        for (int k = 0; k < KDIM; ++k) {
            float2 w2 = *(const float2*)(Wsh + k * HID + 2 * j2);
            unsigned long long wa = pack2(w2.x, w2.x);
            unsigned long long wb = pack2(w2.y, w2.y);
            const float* xb = xsh + k * XSTRIDE + rbase;
            #pragma unroll
            for (int q = 0; q < 4; ++q) {
                ulonglong2 xp = *(const ulonglong2*)(xb + 4 * q);
                fma2(acc[q * 4 + 0], xp.x, wa);
                fma2(acc[q * 4 + 1], xp.x, wb);
                fma2(acc[q * 4 + 2], xp.y, wa);
                fma2(acc[q * 4 + 3], xp.y, wb);
            }
        }

        #pragma unroll
        for (int q = 0; q < 4; ++q) {
            float c0e, c0o, c1e, c1o;
            int r = rbase + 4 * q;
            unpack2(acc[q * 4 + 0], c0e, c0o);
            unpack2(acc[q * 4 + 1], c1e, c1o);
            if (row0 + r < n)
                *(float2*)(out + obase + (size_t)(row0 + r) * ZDIM + cc0) =
                    make_float2(c0e + bias0, c1e + bias1);
            if (row0 + r + 1 < n)
                *(float2*)(out + obase + (size_t)(row0 + r + 1) * ZDIM + cc0) =
                    make_float2(c0o + bias0, c1o + bias1);
            unpack2(acc[q * 4 + 2], c0e, c0o);
            unpack2(acc[q * 4 + 3], c1e, c1o);
            if (row0 + r + 2 < n)
                *(float2*)(out + obase + (size_t)(row0 + r + 2) * ZDIM + cc0) =
                    make_float2(c0e + bias0, c1e + bias1);
            if (row0 + r + 3 < n)
                *(float2*)(out + obase + (size_t)(row0 + r + 3) * ZDIM + cc0) =
                    make_float2(c0o + bias0, c1o + bias1);
        }
    }
}

// ---------------- launch ------------------------------------------------------------
extern "C" void kernel_launch(void* const* d_in, const int* in_sizes, int n_in,
                              void* d_out, int out_size)
{
    const float* nodes = (const float*)d_in[0];
    const int*   snd   = (const int*)d_in[1];
    const int*   rcv   = (const int*)d_in[2];
    const float* W0    = (const float*)d_in[3];
    const float* b0    = (const float*)d_in[4];
    const float* W1    = (const float*)d_in[5];
    const float* b1    = (const float*)d_in[6];
    const float* Wmu   = (const float*)d_in[7];
    const float* bmu   = (const float*)d_in[8];
    const float* Wls   = (const float*)d_in[9];
    const float* bls   = (const float*)d_in[10];
    float* out = (float*)d_out;

    const int n = in_sizes[0] / FIN;
    const int E = in_sizes[1];

    float *h, *h2;
    int *sdeg, *rdeg, *offs, *cursor, *csr;
    uint8_t *w0p;
    cudaGetSymbolAddress((void**)&h,      g_h);
    cudaGetSymbolAddress((void**)&h2,     g_h2);
    cudaGetSymbolAddress((void**)&sdeg,   g_sdeg);
    cudaGetSymbolAddress((void**)&rdeg,   g_rdeg);
    cudaGetSymbolAddress((void**)&offs,   g_offs);
    cudaGetSymbolAddress((void**)&cursor, g_cursor);
    cudaGetSymbolAddress((void**)&csr,    g_csr);
    cudaGetSymbolAddress((void**)&w0p,    g_w0p);

    cudaFuncSetAttribute(mma_dense1_kernel, cudaFuncAttributeMaxDynamicSharedMemorySize, MMA_SMEM);
    cudaFuncSetAttribute(gc_dense_kernel,   cudaFuncAttributeMaxDynamicSharedMemorySize, DENSE_SMEM);
    cudaFuncSetAttribute(final_kernel,      cudaFuncAttributeMaxDynamicSharedMemorySize, FINAL_SMEM);

    const int tiles128 = (n + TILE_M - 1) / TILE_M;
    const int tiles64  = (n + 63) / 64;
    const int denseGrid = tiles64 < 296 ? tiles64 : 296;
    const int finalGrid = tiles64 < 148 ? tiles64 : 148;
    const int IMG = 128 * PKB;

    // 0: prep   1-2: degrees   (3: mma dense1 -> profiled)
    prep_w_kernel<<<64, 256>>>(W0);
    zero_deg_kernel<<<(n + 255) / 256, 256>>>(sdeg, rdeg, n);
    count_deg_kernel<<<(E + 255) / 256, 256>>>(snd, rcv, sdeg, rdeg, E);

    // 3: layer-1 dense via mma.sync (BISECTED COMPONENT)
    mma_dense1_kernel<<<148, 256, MMA_SMEM>>>(
        (const float4*)nodes, w0p, w0p + IMG, b0, sdeg, h, n, tiles128);

    // 4-5: CSR build
    scan_kernel<<<1, 1024>>>(rdeg, offs, cursor, n);
    fill_kernel<<<(E + 255) / 256, 256>>>(snd, rcv, cursor, csr, E);

    // 6: layer-2 dense, FFMA2 (proven) — reads h, writes h2 (no aliasing)
    gc_dense_kernel<<<denseGrid, 256, DENSE_SMEM>>>(h, offs, csr,
                                                    W1, b1, sdeg, h2, n, tiles64);

    // 7: final heads, FFMA2 (proven) — gathers h2 + concat nodes
    final_kernel<<<finalGrid, 256, FINAL_SMEM>>>(h2, offs, csr, nodes,
                                                 Wmu, bmu, Wls, bls, out, n, tiles64);
}

// round 8
// speedup vs baseline: 3.0302x; 1.4212x over previous
#include <cuda_runtime.h>
#include <cuda_bf16.h>
#include <cstdint>

#define NMAX   100000
#define EMAX   600000
#define HID    128
#define FIN    128
#define ZDIM   64
#define PKB    272    // padded bf16 row pitch (136 bf16)

// ---------------- static device scratch --------------------------------------
__device__ float g_h [(size_t)NMAX * HID];
__device__ float g_h2[(size_t)NMAX * HID];
__device__ int   g_sdeg[NMAX];
__device__ int   g_rdeg[NMAX];
__device__ int   g_offs[NMAX + 1];
__device__ int   g_cursor[NMAX];
__device__ int   g_csr[EMAX];
__device__ __align__(16) uint8_t g_w0p[2][128 * PKB];      // [hi/lo]
__device__ __align__(16) uint8_t g_w1p[2][128 * PKB];      // [hi/lo]
__device__ __align__(16) uint8_t g_wfp[2][2][128 * PKB];   // [k-half][hi/lo]

// ---------------- PTX helpers --------------------------------------------------
__device__ __forceinline__ uint32_t smem_u32(const void* p) {
    uint32_t a;
    asm("{ .reg .u64 t; cvta.to.shared.u64 t, %1; cvt.u32.u64 %0, t; }" : "=r"(a) : "l"(p));
    return a;
}
__device__ __forceinline__ void ldsm4(uint32_t* r, uint32_t addr) {
    asm volatile("ldmatrix.sync.aligned.m8n8.x4.shared.b16 {%0,%1,%2,%3}, [%4];"
                 : "=r"(r[0]), "=r"(r[1]), "=r"(r[2]), "=r"(r[3]) : "r"(addr) : "memory");
}
__device__ __forceinline__ void mma_bf16(float* c, const uint32_t* a,
                                         uint32_t b0, uint32_t b1) {
    asm volatile(
        "mma.sync.aligned.m16n8k16.row.col.f32.bf16.bf16.f32 "
        "{%0,%1,%2,%3}, {%4,%5,%6,%7}, {%8,%9}, {%0,%1,%2,%3};"
        : "+f"(c[0]), "+f"(c[1]), "+f"(c[2]), "+f"(c[3])
        : "r"(a[0]), "r"(a[1]), "r"(a[2]), "r"(a[3]), "r"(b0), "r"(b1));
}
__device__ __forceinline__ uint32_t bf2u(__nv_bfloat162 v) {
    return *reinterpret_cast<uint32_t*>(&v);
}

// ---------------- degree / CSR build -------------------------------------------
__global__ void zero_deg_kernel(int* sdeg, int* rdeg, int n) {
    int t = blockIdx.x * blockDim.x + threadIdx.x;
    if (t < n) { sdeg[t] = 0; rdeg[t] = 0; }
}
__global__ void count_deg_kernel(const int* __restrict__ snd, const int* __restrict__ rcv,
                                 int* sdeg, int* rdeg, int E) {
    int t = blockIdx.x * blockDim.x + threadIdx.x;
    if (t < E) {
        atomicAdd(&sdeg[snd[t]], 1);
        atomicAdd(&rdeg[rcv[t]], 1);
    }
}
__global__ __launch_bounds__(1024) void scan_kernel(
    const int* __restrict__ deg, int* __restrict__ offs, int* __restrict__ cursor, int n)
{
    __shared__ int warpsum[32];
    __shared__ int carry_sh;
    const int tid = threadIdx.x, lane = tid & 31, warp = tid >> 5;
    int carry = 0;
    for (int base = 0; base < n; base += 4096) {
        int idx = base + tid * 4;
        int4 v = make_int4(0, 0, 0, 0);
        if (idx + 3 < n) v = *(const int4*)(deg + idx);
        else {
            if (idx     < n) v.x = deg[idx];
            if (idx + 1 < n) v.y = deg[idx + 1];
            if (idx + 2 < n) v.z = deg[idx + 2];
        }
        int s0 = v.x, s1 = s0 + v.y, s2 = s1 + v.z, s3 = s2 + v.w;
        int inc = s3;
        #pragma unroll
        for (int o = 1; o < 32; o <<= 1) {
            int t = __shfl_up_sync(0xffffffffu, inc, o);
            if (lane >= o) inc += t;
        }
        if (lane == 31) warpsum[warp] = inc;
        __syncthreads();
        if (warp == 0) {
            int w = warpsum[lane];
            int wi = w;
            #pragma unroll
            for (int o = 1; o < 32; o <<= 1) {
                int t = __shfl_up_sync(0xffffffffu, wi, o);
                if (lane >= o) wi += t;
            }
            warpsum[lane] = wi - w;
        }
        __syncthreads();
        int texcl = carry + warpsum[warp] + inc - s3;
        int4 o4 = make_int4(texcl, texcl + s0, texcl + s1, texcl + s2);
        if (idx + 3 < n) {
            *(int4*)(offs + idx)   = o4;
            *(int4*)(cursor + idx) = o4;
        } else {
            if (idx     < n) { offs[idx]     = o4.x; cursor[idx]     = o4.x; }
            if (idx + 1 < n) { offs[idx + 1] = o4.y; cursor[idx + 1] = o4.y; }
            if (idx + 2 < n) { offs[idx + 2] = o4.z; cursor[idx + 2] = o4.z; }
        }
        if (tid == 1023) carry_sh = texcl + s3;
        __syncthreads();
        carry = carry_sh;
    }
    if (tid == 0) offs[n] = carry;
}
__global__ void fill_kernel(const int* __restrict__ snd, const int* __restrict__ rcv,
                            int* cursor, int* __restrict__ csr, int E)
{
    int t = blockIdx.x * blockDim.x + threadIdx.x;
    if (t < E) {
        int r = rcv[t];
        int p = atomicAdd(&cursor[r], 1);
        csr[p] = snd[t];
    }
}

// ---------------- weight prep (FIXED: 65536 entries) ----------------------------
__global__ void prep_w_kernel(const float* __restrict__ W0, const float* __restrict__ W1,
                              const float* __restrict__ Wmu, const float* __restrict__ Wls)
{
    int idx = blockIdx.x * blockDim.x + threadIdx.x;
    if (idx >= 65536) return;
    float v; uint8_t *bh, *bl; int row, col;
    if (idx < 16384) {
        int k = idx >> 7, nn = idx & 127;
        v = W0[idx]; row = nn; col = k; bh = g_w0p[0]; bl = g_w0p[1];
    } else if (idx < 32768) {
        int r = idx - 16384;
        int k = r >> 7, nn = r & 127;
        v = W1[r]; row = nn; col = k; bh = g_w1p[0]; bl = g_w1p[1];
    } else {
        int r = idx - 32768;                 // [0, 32768)
        int half = r >> 14, r2 = r & 16383;  // half in {0,1}
        int kl = r2 >> 7, nn = r2 & 127;
        int kg = half * 128 + kl;
        v = (nn < 64) ? Wmu[kg * 64 + nn] : Wls[kg * 64 + (nn - 64)];
        row = nn; col = kl; bh = g_wfp[half][0]; bl = g_wfp[half][1];
    }
    __nv_bfloat16 h = __float2bfloat16(v);
    __nv_bfloat16 l = __float2bfloat16(v - __bfloat162float(h));
    *(__nv_bfloat16*)(bh + row * PKB + col * 2) = h;
    *(__nv_bfloat16*)(bl + row * PKB + col * 2) = l;
}

// ---------------- staging: coalesced rows (NW warps stage NW*16 rows) ------------
template <int NW>
__device__ __forceinline__ void stage_rows_mma(
    const float4* __restrict__ X4, uint8_t* a_hi, uint8_t* a_lo,
    int row0, int n, int wid, int lane)
{
    #pragma unroll 4
    for (int rr = 0; rr < 16; ++rr) {
        int r = wid * 16 + rr;
        int i = row0 + r;
        float4 v = make_float4(0.f, 0.f, 0.f, 0.f);
        if (i < n) v = X4[(size_t)i * 32 + lane];
        __nv_bfloat162 h01 = __floats2bfloat162_rn(v.x, v.y);
        __nv_bfloat162 h23 = __floats2bfloat162_rn(v.z, v.w);
        float2 f01 = __bfloat1622float2(h01);
        float2 f23 = __bfloat1622float2(h23);
        __nv_bfloat162 l01 = __floats2bfloat162_rn(v.x - f01.x, v.y - f01.y);
        __nv_bfloat162 l23 = __floats2bfloat162_rn(v.z - f23.x, v.w - f23.y);
        uint32_t off = (uint32_t)r * PKB + lane * 8;
        *(uint2*)(a_hi + off) = make_uint2(bf2u(h01), bf2u(h23));
        *(uint2*)(a_lo + off) = make_uint2(bf2u(l01), bf2u(l23));
    }
}

// ---------------- staging: CSR gather + rsqrt(deg) scale -------------------------
// NW warps cover NW*8 rows per pass, 2 passes -> NW*16 rows total.
template <int NW>
__device__ __forceinline__ void stage_gather_mma(
    const float4* __restrict__ H4, const int* __restrict__ offs,
    const int* __restrict__ csr, uint8_t* a_hi, uint8_t* a_lo,
    int row0, int n, int wid, int lane)
{
    #pragma unroll
    for (int pass = 0; pass < 2; ++pass) {
        int r = pass * (NW * 8) + wid * 8 + (lane >> 2);
        int cseg = lane & 3;
        int i = row0 + r;
        float acc[32];
        #pragma unroll
        for (int q = 0; q < 32; ++q) acc[q] = 0.f;
        if (i < n) {
            int beg = __ldg(&offs[i]), end = __ldg(&offs[i + 1]);
            for (int e = beg; e < end; ++e) {
                int s = __ldg(&csr[e]);
                const float4* hp = H4 + (size_t)s * 32 + cseg * 8;
                #pragma unroll
                for (int q = 0; q < 8; ++q) {
                    float4 vv = hp[q];
                    acc[4 * q]     += vv.x;
                    acc[4 * q + 1] += vv.y;
                    acc[4 * q + 2] += vv.z;
                    acc[4 * q + 3] += vv.w;
                }
            }
            float scl = rsqrtf(fmaxf((float)(end - beg), 1.f));
            #pragma unroll
            for (int q = 0; q < 32; ++q) acc[q] *= scl;
        }
        #pragma unroll
        for (int qq = 0; qq < 8; ++qq) {
            float x0 = acc[4 * qq], x1 = acc[4 * qq + 1];
            float x2 = acc[4 * qq + 2], x3 = acc[4 * qq + 3];
            __nv_bfloat162 h01 = __floats2bfloat162_rn(x0, x1);
            __nv_bfloat162 h23 = __floats2bfloat162_rn(x2, x3);
            float2 f01 = __bfloat1622float2(h01);
            float2 f23 = __bfloat1622float2(h23);
            __nv_bfloat162 l01 = __floats2bfloat162_rn(x0 - f01.x, x1 - f01.y);
            __nv_bfloat162 l23 = __floats2bfloat162_rn(x2 - f23.x, x3 - f23.y);
            uint32_t off = (uint32_t)r * PKB + (cseg * 32 + 4 * qq) * 2;
            *(uint2*)(a_hi + off) = make_uint2(bf2u(h01), bf2u(h23));
            *(uint2*)(a_lo + off) = make_uint2(bf2u(l01), bf2u(l23));
        }
    }
}

// ---------------- 3-term bf16 MMA, one K=128 block, m32 x n64 per warp -----------
__device__ __forceinline__ void mma_block(
    float acc[2][8][4], uint32_t aH, uint32_t aL, uint32_t bH, uint32_t bL)
{
    #pragma unroll
    for (int k16 = 0; k16 < 8; ++k16) {
        const uint32_t kb = k16 * 32;
        uint32_t ah0[4], ah1[4], al0[4], al1[4];
        ldsm4(ah0, aH + kb);
        ldsm4(ah1, aH + 16 * PKB + kb);
        ldsm4(al0, aL + kb);
        ldsm4(al1, aL + 16 * PKB + kb);
        #pragma unroll
        for (int nf16 = 0; nf16 < 4; ++nf16) {
            uint32_t bh[4], bl[4];
            ldsm4(bh, bH + nf16 * 16 * PKB + kb);
            ldsm4(bl, bL + nf16 * 16 * PKB + kb);
            const int nf = nf16 * 2;
            mma_bf16(acc[0][nf],     ah0, bh[0], bh[1]);
            mma_bf16(acc[0][nf],     ah0, bl[0], bl[1]);
            mma_bf16(acc[0][nf],     al0, bh[0], bh[1]);
            mma_bf16(acc[0][nf + 1], ah0, bh[2], bh[3]);
            mma_bf16(acc[0][nf + 1], ah0, bl[2], bl[3]);
            mma_bf16(acc[0][nf + 1], al0, bh[2], bh[3]);
            mma_bf16(acc[1][nf],     ah1, bh[0], bh[1]);
            mma_bf16(acc[1][nf],     ah1, bl[0], bl[1]);
            mma_bf16(acc[1][nf],     al1, bh[0], bh[1]);
            mma_bf16(acc[1][nf + 1], ah1, bh[2], bh[3]);
            mma_bf16(acc[1][nf + 1], ah1, bl[2], bl[3]);
            mma_bf16(acc[1][nf + 1], al1, bh[2], bh[3]);
        }
    }
}

// ---------------- dense GC layer: 512 threads, 256-row tiles ---------------------
// smem: a_hi 0 (69632), a_lo 69632, b_hi 139264, b_lo 174080,
//       bias 208896 (512B), red1 209408 (2KB), red2 211456 (2KB) -> 213504
#define MMA_SMEM 213504
__global__ __launch_bounds__(512, 1) void mma_dense_kernel(
    const float4* __restrict__ X4, const float4* __restrict__ Hin,
    const int* __restrict__ offs, const int* __restrict__ csr,
    const uint8_t* __restrict__ whi, const uint8_t* __restrict__ wlo,
    const float* __restrict__ bias, const int* __restrict__ sdeg,
    float* __restrict__ Hout, int n, int tiles)
{
    extern __shared__ uint8_t sm[];
    uint8_t* a_hi = sm;
    uint8_t* a_lo = sm + 69632;
    float* bias_sm = (float*)(sm + 208896);
    float* red1    = (float*)(sm + 209408);
    float* red2    = (float*)(sm + 211456);

    const int tid = threadIdx.x, wid = tid >> 5, lane = tid & 31;
    const int sub  = wid >> 3;                       // 0/1: 128-row subtile
    const int mrow = (wid & 3) * 32 + sub * 128;     // row base within 256-tile
    const int ch   = (wid >> 2) & 1;                 // column half 0/1
    const int ncol = ch * 64;
    const int q2   = (lane & 3) * 2;

    for (int idx = tid; idx < 2176; idx += 512) {
        ((uint4*)(sm + 139264))[idx] = ((const uint4*)whi)[idx];
        ((uint4*)(sm + 174080))[idx] = ((const uint4*)wlo)[idx];
    }
    if (tid < 128) bias_sm[tid] = bias[tid];
    __syncthreads();

    float brg[16];
    #pragma unroll
    for (int nf = 0; nf < 8; ++nf) {
        brg[2 * nf]     = bias_sm[ncol + nf * 8 + q2];
        brg[2 * nf + 1] = bias_sm[ncol + nf * 8 + q2 + 1];
    }
    int rl[4];
    #pragma unroll
    for (int ri = 0; ri < 4; ++ri)
        rl[ri] = mrow + (ri >> 1) * 16 + (ri & 1) * 8 + (lane >> 2);

    const uint32_t smb  = smem_u32(sm);
    const uint32_t aoff = (lane & 15) * PKB + (lane >> 4) * 16;
    const uint32_t boff = ((lane >> 4) * 8 + (lane & 7)) * PKB + ((lane >> 3) & 1) * 16;
    const uint32_t aH = smb + mrow * PKB + aoff;
    const uint32_t aL = smb + 69632 + mrow * PKB + aoff;
    const uint32_t bH = smb + 139264 + ncol * PKB + boff;
    const uint32_t bL = smb + 174080 + ncol * PKB + boff;

    for (int t = blockIdx.x; t < tiles; t += gridDim.x) {
        const int row0 = t * 256;
        __syncthreads();
        if (csr) stage_gather_mma<16>(Hin, offs, csr, a_hi, a_lo, row0, n, wid, lane);
        else     stage_rows_mma<16>(X4, a_hi, a_lo, row0, n, wid, lane);
        __syncthreads();

        float acc[2][8][4];
        #pragma unroll
        for (int a = 0; a < 2; ++a)
            #pragma unroll
            for (int b = 0; b < 8; ++b)
                #pragma unroll
                for (int c = 0; c < 4; ++c) acc[a][b][c] = 0.f;

        mma_block(acc, aH, aL, bH, bL);

        // epilogue: bias + relu + softmax(128) + rsqrt(sdeg)
        float rmax[4];
        #pragma unroll
        for (int ri = 0; ri < 4; ++ri) {
            const int mt = ri >> 1, h8 = (ri & 1) * 2;
            float m = -3.4e38f;
            #pragma unroll
            for (int nf = 0; nf < 8; ++nf) {
                float x0 = fmaxf(acc[mt][nf][h8]     + brg[2 * nf],     0.f);
                float x1 = fmaxf(acc[mt][nf][h8 + 1] + brg[2 * nf + 1], 0.f);
                acc[mt][nf][h8] = x0; acc[mt][nf][h8 + 1] = x1;
                m = fmaxf(m, fmaxf(x0, x1));
            }
            m = fmaxf(m, __shfl_xor_sync(0xffffffffu, m, 1));
            m = fmaxf(m, __shfl_xor_sync(0xffffffffu, m, 2));
            rmax[ri] = m;
            red1[ch * 256 + rl[ri]] = m;
        }
        __syncthreads();
        #pragma unroll
        for (int ri = 0; ri < 4; ++ri) {
            const int mt = ri >> 1, h8 = (ri & 1) * 2;
            float m = fmaxf(rmax[ri], red1[(ch ^ 1) * 256 + rl[ri]]);
            float s = 0.f;
            #pragma unroll
            for (int nf = 0; nf < 8; ++nf) {
                float v0 = __expf(acc[mt][nf][h8] - m);
                float v1 = __expf(acc[mt][nf][h8 + 1] - m);
                acc[mt][nf][h8] = v0; acc[mt][nf][h8 + 1] = v1;
                s += v0 + v1;
            }
            s += __shfl_xor_sync(0xffffffffu, s, 1);
            s += __shfl_xor_sync(0xffffffffu, s, 2);
            red2[ch * 256 + rl[ri]] = s;
        }
        __syncthreads();
        #pragma unroll
        for (int ri = 0; ri < 4; ++ri) {
            const int mt = ri >> 1, h8 = (ri & 1) * 2;
            const int i = row0 + rl[ri];
            if (i >= n) continue;
            float s = red2[rl[ri]] + red2[256 + rl[ri]];
            float scl = rsqrtf(fmaxf((float)__ldg(&sdeg[i]), 1.f)) / s;
            float* op = Hout + (size_t)i * HID + ncol;
            #pragma unroll
            for (int nf = 0; nf < 8; ++nf)
                *(float2*)(op + nf * 8 + q2) =
                    make_float2(acc[mt][nf][h8] * scl, acc[mt][nf][h8 + 1] * scl);
        }
    }
}

// ---------------- final: [gather(h2) | nodes] @ [Wmu|Wls] + bias ------------------
// smem: a_hi 0 (34816), a_lo 34816, b0h 69632, b0l 104448, b1h 139264,
//       b1l 174080, bias 208896 -> 209408
#define FINAL_SMEM 209408
__global__ __launch_bounds__(256, 1) void mma_final_kernel(
    const float4* __restrict__ Hin, const int* __restrict__ offs,
    const int* __restrict__ csr, const float4* __restrict__ nodes4,
    const uint8_t* __restrict__ w0hi, const uint8_t* __restrict__ w0lo,
    const uint8_t* __restrict__ w1hi, const uint8_t* __restrict__ w1lo,
    const float* __restrict__ bmu, const float* __restrict__ bls,
    float* __restrict__ out, int n, int tiles)
{
    extern __shared__ uint8_t sm[];
    uint8_t* a_hi = sm;
    uint8_t* a_lo = sm + 34816;
    float* bias_sm = (float*)(sm + 208896);

    const int tid = threadIdx.x, wid = tid >> 5, lane = tid & 31;
    const int mrow = (wid & 3) * 32;
    const int ch   = wid >> 2;
    const int ncol = ch * 64;
    const int q2   = (lane & 3) * 2;

    for (int idx = tid; idx < 2176; idx += 256) {
        ((uint4*)(sm + 69632))[idx]  = ((const uint4*)w0hi)[idx];
        ((uint4*)(sm + 104448))[idx] = ((const uint4*)w0lo)[idx];
        ((uint4*)(sm + 139264))[idx] = ((const uint4*)w1hi)[idx];
        ((uint4*)(sm + 174080))[idx] = ((const uint4*)w1lo)[idx];
    }
    if (tid < 64) bias_sm[tid] = bmu[tid];
    else if (tid < 128) bias_sm[tid] = bls[tid - 64];
    __syncthreads();

    float brg[16];
    #pragma unroll
    for (int nf = 0; nf < 8; ++nf) {
        brg[2 * nf]     = bias_sm[ncol + nf * 8 + q2];
        brg[2 * nf + 1] = bias_sm[ncol + nf * 8 + q2 + 1];
    }
    int rl[4];
    #pragma unroll
    for (int ri = 0; ri < 4; ++ri)
        rl[ri] = mrow + (ri >> 1) * 16 + (ri & 1) * 8 + (lane >> 2);

    const uint32_t smb  = smem_u32(sm);
    const uint32_t aoff = (lane & 15) * PKB + (lane >> 4) * 16;
    const uint32_t boff = ((lane >> 4) * 8 + (lane & 7)) * PKB + ((lane >> 3) & 1) * 16;
    const uint32_t aH  = smb + mrow * PKB + aoff;
    const uint32_t aL  = smb + 34816 + mrow * PKB + aoff;
    const uint32_t b0H = smb + 69632 + ncol * PKB + boff;
    const uint32_t b0L = smb + 104448 + ncol * PKB + boff;
    const uint32_t b1H = smb + 139264 + ncol * PKB + boff;
    const uint32_t b1L = smb + 174080 + ncol * PKB + boff;

    for (int t = blockIdx.x; t < tiles; t += gridDim.x) {
        const int row0 = t * 128;

        float acc[2][8][4];
        #pragma unroll
        for (int a = 0; a < 2; ++a)
            #pragma unroll
            for (int b = 0; b < 8; ++b)
                #pragma unroll
                for (int c = 0; c < 4; ++c) acc[a][b][c] = 0.f;

        __syncthreads();
        stage_gather_mma<8>(Hin, offs, csr, a_hi, a_lo, row0, n, wid, lane);
        __syncthreads();
        mma_block(acc, aH, aL, b0H, b0L);

        __syncthreads();   // all A reads complete before restage
        stage_rows_mma<8>(nodes4, a_hi, a_lo, row0, n, wid, lane);
        __syncthreads();
        mma_block(acc, aH, aL, b1H, b1L);

        #pragma unroll
        for (int ri = 0; ri < 4; ++ri) {
            const int mt = ri >> 1, h8 = (ri & 1) * 2;
            const int i = row0 + rl[ri];
            if (i >= n) continue;
            float* op = out + (ch ? (size_t)n * ZDIM : 0) + (size_t)i * ZDIM;
            #pragma unroll
            for (int nf = 0; nf < 8; ++nf)
                *(float2*)(op + nf * 8 + q2) =
                    make_float2(acc[mt][nf][h8]     + brg[2 * nf],
                                acc[mt][nf][h8 + 1] + brg[2 * nf + 1]);
        }
    }
}

// ---------------- launch ----------------------------------------------------------
extern "C" void kernel_launch(void* const* d_in, const int* in_sizes, int n_in,
                              void* d_out, int out_size)
{
    const float* nodes = (const float*)d_in[0];
    const int*   snd   = (const int*)d_in[1];
    const int*   rcv   = (const int*)d_in[2];
    const float* W0    = (const float*)d_in[3];
    const float* b0    = (const float*)d_in[4];
    const float* W1    = (const float*)d_in[5];
    const float* b1    = (const float*)d_in[6];
    const float* Wmu   = (const float*)d_in[7];
    const float* bmu   = (const float*)d_in[8];
    const float* Wls   = (const float*)d_in[9];
    const float* bls   = (const float*)d_in[10];
    float* out = (float*)d_out;

    const int n = in_sizes[0] / FIN;
    const int E = in_sizes[1];

    float *h, *h2;
    int *sdeg, *rdeg, *offs, *cursor, *csr;
    uint8_t *w0p, *w1p, *wfp;
    cudaGetSymbolAddress((void**)&h,      g_h);
    cudaGetSymbolAddress((void**)&h2,     g_h2);
    cudaGetSymbolAddress((void**)&sdeg,   g_sdeg);
    cudaGetSymbolAddress((void**)&rdeg,   g_rdeg);
    cudaGetSymbolAddress((void**)&offs,   g_offs);
    cudaGetSymbolAddress((void**)&cursor, g_cursor);
    cudaGetSymbolAddress((void**)&csr,    g_csr);
    cudaGetSymbolAddress((void**)&w0p,    g_w0p);
    cudaGetSymbolAddress((void**)&w1p,    g_w1p);
    cudaGetSymbolAddress((void**)&wfp,    g_wfp);

    cudaFuncSetAttribute(mma_dense_kernel, cudaFuncAttributeMaxDynamicSharedMemorySize, MMA_SMEM);
    cudaFuncSetAttribute(mma_final_kernel, cudaFuncAttributeMaxDynamicSharedMemorySize, FINAL_SMEM);

    const int tiles256 = (n + 255) / 256;
    const int tiles128 = (n + 127) / 128;
    const int IMG = 128 * PKB;

    // 0: prep (FIXED: 65536 entries)   1-2: degrees   (3: dense1 -> profiled)
    prep_w_kernel<<<256, 256>>>(W0, W1, Wmu, Wls);
    zero_deg_kernel<<<(n + 255) / 256, 256>>>(sdeg, rdeg, n);
    count_deg_kernel<<<(E + 255) / 256, 256>>>(snd, rcv, sdeg, rdeg, E);

    // 3: layer-1 dense (coalesced staging)
    mma_dense_kernel<<<148, 512, MMA_SMEM>>>(
        (const float4*)nodes, nullptr, nullptr, nullptr,
        w0p, w0p + IMG, b0, sdeg, h, n, tiles256);

    // 4-5: CSR build
    scan_kernel<<<1, 1024>>>(rdeg, offs, cursor, n);
    fill_kernel<<<(E + 255) / 256, 256>>>(snd, rcv, cursor, csr, E);

    // 6: layer-2 dense (fused gather) — reads h, writes h2
    mma_dense_kernel<<<148, 512, MMA_SMEM>>>(
        nullptr, (const float4*)h, offs, csr,
        w1p, w1p + IMG, b1, sdeg, h2, n, tiles256);

    // 7: final heads (fused gather + concat, K=256 two-pass)
    mma_final_kernel<<<148, 256, FINAL_SMEM>>>(
        (const float4*)h2, offs, csr, (const float4*)nodes,
        wfp, wfp + IMG, wfp + 2 * IMG, wfp + 3 * IMG,
        bmu, bls, out, n, tiles128);
}

// round 9
// speedup vs baseline: 3.9304x; 1.2971x over previous
#include <cuda_runtime.h>
#include <cuda_bf16.h>
#include <cstdint>

#define NMAX   100000
#define EMAX   600000
#define HID    128
#define FIN    128
#define ZDIM   64
#define PKB    272    // padded bf16 row pitch (136 bf16)

// ---------------- static device scratch --------------------------------------
__device__ float g_h [(size_t)NMAX * HID];
__device__ float g_h2[(size_t)NMAX * HID];
__device__ int   g_sdeg[NMAX];
__device__ int   g_rdeg[NMAX];
__device__ int   g_offs[NMAX + 1];
__device__ int   g_cursor[NMAX];
__device__ int   g_csr[EMAX];
__device__ __align__(16) uint8_t g_w0p[2][128 * PKB];      // [hi/lo]
__device__ __align__(16) uint8_t g_w1p[2][128 * PKB];      // [hi/lo]
__device__ __align__(16) uint8_t g_wfp[2][2][128 * PKB];   // [k-half][hi/lo]

// ---------------- PTX helpers --------------------------------------------------
__device__ __forceinline__ uint32_t smem_u32(const void* p) {
    uint32_t a;
    asm("{ .reg .u64 t; cvta.to.shared.u64 t, %1; cvt.u32.u64 %0, t; }" : "=r"(a) : "l"(p));
    return a;
}
__device__ __forceinline__ void ldsm4(uint32_t* r, uint32_t addr) {
    asm volatile("ldmatrix.sync.aligned.m8n8.x4.shared.b16 {%0,%1,%2,%3}, [%4];"
                 : "=r"(r[0]), "=r"(r[1]), "=r"(r[2]), "=r"(r[3]) : "r"(addr) : "memory");
}
__device__ __forceinline__ void mma_bf16(float* c, const uint32_t* a,
                                         uint32_t b0, uint32_t b1) {
    asm volatile(
        "mma.sync.aligned.m16n8k16.row.col.f32.bf16.bf16.f32 "
        "{%0,%1,%2,%3}, {%4,%5,%6,%7}, {%8,%9}, {%0,%1,%2,%3};"
        : "+f"(c[0]), "+f"(c[1]), "+f"(c[2]), "+f"(c[3])
        : "r"(a[0]), "r"(a[1]), "r"(a[2]), "r"(a[3]), "r"(b0), "r"(b1));
}
__device__ __forceinline__ uint32_t bf2u(__nv_bfloat162 v) {
    return *reinterpret_cast<uint32_t*>(&v);
}

// ---------------- degree / CSR build -------------------------------------------
__global__ void zero_deg_kernel(int* sdeg, int* rdeg, int n) {
    int t = blockIdx.x * blockDim.x + threadIdx.x;
    if (t < n) { sdeg[t] = 0; rdeg[t] = 0; }
}
__global__ void count_deg_kernel(const int* __restrict__ snd, const int* __restrict__ rcv,
                                 int* sdeg, int* rdeg, int E) {
    int t = blockIdx.x * blockDim.x + threadIdx.x;
    if (t < E) {
        atomicAdd(&sdeg[snd[t]], 1);
        atomicAdd(&rdeg[rcv[t]], 1);
    }
}
__global__ __launch_bounds__(1024) void scan_kernel(
    const int* __restrict__ deg, int* __restrict__ offs, int* __restrict__ cursor, int n)
{
    __shared__ int warpsum[32];
    __shared__ int carry_sh;
    const int tid = threadIdx.x, lane = tid & 31, warp = tid >> 5;
    int carry = 0;
    for (int base = 0; base < n; base += 4096) {
        int idx = base + tid * 4;
        int4 v = make_int4(0, 0, 0, 0);
        if (idx + 3 < n) v = *(const int4*)(deg + idx);
        else {
            if (idx     < n) v.x = deg[idx];
            if (idx + 1 < n) v.y = deg[idx + 1];
            if (idx + 2 < n) v.z = deg[idx + 2];
        }
        int s0 = v.x, s1 = s0 + v.y, s2 = s1 + v.z, s3 = s2 + v.w;
        int inc = s3;
        #pragma unroll
        for (int o = 1; o < 32; o <<= 1) {
            int t = __shfl_up_sync(0xffffffffu, inc, o);
            if (lane >= o) inc += t;
        }
        if (lane == 31) warpsum[warp] = inc;
        __syncthreads();
        if (warp == 0) {
            int w = warpsum[lane];
            int wi = w;
            #pragma unroll
            for (int o = 1; o < 32; o <<= 1) {
                int t = __shfl_up_sync(0xffffffffu, wi, o);
                if (lane >= o) wi += t;
            }
            warpsum[lane] = wi - w;
        }
        __syncthreads();
        int texcl = carry + warpsum[warp] + inc - s3;
        int4 o4 = make_int4(texcl, texcl + s0, texcl + s1, texcl + s2);
        if (idx + 3 < n) {
            *(int4*)(offs + idx)   = o4;
            *(int4*)(cursor + idx) = o4;
        } else {
            if (idx     < n) { offs[idx]     = o4.x; cursor[idx]     = o4.x; }
            if (idx + 1 < n) { offs[idx + 1] = o4.y; cursor[idx + 1] = o4.y; }
            if (idx + 2 < n) { offs[idx + 2] = o4.z; cursor[idx + 2] = o4.z; }
        }
        if (tid == 1023) carry_sh = texcl + s3;
        __syncthreads();
        carry = carry_sh;
    }
    if (tid == 0) offs[n] = carry;
}
__global__ void fill_kernel(const int* __restrict__ snd, const int* __restrict__ rcv,
                            int* cursor, int* __restrict__ csr, int E)
{
    int t = blockIdx.x * blockDim.x + threadIdx.x;
    if (t < E) {
        int r = rcv[t];
        int p = atomicAdd(&cursor[r], 1);
        csr[p] = snd[t];
    }
}

// ---------------- weight prep ------------------------------------------------------
__global__ void prep_w_kernel(const float* __restrict__ W0, const float* __restrict__ W1,
                              const float* __restrict__ Wmu, const float* __restrict__ Wls)
{
    int idx = blockIdx.x * blockDim.x + threadIdx.x;
    if (idx >= 65536) return;
    float v; uint8_t *bh, *bl; int row, col;
    if (idx < 16384) {
        int k = idx >> 7, nn = idx & 127;
        v = W0[idx]; row = nn; col = k; bh = g_w0p[0]; bl = g_w0p[1];
    } else if (idx < 32768) {
        int r = idx - 16384;
        int k = r >> 7, nn = r & 127;
        v = W1[r]; row = nn; col = k; bh = g_w1p[0]; bl = g_w1p[1];
    } else {
        int r = idx - 32768;
        int half = r >> 14, r2 = r & 16383;
        int kl = r2 >> 7, nn = r2 & 127;
        int kg = half * 128 + kl;
        v = (nn < 64) ? Wmu[kg * 64 + nn] : Wls[kg * 64 + (nn - 64)];
        row = nn; col = kl; bh = g_wfp[half][0]; bl = g_wfp[half][1];
    }
    __nv_bfloat16 h = __float2bfloat16(v);
    __nv_bfloat16 l = __float2bfloat16(v - __bfloat162float(h));
    *(__nv_bfloat16*)(bh + row * PKB + col * 2) = h;
    *(__nv_bfloat16*)(bl + row * PKB + col * 2) = l;
}

// ---------------- staging: coalesced rows (NW warps stage NW*16 rows) ---------------
template <int NW>
__device__ __forceinline__ void stage_rows_mma(
    const float4* __restrict__ X4, uint8_t* a_hi, uint8_t* a_lo,
    int row0, int n, int wid, int lane)
{
    #pragma unroll 4
    for (int rr = 0; rr < 16; ++rr) {
        int r = wid * 16 + rr;
        int i = row0 + r;
        float4 v = make_float4(0.f, 0.f, 0.f, 0.f);
        if (i < n) v = X4[(size_t)i * 32 + lane];
        __nv_bfloat162 h01 = __floats2bfloat162_rn(v.x, v.y);
        __nv_bfloat162 h23 = __floats2bfloat162_rn(v.z, v.w);
        float2 f01 = __bfloat1622float2(h01);
        float2 f23 = __bfloat1622float2(h23);
        __nv_bfloat162 l01 = __floats2bfloat162_rn(v.x - f01.x, v.y - f01.y);
        __nv_bfloat162 l23 = __floats2bfloat162_rn(v.z - f23.x, v.w - f23.y);
        uint32_t off = (uint32_t)r * PKB + lane * 8;
        *(uint2*)(a_hi + off) = make_uint2(bf2u(h01), bf2u(h23));
        *(uint2*)(a_lo + off) = make_uint2(bf2u(l01), bf2u(l23));
    }
}

// ---------------- staging: CSR gather, 8 threads/row, dual-buffer pipeline ----------
// Warp covers 4 rows (lane>>3); cseg = lane&7 covers 16 cols (4 float4).
// ROWS total rows per tile; passes = ROWS/(NW*4).
template <int NW, int ROWS>
__device__ __forceinline__ void stage_gather_mma(
    const float4* __restrict__ H4, const int* __restrict__ offs,
    const int* __restrict__ csr, uint8_t* a_hi, uint8_t* a_lo,
    int row0, int n, int wid, int lane)
{
    const int cseg = lane & 7;
    #pragma unroll
    for (int pass = 0; pass < ROWS / (NW * 4); ++pass) {
        int r = pass * (NW * 4) + wid * 4 + (lane >> 3);
        int i = row0 + r;
        float acc[16];
        #pragma unroll
        for (int q = 0; q < 16; ++q) acc[q] = 0.f;
        float scl = 1.f;
        if (i < n) {
            int beg = __ldg(&offs[i]), end = __ldg(&offs[i + 1]);
            if (beg < end) {
                // prime pipeline
                const float4* p = H4 + (size_t)__ldg(&csr[beg]) * 32 + cseg * 4;
                float4 c0 = __ldg(p), c1 = __ldg(p + 1), c2 = __ldg(p + 2), c3 = __ldg(p + 3);
                for (int e = beg + 1; e < end; ++e) {
                    const float4* np = H4 + (size_t)__ldg(&csr[e]) * 32 + cseg * 4;
                    float4 n0 = __ldg(np), n1 = __ldg(np + 1),
                           n2 = __ldg(np + 2), n3 = __ldg(np + 3);
                    acc[0]  += c0.x; acc[1]  += c0.y; acc[2]  += c0.z; acc[3]  += c0.w;
                    acc[4]  += c1.x; acc[5]  += c1.y; acc[6]  += c1.z; acc[7]  += c1.w;
                    acc[8]  += c2.x; acc[9]  += c2.y; acc[10] += c2.z; acc[11] += c2.w;
                    acc[12] += c3.x; acc[13] += c3.y; acc[14] += c3.z; acc[15] += c3.w;
                    c0 = n0; c1 = n1; c2 = n2; c3 = n3;
                }
                acc[0]  += c0.x; acc[1]  += c0.y; acc[2]  += c0.z; acc[3]  += c0.w;
                acc[4]  += c1.x; acc[5]  += c1.y; acc[6]  += c1.z; acc[7]  += c1.w;
                acc[8]  += c2.x; acc[9]  += c2.y; acc[10] += c2.z; acc[11] += c2.w;
                acc[12] += c3.x; acc[13] += c3.y; acc[14] += c3.z; acc[15] += c3.w;
            }
            scl = rsqrtf(fmaxf((float)(end - beg), 1.f));
        }
        #pragma unroll
        for (int q = 0; q < 16; ++q) acc[q] *= scl;

        #pragma unroll
        for (int qq = 0; qq < 4; ++qq) {
            float x0 = acc[4 * qq], x1 = acc[4 * qq + 1];
            float x2 = acc[4 * qq + 2], x3 = acc[4 * qq + 3];
            __nv_bfloat162 h01 = __floats2bfloat162_rn(x0, x1);
            __nv_bfloat162 h23 = __floats2bfloat162_rn(x2, x3);
            float2 f01 = __bfloat1622float2(h01);
            float2 f23 = __bfloat1622float2(h23);
            __nv_bfloat162 l01 = __floats2bfloat162_rn(x0 - f01.x, x1 - f01.y);
            __nv_bfloat162 l23 = __floats2bfloat162_rn(x2 - f23.x, x3 - f23.y);
            uint32_t off = (uint32_t)r * PKB + (cseg * 16 + 4 * qq) * 2;
            *(uint2*)(a_hi + off) = make_uint2(bf2u(h01), bf2u(h23));
            *(uint2*)(a_lo + off) = make_uint2(bf2u(l01), bf2u(l23));
        }
    }
}

// ---------------- 3-term bf16 MMA, one K=128 block, m32 x (NF16*16) per warp ---------
template <int NF16>
__device__ __forceinline__ void mma_block_t(
    float acc[2][NF16 * 2][4], uint32_t aH, uint32_t aL, uint32_t bH, uint32_t bL)
{
    #pragma unroll
    for (int k16 = 0; k16 < 8; ++k16) {
        const uint32_t kb = k16 * 32;
        uint32_t ah0[4], ah1[4], al0[4], al1[4];
        ldsm4(ah0, aH + kb);
        ldsm4(ah1, aH + 16 * PKB + kb);
        ldsm4(al0, aL + kb);
        ldsm4(al1, aL + 16 * PKB + kb);
        #pragma unroll
        for (int nf16 = 0; nf16 < NF16; ++nf16) {
            uint32_t bh[4], bl[4];
            ldsm4(bh, bH + nf16 * 16 * PKB + kb);
            ldsm4(bl, bL + nf16 * 16 * PKB + kb);
            const int nf = nf16 * 2;
            mma_bf16(acc[0][nf],     ah0, bh[0], bh[1]);
            mma_bf16(acc[0][nf],     ah0, bl[0], bl[1]);
            mma_bf16(acc[0][nf],     al0, bh[0], bh[1]);
            mma_bf16(acc[0][nf + 1], ah0, bh[2], bh[3]);
            mma_bf16(acc[0][nf + 1], ah0, bl[2], bl[3]);
            mma_bf16(acc[0][nf + 1], al0, bh[2], bh[3]);
            mma_bf16(acc[1][nf],     ah1, bh[0], bh[1]);
            mma_bf16(acc[1][nf],     ah1, bl[0], bl[1]);
            mma_bf16(acc[1][nf],     al1, bh[0], bh[1]);
            mma_bf16(acc[1][nf + 1], ah1, bh[2], bh[3]);
            mma_bf16(acc[1][nf + 1], ah1, bl[2], bl[3]);
            mma_bf16(acc[1][nf + 1], al1, bh[2], bh[3]);
        }
    }
}

// ---------------- dense GC layer: 512 threads, 256-row tiles ------------------------
// smem: a_hi 0 (69632), a_lo 69632, b_hi 139264, b_lo 174080,
//       bias 208896, red1 209408, red2 211456 -> 213504
#define MMA_SMEM 213504
__global__ __launch_bounds__(512, 1) void mma_dense_kernel(
    const float4* __restrict__ X4, const float4* __restrict__ Hin,
    const int* __restrict__ offs, const int* __restrict__ csr,
    const uint8_t* __restrict__ whi, const uint8_t* __restrict__ wlo,
    const float* __restrict__ bias, const int* __restrict__ sdeg,
    float* __restrict__ Hout, int n, int tiles)
{
    extern __shared__ uint8_t sm[];
    uint8_t* a_hi = sm;
    uint8_t* a_lo = sm + 69632;
    float* bias_sm = (float*)(sm + 208896);
    float* red1    = (float*)(sm + 209408);
    float* red2    = (float*)(sm + 211456);

    const int tid = threadIdx.x, wid = tid >> 5, lane = tid & 31;
    const int sub  = wid >> 3;
    const int mrow = (wid & 3) * 32 + sub * 128;
    const int ch   = (wid >> 2) & 1;
    const int ncol = ch * 64;
    const int q2   = (lane & 3) * 2;

    for (int idx = tid; idx < 2176; idx += 512) {
        ((uint4*)(sm + 139264))[idx] = ((const uint4*)whi)[idx];
        ((uint4*)(sm + 174080))[idx] = ((const uint4*)wlo)[idx];
    }
    if (tid < 128) bias_sm[tid] = bias[tid];
    __syncthreads();

    float brg[16];
    #pragma unroll
    for (int nf = 0; nf < 8; ++nf) {
        brg[2 * nf]     = bias_sm[ncol + nf * 8 + q2];
        brg[2 * nf + 1] = bias_sm[ncol + nf * 8 + q2 + 1];
    }
    int rl[4];
    #pragma unroll
    for (int ri = 0; ri < 4; ++ri)
        rl[ri] = mrow + (ri >> 1) * 16 + (ri & 1) * 8 + (lane >> 2);

    const uint32_t smb  = smem_u32(sm);
    const uint32_t aoff = (lane & 15) * PKB + (lane >> 4) * 16;
    const uint32_t boff = ((lane >> 4) * 8 + (lane & 7)) * PKB + ((lane >> 3) & 1) * 16;
    const uint32_t aH = smb + mrow * PKB + aoff;
    const uint32_t aL = smb + 69632 + mrow * PKB + aoff;
    const uint32_t bH = smb + 139264 + ncol * PKB + boff;
    const uint32_t bL = smb + 174080 + ncol * PKB + boff;

    for (int t = blockIdx.x; t < tiles; t += gridDim.x) {
        const int row0 = t * 256;
        __syncthreads();
        if (csr) stage_gather_mma<16, 256>(Hin, offs, csr, a_hi, a_lo, row0, n, wid, lane);
        else     stage_rows_mma<16>(X4, a_hi, a_lo, row0, n, wid, lane);
        __syncthreads();

        float acc[2][8][4];
        #pragma unroll
        for (int a = 0; a < 2; ++a)
            #pragma unroll
            for (int b = 0; b < 8; ++b)
                #pragma unroll
                for (int c = 0; c < 4; ++c) acc[a][b][c] = 0.f;

        mma_block_t<4>(acc, aH, aL, bH, bL);

        // epilogue: bias + relu + softmax(128) + rsqrt(sdeg)
        float rmax[4];
        #pragma unroll
        for (int ri = 0; ri < 4; ++ri) {
            const int mt = ri >> 1, h8 = (ri & 1) * 2;
            float m = -3.4e38f;
            #pragma unroll
            for (int nf = 0; nf < 8; ++nf) {
                float x0 = fmaxf(acc[mt][nf][h8]     + brg[2 * nf],     0.f);
                float x1 = fmaxf(acc[mt][nf][h8 + 1] + brg[2 * nf + 1], 0.f);
                acc[mt][nf][h8] = x0; acc[mt][nf][h8 + 1] = x1;
                m = fmaxf(m, fmaxf(x0, x1));
            }
            m = fmaxf(m, __shfl_xor_sync(0xffffffffu, m, 1));
            m = fmaxf(m, __shfl_xor_sync(0xffffffffu, m, 2));
            rmax[ri] = m;
            red1[ch * 256 + rl[ri]] = m;
        }
        __syncthreads();
        #pragma unroll
        for (int ri = 0; ri < 4; ++ri) {
            const int mt = ri >> 1, h8 = (ri & 1) * 2;
            float m = fmaxf(rmax[ri], red1[(ch ^ 1) * 256 + rl[ri]]);
            float s = 0.f;
            #pragma unroll
            for (int nf = 0; nf < 8; ++nf) {
                float v0 = __expf(acc[mt][nf][h8] - m);
                float v1 = __expf(acc[mt][nf][h8 + 1] - m);
                acc[mt][nf][h8] = v0; acc[mt][nf][h8 + 1] = v1;
                s += v0 + v1;
            }
            s += __shfl_xor_sync(0xffffffffu, s, 1);
            s += __shfl_xor_sync(0xffffffffu, s, 2);
            red2[ch * 256 + rl[ri]] = s;
        }
        __syncthreads();
        #pragma unroll
        for (int ri = 0; ri < 4; ++ri) {
            const int mt = ri >> 1, h8 = (ri & 1) * 2;
            const int i = row0 + rl[ri];
            if (i >= n) continue;
            float s = red2[rl[ri]] + red2[256 + rl[ri]];
            float scl = rsqrtf(fmaxf((float)__ldg(&sdeg[i]), 1.f)) / s;
            float* op = Hout + (size_t)i * HID + ncol;
            #pragma unroll
            for (int nf = 0; nf < 8; ++nf)
                *(float2*)(op + nf * 8 + q2) =
                    make_float2(acc[mt][nf][h8] * scl, acc[mt][nf][h8 + 1] * scl);
        }
    }
}

// ---------------- final: 512 threads, m32xn32 warps, K=256 two-pass ------------------
// smem: a_hi 0 (34816), a_lo 34816, b0h 69632, b0l 104448, b1h 139264,
//       b1l 174080, bias 208896 -> 209408
#define FINAL_SMEM 209408
__global__ __launch_bounds__(512, 1) void mma_final_kernel(
    const float4* __restrict__ Hin, const int* __restrict__ offs,
    const int* __restrict__ csr, const float4* __restrict__ nodes4,
    const uint8_t* __restrict__ w0hi, const uint8_t* __restrict__ w0lo,
    const uint8_t* __restrict__ w1hi, const uint8_t* __restrict__ w1lo,
    const float* __restrict__ bmu, const float* __restrict__ bls,
    float* __restrict__ out, int n, int tiles)
{
    extern __shared__ uint8_t sm[];
    uint8_t* a_hi = sm;
    uint8_t* a_lo = sm + 34816;
    float* bias_sm = (float*)(sm + 208896);

    const int tid = threadIdx.x, wid = tid >> 5, lane = tid & 31;
    const int mrow = (wid & 3) * 32;
    const int nsub = (wid >> 2) & 1;
    const int ch   = wid >> 3;
    const int ncol = ch * 64 + nsub * 32;    // combined column base (n32 per warp)
    const int q2   = (lane & 3) * 2;

    for (int idx = tid; idx < 2176; idx += 512) {
        ((uint4*)(sm + 69632))[idx]  = ((const uint4*)w0hi)[idx];
        ((uint4*)(sm + 104448))[idx] = ((const uint4*)w0lo)[idx];
        ((uint4*)(sm + 139264))[idx] = ((const uint4*)w1hi)[idx];
        ((uint4*)(sm + 174080))[idx] = ((const uint4*)w1lo)[idx];
    }
    if (tid < 64) bias_sm[tid] = bmu[tid];
    else if (tid < 128) bias_sm[tid] = bls[tid - 64];
    __syncthreads();

    float brg[8];
    #pragma unroll
    for (int nf = 0; nf < 4; ++nf) {
        brg[2 * nf]     = bias_sm[ncol + nf * 8 + q2];
        brg[2 * nf + 1] = bias_sm[ncol + nf * 8 + q2 + 1];
    }
    int rl[4];
    #pragma unroll
    for (int ri = 0; ri < 4; ++ri)
        rl[ri] = mrow + (ri >> 1) * 16 + (ri & 1) * 8 + (lane >> 2);

    const uint32_t smb  = smem_u32(sm);
    const uint32_t aoff = (lane & 15) * PKB + (lane >> 4) * 16;
    const uint32_t boff = ((lane >> 4) * 8 + (lane & 7)) * PKB + ((lane >> 3) & 1) * 16;
    const uint32_t aH  = smb + mrow * PKB + aoff;
    const uint32_t aL  = smb + 34816 + mrow * PKB + aoff;
    const uint32_t b0H = smb + 69632 + ncol * PKB + boff;
    const uint32_t b0L = smb + 104448 + ncol * PKB + boff;
    const uint32_t b1H = smb + 139264 + ncol * PKB + boff;
    const uint32_t b1L = smb + 174080 + ncol * PKB + boff;

    const int cc0 = nsub * 32;   // output column base within the 64-wide head

    for (int t = blockIdx.x; t < tiles; t += gridDim.x) {
        const int row0 = t * 128;

        float acc[2][4][4];
        #pragma unroll
        for (int a = 0; a < 2; ++a)
            #pragma unroll
            for (int b = 0; b < 4; ++b)
                #pragma unroll
                for (int c = 0; c < 4; ++c) acc[a][b][c] = 0.f;

        __syncthreads();
        stage_gather_mma<16, 128>(Hin, offs, csr, a_hi, a_lo, row0, n, wid, lane);
        __syncthreads();
        mma_block_t<2>(acc, aH, aL, b0H, b0L);

        __syncthreads();   // all A reads complete before restage
        stage_rows_mma<16>(nodes4, a_hi, a_lo, row0, n, wid, lane);
        // NOTE: stage_rows_mma<16> covers rows 0..255 but tile is 128 rows;
        // guard: only warps 0..7 have rows < 128. Warps 8-15 write rows 128-255
        // out of the A buffer! Use 8-warp staging with wid&7 instead:
        __syncthreads();
        mma_block_t<2>(acc, aH, aL, b1H, b1L);

        #pragma unroll
        for (int ri = 0; ri < 4; ++ri) {
            const int mt = ri >> 1, h8 = (ri & 1) * 2;
            const int i = row0 + rl[ri];
            if (i >= n) continue;
            float* op = out + (ch ? (size_t)n * ZDIM : 0) + (size_t)i * ZDIM + cc0;
            #pragma unroll
            for (int nf = 0; nf < 4; ++nf)
                *(float2*)(op + nf * 8 + q2) =
                    make_float2(acc[mt][nf][h8]     + brg[2 * nf],
                                acc[mt][nf][h8 + 1] + brg[2 * nf + 1]);
        }
    }
}

// 8-warp-row staging for 128-row tiles at 512 threads: warps 0-7 stage, 8-15 idle.
// Implemented by replacing the call above via a wrapper is cleaner, but to keep a
// single staging routine, mma_final uses a dedicated variant below.
// (The stage_rows_mma<16> call above is REPLACED at compile time by this macro.)
// -- To avoid the hazard flagged above, we redefine the staging in-place:
//    see stage_rows_half() used in the actual kernel body.

// ---------------- launch -------------------------------------------------------------
extern "C" void kernel_launch(void* const* d_in, const int* in_sizes, int n_in,
                              void* d_out, int out_size);

// Variant of stage_rows for 512 threads covering only 128 rows (8 rows per warp).
__device__ __forceinline__ void stage_rows_half(
    const float4* __restrict__ X4, uint8_t* a_hi, uint8_t* a_lo,
    int row0, int n, int wid, int lane)
{
    #pragma unroll 4
    for (int rr = 0; rr < 8; ++rr) {
        int r = wid * 8 + rr;
        int i = row0 + r;
        float4 v = make_float4(0.f, 0.f, 0.f, 0.f);
        if (i < n) v = X4[(size_t)i * 32 + lane];
        __nv_bfloat162 h01 = __floats2bfloat162_rn(v.x, v.y);
        __nv_bfloat162 h23 = __floats2bfloat162_rn(v.z, v.w);
        float2 f01 = __bfloat1622float2(h01);
        float2 f23 = __bfloat1622float2(h23);
        __nv_bfloat162 l01 = __floats2bfloat162_rn(v.x - f01.x, v.y - f01.y);
        __nv_bfloat162 l23 = __floats2bfloat162_rn(v.z - f23.x, v.w - f23.y);
        uint32_t off = (uint32_t)r * PKB + lane * 8;
        *(uint2*)(a_hi + off) = make_uint2(bf2u(h01), bf2u(h23));
        *(uint2*)(a_lo + off) = make_uint2(bf2u(l01), bf2u(l23));
    }
}

// Corrected final kernel (the one actually launched).
__global__ __launch_bounds__(512, 1) void mma_final_kernel2(
    const float4* __restrict__ Hin, const int* __restrict__ offs,
    const int* __restrict__ csr, const float4* __restrict__ nodes4,
    const uint8_t* __restrict__ w0hi, const uint8_t* __restrict__ w0lo,
    const uint8_t* __restrict__ w1hi, const uint8_t* __restrict__ w1lo,
    const float* __restrict__ bmu, const float* __restrict__ bls,
    float* __restrict__ out, int n, int tiles)
{
    extern __shared__ uint8_t sm[];
    uint8_t* a_hi = sm;
    uint8_t* a_lo = sm + 34816;
    float* bias_sm = (float*)(sm + 208896);

    const int tid = threadIdx.x, wid = tid >> 5, lane = tid & 31;
    const int mrow = (wid & 3) * 32;
    const int nsub = (wid >> 2) & 1;
    const int ch   = wid >> 3;
    const int ncol = ch * 64 + nsub * 32;
    const int q2   = (lane & 3) * 2;

    for (int idx = tid; idx < 2176; idx += 512) {
        ((uint4*)(sm + 69632))[idx]  = ((const uint4*)w0hi)[idx];
        ((uint4*)(sm + 104448))[idx] = ((const uint4*)w0lo)[idx];
        ((uint4*)(sm + 139264))[idx] = ((const uint4*)w1hi)[idx];
        ((uint4*)(sm + 174080))[idx] = ((const uint4*)w1lo)[idx];
    }
    if (tid < 64) bias_sm[tid] = bmu[tid];
    else if (tid < 128) bias_sm[tid] = bls[tid - 64];
    __syncthreads();

    float brg[8];
    #pragma unroll
    for (int nf = 0; nf < 4; ++nf) {
        brg[2 * nf]     = bias_sm[ncol + nf * 8 + q2];
        brg[2 * nf + 1] = bias_sm[ncol + nf * 8 + q2 + 1];
    }
    int rl[4];
    #pragma unroll
    for (int ri = 0; ri < 4; ++ri)
        rl[ri] = mrow + (ri >> 1) * 16 + (ri & 1) * 8 + (lane >> 2);

    const uint32_t smb  = smem_u32(sm);
    const uint32_t aoff = (lane & 15) * PKB + (lane >> 4) * 16;
    const uint32_t boff = ((lane >> 4) * 8 + (lane & 7)) * PKB + ((lane >> 3) & 1) * 16;
    const uint32_t aH  = smb + mrow * PKB + aoff;
    const uint32_t aL  = smb + 34816 + mrow * PKB + aoff;
    const uint32_t b0H = smb + 69632 + ncol * PKB + boff;
    const uint32_t b0L = smb + 104448 + ncol * PKB + boff;
    const uint32_t b1H = smb + 139264 + ncol * PKB + boff;
    const uint32_t b1L = smb + 174080 + ncol * PKB + boff;

    const int cc0 = nsub * 32;

    for (int t = blockIdx.x; t < tiles; t += gridDim.x) {
        const int row0 = t * 128;

        float acc[2][4][4];
        #pragma unroll
        for (int a = 0; a < 2; ++a)
            #pragma unroll
            for (int b = 0; b < 4; ++b)
                #pragma unroll
                for (int c = 0; c < 4; ++c) acc[a][b][c] = 0.f;

        __syncthreads();
        stage_gather_mma<16, 128>(Hin, offs, csr, a_hi, a_lo, row0, n, wid, lane);
        __syncthreads();
        mma_block_t<2>(acc, aH, aL, b0H, b0L);

        __syncthreads();
        stage_rows_half(nodes4, a_hi, a_lo, row0, n, wid, lane);
        __syncthreads();
        mma_block_t<2>(acc, aH, aL, b1H, b1L);

        #pragma unroll
        for (int ri = 0; ri < 4; ++ri) {
            const int mt = ri >> 1, h8 = (ri & 1) * 2;
            const int i = row0 + rl[ri];
            if (i >= n) continue;
            float* op = out + (ch ? (size_t)n * ZDIM : 0) + (size_t)i * ZDIM + cc0;
            #pragma unroll
            for (int nf = 0; nf < 4; ++nf)
                *(float2*)(op + nf * 8 + q2) =
                    make_float2(acc[mt][nf][h8]     + brg[2 * nf],
                                acc[mt][nf][h8 + 1] + brg[2 * nf + 1]);
        }
    }
}

extern "C" void kernel_launch(void* const* d_in, const int* in_sizes, int n_in,
                              void* d_out, int out_size)
{
    const float* nodes = (const float*)d_in[0];
    const int*   snd   = (const int*)d_in[1];
    const int*   rcv   = (const int*)d_in[2];
    const float* W0    = (const float*)d_in[3];
    const float* b0    = (const float*)d_in[4];
    const float* W1    = (const float*)d_in[5];
    const float* b1    = (const float*)d_in[6];
    const float* Wmu   = (const float*)d_in[7];
    const float* bmu   = (const float*)d_in[8];
    const float* Wls   = (const float*)d_in[9];
    const float* bls   = (const float*)d_in[10];
    float* out = (float*)d_out;

    const int n = in_sizes[0] / FIN;
    const int E = in_sizes[1];

    float *h, *h2;
    int *sdeg, *rdeg, *offs, *cursor, *csr;
    uint8_t *w0p, *w1p, *wfp;
    cudaGetSymbolAddress((void**)&h,      g_h);
    cudaGetSymbolAddress((void**)&h2,     g_h2);
    cudaGetSymbolAddress((void**)&sdeg,   g_sdeg);
    cudaGetSymbolAddress((void**)&rdeg,   g_rdeg);
    cudaGetSymbolAddress((void**)&offs,   g_offs);
    cudaGetSymbolAddress((void**)&cursor, g_cursor);
    cudaGetSymbolAddress((void**)&csr,    g_csr);
    cudaGetSymbolAddress((void**)&w0p,    g_w0p);
    cudaGetSymbolAddress((void**)&w1p,    g_w1p);
    cudaGetSymbolAddress((void**)&wfp,    g_wfp);

    cudaFuncSetAttribute(mma_dense_kernel,  cudaFuncAttributeMaxDynamicSharedMemorySize, MMA_SMEM);
    cudaFuncSetAttribute(mma_final_kernel2, cudaFuncAttributeMaxDynamicSharedMemorySize, FINAL_SMEM);

    const int tiles256 = (n + 255) / 256;
    const int tiles128 = (n + 127) / 128;
    const int IMG = 128 * PKB;

    // 0: prep   1-2: degrees   (3: dense1 -> profiled)
    prep_w_kernel<<<256, 256>>>(W0, W1, Wmu, Wls);
    zero_deg_kernel<<<(n + 255) / 256, 256>>>(sdeg, rdeg, n);
    count_deg_kernel<<<(E + 255) / 256, 256>>>(snd, rcv, sdeg, rdeg, E);

    // 3: layer-1 dense (coalesced staging)
    mma_dense_kernel<<<148, 512, MMA_SMEM>>>(
        (const float4*)nodes, nullptr, nullptr, nullptr,
        w0p, w0p + IMG, b0, sdeg, h, n, tiles256);

    // 4-5: CSR build
    scan_kernel<<<1, 1024>>>(rdeg, offs, cursor, n);
    fill_kernel<<<(E + 255) / 256, 256>>>(snd, rcv, cursor, csr, E);

    // 6: layer-2 dense (fused pipelined gather) — reads h, writes h2
    mma_dense_kernel<<<148, 512, MMA_SMEM>>>(
        nullptr, (const float4*)h, offs, csr,
        w1p, w1p + IMG, b1, sdeg, h2, n, tiles256);

    // 7: final heads (fused gather + concat, 512 threads)
    mma_final_kernel2<<<148, 512, FINAL_SMEM>>>(
        (const float4*)h2, offs, csr, (const float4*)nodes,
        wfp, wfp + IMG, wfp + 2 * IMG, wfp + 3 * IMG,
        bmu, bls, out, n, tiles128);
}

// round 10
// speedup vs baseline: 4.1415x; 1.0537x over previous
#include <cuda_runtime.h>
#include <cuda_bf16.h>
#include <cstdint>

#define NMAX   100000
#define EMAX   600000
#define HID    128
#define FIN    128
#define ZDIM   64
#define PKB    272    // padded bf16 row pitch (136 bf16)

// ---------------- static device scratch --------------------------------------
__device__ float g_h [(size_t)NMAX * HID];
__device__ float g_h2[(size_t)NMAX * HID];
__device__ int   g_sdeg[NMAX];
__device__ int   g_rdeg[NMAX];
__device__ int   g_offs[NMAX + 1];
__device__ int   g_cursor[NMAX];
__device__ int   g_csr[EMAX];
__device__ __align__(16) uint8_t g_w0p[2][128 * PKB];      // [hi/lo]
__device__ __align__(16) uint8_t g_w1p[2][128 * PKB];      // [hi/lo]
__device__ __align__(16) uint8_t g_wfp[2][2][128 * PKB];   // [k-half][hi/lo]

// ---------------- PTX helpers --------------------------------------------------
__device__ __forceinline__ uint32_t smem_u32(const void* p) {
    uint32_t a;
    asm("{ .reg .u64 t; cvta.to.shared.u64 t, %1; cvt.u32.u64 %0, t; }" : "=r"(a) : "l"(p));
    return a;
}
__device__ __forceinline__ void ldsm4(uint32_t* r, uint32_t addr) {
    asm volatile("ldmatrix.sync.aligned.m8n8.x4.shared.b16 {%0,%1,%2,%3}, [%4];"
                 : "=r"(r[0]), "=r"(r[1]), "=r"(r[2]), "=r"(r[3]) : "r"(addr) : "memory");
}
__device__ __forceinline__ void mma_bf16(float* c, const uint32_t* a,
                                         uint32_t b0, uint32_t b1) {
    asm volatile(
        "mma.sync.aligned.m16n8k16.row.col.f32.bf16.bf16.f32 "
        "{%0,%1,%2,%3}, {%4,%5,%6,%7}, {%8,%9}, {%0,%1,%2,%3};"
        : "+f"(c[0]), "+f"(c[1]), "+f"(c[2]), "+f"(c[3])
        : "r"(a[0]), "r"(a[1]), "r"(a[2]), "r"(a[3]), "r"(b0), "r"(b1));
}
__device__ __forceinline__ uint32_t bf2u(__nv_bfloat162 v) {
    return *reinterpret_cast<uint32_t*>(&v);
}

// ---------------- fused prep + degree-zero ---------------------------------------
__global__ void prep_zero_kernel(const float* __restrict__ W0, const float* __restrict__ W1,
                                 const float* __restrict__ Wmu, const float* __restrict__ Wls,
                                 int* sdeg, int* rdeg, int n)
{
    int idx = blockIdx.x * blockDim.x + threadIdx.x;
    if (idx < n) { sdeg[idx] = 0; rdeg[idx] = 0; }
    if (idx >= 65536) return;
    float v; uint8_t *bh, *bl; int row, col;
    if (idx < 16384) {
        int k = idx >> 7, nn = idx & 127;
        v = W0[idx]; row = nn; col = k; bh = g_w0p[0]; bl = g_w0p[1];
    } else if (idx < 32768) {
        int r = idx - 16384;
        int k = r >> 7, nn = r & 127;
        v = W1[r]; row = nn; col = k; bh = g_w1p[0]; bl = g_w1p[1];
    } else {
        int r = idx - 32768;
        int half = r >> 14, r2 = r & 16383;
        int kl = r2 >> 7, nn = r2 & 127;
        int kg = half * 128 + kl;
        v = (nn < 64) ? Wmu[kg * 64 + nn] : Wls[kg * 64 + (nn - 64)];
        row = nn; col = kl; bh = g_wfp[half][0]; bl = g_wfp[half][1];
    }
    __nv_bfloat16 h = __float2bfloat16(v);
    __nv_bfloat16 l = __float2bfloat16(v - __bfloat162float(h));
    *(__nv_bfloat16*)(bh + row * PKB + col * 2) = h;
    *(__nv_bfloat16*)(bl + row * PKB + col * 2) = l;
}

__global__ void count_deg_kernel(const int* __restrict__ snd, const int* __restrict__ rcv,
                                 int* sdeg, int* rdeg, int E) {
    int t = blockIdx.x * blockDim.x + threadIdx.x;
    if (t < E) {
        atomicAdd(&sdeg[snd[t]], 1);
        atomicAdd(&rdeg[rcv[t]], 1);
    }
}
__global__ __launch_bounds__(1024) void scan_kernel(
    const int* __restrict__ deg, int* __restrict__ offs, int* __restrict__ cursor, int n)
{
    __shared__ int warpsum[32];
    __shared__ int carry_sh;
    const int tid = threadIdx.x, lane = tid & 31, warp = tid >> 5;
    int carry = 0;
    for (int base = 0; base < n; base += 4096) {
        int idx = base + tid * 4;
        int4 v = make_int4(0, 0, 0, 0);
        if (idx + 3 < n) v = *(const int4*)(deg + idx);
        else {
            if (idx     < n) v.x = deg[idx];
            if (idx + 1 < n) v.y = deg[idx + 1];
            if (idx + 2 < n) v.z = deg[idx + 2];
        }
        int s0 = v.x, s1 = s0 + v.y, s2 = s1 + v.z, s3 = s2 + v.w;
        int inc = s3;
        #pragma unroll
        for (int o = 1; o < 32; o <<= 1) {
            int t = __shfl_up_sync(0xffffffffu, inc, o);
            if (lane >= o) inc += t;
        }
        if (lane == 31) warpsum[warp] = inc;
        __syncthreads();
        if (warp == 0) {
            int w = warpsum[lane];
            int wi = w;
            #pragma unroll
            for (int o = 1; o < 32; o <<= 1) {
                int t = __shfl_up_sync(0xffffffffu, wi, o);
                if (lane >= o) wi += t;
            }
            warpsum[lane] = wi - w;
        }
        __syncthreads();
        int texcl = carry + warpsum[warp] + inc - s3;
        int4 o4 = make_int4(texcl, texcl + s0, texcl + s1, texcl + s2);
        if (idx + 3 < n) {
            *(int4*)(offs + idx)   = o4;
            *(int4*)(cursor + idx) = o4;
        } else {
            if (idx     < n) { offs[idx]     = o4.x; cursor[idx]     = o4.x; }
            if (idx + 1 < n) { offs[idx + 1] = o4.y; cursor[idx + 1] = o4.y; }
            if (idx + 2 < n) { offs[idx + 2] = o4.z; cursor[idx + 2] = o4.z; }
        }
        if (tid == 1023) carry_sh = texcl + s3;
        __syncthreads();
        carry = carry_sh;
    }
    if (tid == 0) offs[n] = carry;
}
__global__ void fill_kernel(const int* __restrict__ snd, const int* __restrict__ rcv,
                            int* cursor, int* __restrict__ csr, int E)
{
    int t = blockIdx.x * blockDim.x + threadIdx.x;
    if (t < E) {
        int r = rcv[t];
        int p = atomicAdd(&cursor[r], 1);
        csr[p] = snd[t];
    }
}

// ---------------- staging: coalesced rows (NW warps stage NW*16 rows) ---------------
template <int NW>
__device__ __forceinline__ void stage_rows_mma(
    const float4* __restrict__ X4, uint8_t* a_hi, uint8_t* a_lo,
    int row0, int n, int wid, int lane)
{
    #pragma unroll 4
    for (int rr = 0; rr < 16; ++rr) {
        int r = wid * 16 + rr;
        int i = row0 + r;
        float4 v = make_float4(0.f, 0.f, 0.f, 0.f);
        if (i < n) v = X4[(size_t)i * 32 + lane];
        __nv_bfloat162 h01 = __floats2bfloat162_rn(v.x, v.y);
        __nv_bfloat162 h23 = __floats2bfloat162_rn(v.z, v.w);
        float2 f01 = __bfloat1622float2(h01);
        float2 f23 = __bfloat1622float2(h23);
        __nv_bfloat162 l01 = __floats2bfloat162_rn(v.x - f01.x, v.y - f01.y);
        __nv_bfloat162 l23 = __floats2bfloat162_rn(v.z - f23.x, v.w - f23.y);
        uint32_t off = (uint32_t)r * PKB + lane * 8;
        *(uint2*)(a_hi + off) = make_uint2(bf2u(h01), bf2u(h23));
        *(uint2*)(a_lo + off) = make_uint2(bf2u(l01), bf2u(l23));
    }
}

// 8-rows-per-warp variant (512 threads staging only 128 rows).
__device__ __forceinline__ void stage_rows_half(
    const float4* __restrict__ X4, uint8_t* a_hi, uint8_t* a_lo,
    int row0, int n, int wid, int lane)
{
    #pragma unroll 4
    for (int rr = 0; rr < 8; ++rr) {
        int r = wid * 8 + rr;
        int i = row0 + r;
        float4 v = make_float4(0.f, 0.f, 0.f, 0.f);
        if (i < n) v = X4[(size_t)i * 32 + lane];
        __nv_bfloat162 h01 = __floats2bfloat162_rn(v.x, v.y);
        __nv_bfloat162 h23 = __floats2bfloat162_rn(v.z, v.w);
        float2 f01 = __bfloat1622float2(h01);
        float2 f23 = __bfloat1622float2(h23);
        __nv_bfloat162 l01 = __floats2bfloat162_rn(v.x - f01.x, v.y - f01.y);
        __nv_bfloat162 l23 = __floats2bfloat162_rn(v.z - f23.x, v.w - f23.y);
        uint32_t off = (uint32_t)r * PKB + lane * 8;
        *(uint2*)(a_hi + off) = make_uint2(bf2u(h01), bf2u(h23));
        *(uint2*)(a_lo + off) = make_uint2(bf2u(l01), bf2u(l23));
    }
}

// ---------------- staging: CSR gather, 8 threads/row, INTERLEAVED loads -------------
// Thread cseg loads float4 indices {cseg, cseg+8, cseg+16, cseg+24}: for a fixed
// load slot q, the 8 threads of a row cover exactly ONE 128B line (vs 4 with the
// blocked mapping) -> 4x fewer L1tex wavefronts per warp-level LDG.
// Warp covers 4 rows (lane>>3); dual-buffer edge pipeline for MLP.
template <int NW, int ROWS>
__device__ __forceinline__ void stage_gather_mma(
    const float4* __restrict__ H4, const int* __restrict__ offs,
    const int* __restrict__ csr, uint8_t* a_hi, uint8_t* a_lo,
    int row0, int n, int wid, int lane)
{
    const int cseg = lane & 7;
    #pragma unroll
    for (int pass = 0; pass < ROWS / (NW * 4); ++pass) {
        int r = pass * (NW * 4) + wid * 4 + (lane >> 3);
        int i = row0 + r;
        float acc[16];
        #pragma unroll
        for (int q = 0; q < 16; ++q) acc[q] = 0.f;
        float scl = 1.f;
        if (i < n) {
            int beg = __ldg(&offs[i]), end = __ldg(&offs[i + 1]);
            if (beg < end) {
                const float4* p = H4 + (size_t)__ldg(&csr[beg]) * 32 + cseg;
                float4 c0 = __ldg(p), c1 = __ldg(p + 8), c2 = __ldg(p + 16), c3 = __ldg(p + 24);
                for (int e = beg + 1; e < end; ++e) {
                    const float4* np = H4 + (size_t)__ldg(&csr[e]) * 32 + cseg;
                    float4 n0 = __ldg(np), n1 = __ldg(np + 8),
                           n2 = __ldg(np + 16), n3 = __ldg(np + 24);
                    acc[0]  += c0.x; acc[1]  += c0.y; acc[2]  += c0.z; acc[3]  += c0.w;
                    acc[4]  += c1.x; acc[5]  += c1.y; acc[6]  += c1.z; acc[7]  += c1.w;
                    acc[8]  += c2.x; acc[9]  += c2.y; acc[10] += c2.z; acc[11] += c2.w;
                    acc[12] += c3.x; acc[13] += c3.y; acc[14] += c3.z; acc[15] += c3.w;
                    c0 = n0; c1 = n1; c2 = n2; c3 = n3;
                }
                acc[0]  += c0.x; acc[1]  += c0.y; acc[2]  += c0.z; acc[3]  += c0.w;
                acc[4]  += c1.x; acc[5]  += c1.y; acc[6]  += c1.z; acc[7]  += c1.w;
                acc[8]  += c2.x; acc[9]  += c2.y; acc[10] += c2.z; acc[11] += c2.w;
                acc[12] += c3.x; acc[13] += c3.y; acc[14] += c3.z; acc[15] += c3.w;
            }
            scl = rsqrtf(fmaxf((float)(end - beg), 1.f));
        }
        #pragma unroll
        for (int q = 0; q < 16; ++q) acc[q] *= scl;

        // acc[4q..4q+3] = float4 index (cseg + 8q) -> bf16 bytes at (cseg+8q)*8
        #pragma unroll
        for (int qq = 0; qq < 4; ++qq) {
            float x0 = acc[4 * qq], x1 = acc[4 * qq + 1];
            float x2 = acc[4 * qq + 2], x3 = acc[4 * qq + 3];
            __nv_bfloat162 h01 = __floats2bfloat162_rn(x0, x1);
            __nv_bfloat162 h23 = __floats2bfloat162_rn(x2, x3);
            float2 f01 = __bfloat1622float2(h01);
            float2 f23 = __bfloat1622float2(h23);
            __nv_bfloat162 l01 = __floats2bfloat162_rn(x0 - f01.x, x1 - f01.y);
            __nv_bfloat162 l23 = __floats2bfloat162_rn(x2 - f23.x, x3 - f23.y);
            uint32_t off = (uint32_t)r * PKB + (cseg + 8 * qq) * 8;
            *(uint2*)(a_hi + off) = make_uint2(bf2u(h01), bf2u(h23));
            *(uint2*)(a_lo + off) = make_uint2(bf2u(l01), bf2u(l23));
        }
    }
}

// ---------------- 3-term bf16 MMA, one K=128 block, m32 x (NF16*16) per warp ---------
template <int NF16>
__device__ __forceinline__ void mma_block_t(
    float acc[2][NF16 * 2][4], uint32_t aH, uint32_t aL, uint32_t bH, uint32_t bL)
{
    #pragma unroll
    for (int k16 = 0; k16 < 8; ++k16) {
        const uint32_t kb = k16 * 32;
        uint32_t ah0[4], ah1[4], al0[4], al1[4];
        ldsm4(ah0, aH + kb);
        ldsm4(ah1, aH + 16 * PKB + kb);
        ldsm4(al0, aL + kb);
        ldsm4(al1, aL + 16 * PKB + kb);
        #pragma unroll
        for (int nf16 = 0; nf16 < NF16; ++nf16) {
            uint32_t bh[4], bl[4];
            ldsm4(bh, bH + nf16 * 16 * PKB + kb);
            ldsm4(bl, bL + nf16 * 16 * PKB + kb);
            const int nf = nf16 * 2;
            mma_bf16(acc[0][nf],     ah0, bh[0], bh[1]);
            mma_bf16(acc[0][nf],     ah0, bl[0], bl[1]);
            mma_bf16(acc[0][nf],     al0, bh[0], bh[1]);
            mma_bf16(acc[0][nf + 1], ah0, bh[2], bh[3]);
            mma_bf16(acc[0][nf + 1], ah0, bl[2], bl[3]);
            mma_bf16(acc[0][nf + 1], al0, bh[2], bh[3]);
            mma_bf16(acc[1][nf],     ah1, bh[0], bh[1]);
            mma_bf16(acc[1][nf],     ah1, bl[0], bl[1]);
            mma_bf16(acc[1][nf],     al1, bh[0], bh[1]);
            mma_bf16(acc[1][nf + 1], ah1, bh[2], bh[3]);
            mma_bf16(acc[1][nf + 1], ah1, bl[2], bl[3]);
            mma_bf16(acc[1][nf + 1], al1, bh[2], bh[3]);
        }
    }
}

// ---------------- dense GC layer: 512 threads, 256-row tiles ------------------------
#define MMA_SMEM 213504
__global__ __launch_bounds__(512, 1) void mma_dense_kernel(
    const float4* __restrict__ X4, const float4* __restrict__ Hin,
    const int* __restrict__ offs, const int* __restrict__ csr,
    const uint8_t* __restrict__ whi, const uint8_t* __restrict__ wlo,
    const float* __restrict__ bias, const int* __restrict__ sdeg,
    float* __restrict__ Hout, int n, int tiles)
{
    extern __shared__ uint8_t sm[];
    uint8_t* a_hi = sm;
    uint8_t* a_lo = sm + 69632;
    float* bias_sm = (float*)(sm + 208896);
    float* red1    = (float*)(sm + 209408);
    float* red2    = (float*)(sm + 211456);

    const int tid = threadIdx.x, wid = tid >> 5, lane = tid & 31;
    const int sub  = wid >> 3;
    const int mrow = (wid & 3) * 32 + sub * 128;
    const int ch   = (wid >> 2) & 1;
    const int ncol = ch * 64;
    const int q2   = (lane & 3) * 2;

    for (int idx = tid; idx < 2176; idx += 512) {
        ((uint4*)(sm + 139264))[idx] = ((const uint4*)whi)[idx];
        ((uint4*)(sm + 174080))[idx] = ((const uint4*)wlo)[idx];
    }
    if (tid < 128) bias_sm[tid] = bias[tid];
    __syncthreads();

    float brg[16];
    #pragma unroll
    for (int nf = 0; nf < 8; ++nf) {
        brg[2 * nf]     = bias_sm[ncol + nf * 8 + q2];
        brg[2 * nf + 1] = bias_sm[ncol + nf * 8 + q2 + 1];
    }
    int rl[4];
    #pragma unroll
    for (int ri = 0; ri < 4; ++ri)
        rl[ri] = mrow + (ri >> 1) * 16 + (ri & 1) * 8 + (lane >> 2);

    const uint32_t smb  = smem_u32(sm);
    const uint32_t aoff = (lane & 15) * PKB + (lane >> 4) * 16;
    const uint32_t boff = ((lane >> 4) * 8 + (lane & 7)) * PKB + ((lane >> 3) & 1) * 16;
    const uint32_t aH = smb + mrow * PKB + aoff;
    const uint32_t aL = smb + 69632 + mrow * PKB + aoff;
    const uint32_t bH = smb + 139264 + ncol * PKB + boff;
    const uint32_t bL = smb + 174080 + ncol * PKB + boff;

    for (int t = blockIdx.x; t < tiles; t += gridDim.x) {
        const int row0 = t * 256;
        __syncthreads();
        if (csr) stage_gather_mma<16, 256>(Hin, offs, csr, a_hi, a_lo, row0, n, wid, lane);
        else     stage_rows_mma<16>(X4, a_hi, a_lo, row0, n, wid, lane);
        __syncthreads();

        float acc[2][8][4];
        #pragma unroll
        for (int a = 0; a < 2; ++a)
            #pragma unroll
            for (int b = 0; b < 8; ++b)
                #pragma unroll
                for (int c = 0; c < 4; ++c) acc[a][b][c] = 0.f;

        mma_block_t<4>(acc, aH, aL, bH, bL);

        float rmax[4];
        #pragma unroll
        for (int ri = 0; ri < 4; ++ri) {
            const int mt = ri >> 1, h8 = (ri & 1) * 2;
            float m = -3.4e38f;
            #pragma unroll
            for (int nf = 0; nf < 8; ++nf) {
                float x0 = fmaxf(acc[mt][nf][h8]     + brg[2 * nf],     0.f);
                float x1 = fmaxf(acc[mt][nf][h8 + 1] + brg[2 * nf + 1], 0.f);
                acc[mt][nf][h8] = x0; acc[mt][nf][h8 + 1] = x1;
                m = fmaxf(m, fmaxf(x0, x1));
            }
            m = fmaxf(m, __shfl_xor_sync(0xffffffffu, m, 1));
            m = fmaxf(m, __shfl_xor_sync(0xffffffffu, m, 2));
            rmax[ri] = m;
            red1[ch * 256 + rl[ri]] = m;
        }
        __syncthreads();
        #pragma unroll
        for (int ri = 0; ri < 4; ++ri) {
            const int mt = ri >> 1, h8 = (ri & 1) * 2;
            float m = fmaxf(rmax[ri], red1[(ch ^ 1) * 256 + rl[ri]]);
            float s = 0.f;
            #pragma unroll
            for (int nf = 0; nf < 8; ++nf) {
                float v0 = __expf(acc[mt][nf][h8] - m);
                float v1 = __expf(acc[mt][nf][h8 + 1] - m);
                acc[mt][nf][h8] = v0; acc[mt][nf][h8 + 1] = v1;
                s += v0 + v1;
            }
            s += __shfl_xor_sync(0xffffffffu, s, 1);
            s += __shfl_xor_sync(0xffffffffu, s, 2);
            red2[ch * 256 + rl[ri]] = s;
        }
        __syncthreads();
        #pragma unroll
        for (int ri = 0; ri < 4; ++ri) {
            const int mt = ri >> 1, h8 = (ri & 1) * 2;
            const int i = row0 + rl[ri];
            if (i >= n) continue;
            float s = red2[rl[ri]] + red2[256 + rl[ri]];
            float scl = rsqrtf(fmaxf((float)__ldg(&sdeg[i]), 1.f)) / s;
            float* op = Hout + (size_t)i * HID + ncol;
            #pragma unroll
            for (int nf = 0; nf < 8; ++nf)
                *(float2*)(op + nf * 8 + q2) =
                    make_float2(acc[mt][nf][h8] * scl, acc[mt][nf][h8 + 1] * scl);
        }
    }
}

// ---------------- final: 512 threads, m32xn32 warps, K=256 two-pass ------------------
#define FINAL_SMEM 209408
__global__ __launch_bounds__(512, 1) void mma_final_kernel(
    const float4* __restrict__ Hin, const int* __restrict__ offs,
    const int* __restrict__ csr, const float4* __restrict__ nodes4,
    const uint8_t* __restrict__ w0hi, const uint8_t* __restrict__ w0lo,
    const uint8_t* __restrict__ w1hi, const uint8_t* __restrict__ w1lo,
    const float* __restrict__ bmu, const float* __restrict__ bls,
    float* __restrict__ out, int n, int tiles)
{
    extern __shared__ uint8_t sm[];
    uint8_t* a_hi = sm;
    uint8_t* a_lo = sm + 34816;
    float* bias_sm = (float*)(sm + 208896);

    const int tid = threadIdx.x, wid = tid >> 5, lane = tid & 31;
    const int mrow = (wid & 3) * 32;
    const int nsub = (wid >> 2) & 1;
    const int ch   = wid >> 3;
    const int ncol = ch * 64 + nsub * 32;
    const int q2   = (lane & 3) * 2;

    for (int idx = tid; idx < 2176; idx += 512) {
        ((uint4*)(sm + 69632))[idx]  = ((const uint4*)w0hi)[idx];
        ((uint4*)(sm + 104448))[idx] = ((const uint4*)w0lo)[idx];
        ((uint4*)(sm + 139264))[idx] = ((const uint4*)w1hi)[idx];
        ((uint4*)(sm + 174080))[idx] = ((const uint4*)w1lo)[idx];
    }
    if (tid < 64) bias_sm[tid] = bmu[tid];
    else if (tid < 128) bias_sm[tid] = bls[tid - 64];
    __syncthreads();

    float brg[8];
    #pragma unroll
    for (int nf = 0; nf < 4; ++nf) {
        brg[2 * nf]     = bias_sm[ncol + nf * 8 + q2];
        brg[2 * nf + 1] = bias_sm[ncol + nf * 8 + q2 + 1];
    }
    int rl[4];
    #pragma unroll
    for (int ri = 0; ri < 4; ++ri)
        rl[ri] = mrow + (ri >> 1) * 16 + (ri & 1) * 8 + (lane >> 2);

    const uint32_t smb  = smem_u32(sm);
    const uint32_t aoff = (lane & 15) * PKB + (lane >> 4) * 16;
    const uint32_t boff = ((lane >> 4) * 8 + (lane & 7)) * PKB + ((lane >> 3) & 1) * 16;
    const uint32_t aH  = smb + mrow * PKB + aoff;
    const uint32_t aL  = smb + 34816 + mrow * PKB + aoff;
    const uint32_t b0H = smb + 69632 + ncol * PKB + boff;
    const uint32_t b0L = smb + 104448 + ncol * PKB + boff;
    const uint32_t b1H = smb + 139264 + ncol * PKB + boff;
    const uint32_t b1L = smb + 174080 + ncol * PKB + boff;

    const int cc0 = nsub * 32;

    for (int t = blockIdx.x; t < tiles; t += gridDim.x) {
        const int row0 = t * 128;

        float acc[2][4][4];
        #pragma unroll
        for (int a = 0; a < 2; ++a)
            #pragma unroll
            for (int b = 0; b < 4; ++b)
                #pragma unroll
                for (int c = 0; c < 4; ++c) acc[a][b][c] = 0.f;

        __syncthreads();
        stage_gather_mma<16, 128>(Hin, offs, csr, a_hi, a_lo, row0, n, wid, lane);
        __syncthreads();
        mma_block_t<2>(acc, aH, aL, b0H, b0L);

        __syncthreads();
        stage_rows_half(nodes4, a_hi, a_lo, row0, n, wid, lane);
        __syncthreads();
        mma_block_t<2>(acc, aH, aL, b1H, b1L);

        #pragma unroll
        for (int ri = 0; ri < 4; ++ri) {
            const int mt = ri >> 1, h8 = (ri & 1) * 2;
            const int i = row0 + rl[ri];
            if (i >= n) continue;
            float* op = out + (ch ? (size_t)n * ZDIM : 0) + (size_t)i * ZDIM + cc0;
            #pragma unroll
            for (int nf = 0; nf < 4; ++nf)
                *(float2*)(op + nf * 8 + q2) =
                    make_float2(acc[mt][nf][h8]     + brg[2 * nf],
                                acc[mt][nf][h8 + 1] + brg[2 * nf + 1]);
        }
    }
}

// ---------------- launch -------------------------------------------------------------
extern "C" void kernel_launch(void* const* d_in, const int* in_sizes, int n_in,
                              void* d_out, int out_size)
{
    const float* nodes = (const float*)d_in[0];
    const int*   snd   = (const int*)d_in[1];
    const int*   rcv   = (const int*)d_in[2];
    const float* W0    = (const float*)d_in[3];
    const float* b0    = (const float*)d_in[4];
    const float* W1    = (const float*)d_in[5];
    const float* b1    = (const float*)d_in[6];
    const float* Wmu   = (const float*)d_in[7];
    const float* bmu   = (const float*)d_in[8];
    const float* Wls   = (const float*)d_in[9];
    const float* bls   = (const float*)d_in[10];
    float* out = (float*)d_out;

    const int n = in_sizes[0] / FIN;
    const int E = in_sizes[1];

    float *h, *h2;
    int *sdeg, *rdeg, *offs, *cursor, *csr;
    uint8_t *w0p, *w1p, *wfp;
    cudaGetSymbolAddress((void**)&h,      g_h);
    cudaGetSymbolAddress((void**)&h2,     g_h2);
    cudaGetSymbolAddress((void**)&sdeg,   g_sdeg);
    cudaGetSymbolAddress((void**)&rdeg,   g_rdeg);
    cudaGetSymbolAddress((void**)&offs,   g_offs);
    cudaGetSymbolAddress((void**)&cursor, g_cursor);
    cudaGetSymbolAddress((void**)&csr,    g_csr);
    cudaGetSymbolAddress((void**)&w0p,    g_w0p);
    cudaGetSymbolAddress((void**)&w1p,    g_w1p);
    cudaGetSymbolAddress((void**)&wfp,    g_wfp);

    cudaFuncSetAttribute(mma_dense_kernel, cudaFuncAttributeMaxDynamicSharedMemorySize, MMA_SMEM);
    cudaFuncSetAttribute(mma_final_kernel, cudaFuncAttributeMaxDynamicSharedMemorySize, FINAL_SMEM);

    const int tiles256 = (n + 255) / 256;
    const int tiles128 = (n + 127) / 128;
    const int IMG = 128 * PKB;
    const int pzBlocks = ((n > 65536 ? n : 65536) + 255) / 256;

    // 0: fused prep + degree-zero
    prep_zero_kernel<<<pzBlocks, 256>>>(W0, W1, Wmu, Wls, sdeg, rdeg, n);
    // 1: degree count
    count_deg_kernel<<<(E + 255) / 256, 256>>>(snd, rcv, sdeg, rdeg, E);

    // 2: layer-1 dense (coalesced staging)
    mma_dense_kernel<<<148, 512, MMA_SMEM>>>(
        (const float4*)nodes, nullptr, nullptr, nullptr,
        w0p, w0p + IMG, b0, sdeg, h, n, tiles256);

    // 3-4: CSR build
    scan_kernel<<<1, 1024>>>(rdeg, offs, cursor, n);
    fill_kernel<<<(E + 255) / 256, 256>>>(snd, rcv, cursor, csr, E);

    // 5: layer-2 dense (fused interleaved gather) — reads h, writes h2
    mma_dense_kernel<<<148, 512, MMA_SMEM>>>(
        nullptr, (const float4*)h, offs, csr,
        w1p, w1p + IMG, b1, sdeg, h2, n, tiles256);

    // 6: final heads (fused gather + concat)
    mma_final_kernel<<<148, 512, FINAL_SMEM>>>(
        (const float4*)h2, offs, csr, (const float4*)nodes,
        wfp, wfp + IMG, wfp + 2 * IMG, wfp + 3 * IMG,
        bmu, bls, out, n, tiles128);
}

// round 11
// speedup vs baseline: 4.6240x; 1.1165x over previous
#include <cuda_runtime.h>
#include <cuda_bf16.h>
#include <cstdint>

#define NMAX   100000
#define EMAX   600000
#define HID    128
#define FIN    128
#define ZDIM   64
#define PKB    272    // padded bf16 row pitch (136 bf16)

// ---------------- static device scratch --------------------------------------
__device__ float g_h [(size_t)NMAX * HID];
__device__ float g_h2[(size_t)NMAX * HID];
__device__ int   g_sdeg[NMAX];
__device__ int   g_rdeg[NMAX];
__device__ int   g_offs[NMAX + 1];
__device__ int   g_cursor[NMAX];
__device__ int   g_csr[EMAX];
__device__ int   g_bsum[128];                              // scan block sums
__device__ __align__(16) uint8_t g_w0p[2][128 * PKB];      // [hi/lo]
__device__ __align__(16) uint8_t g_w1p[2][128 * PKB];      // [hi/lo]
__device__ __align__(16) uint8_t g_wfp[2][2][128 * PKB];   // [k-half][hi/lo]

// ---------------- PTX helpers --------------------------------------------------
__device__ __forceinline__ uint32_t smem_u32(const void* p) {
    uint32_t a;
    asm("{ .reg .u64 t; cvta.to.shared.u64 t, %1; cvt.u32.u64 %0, t; }" : "=r"(a) : "l"(p));
    return a;
}
__device__ __forceinline__ void ldsm4(uint32_t* r, uint32_t addr) {
    asm volatile("ldmatrix.sync.aligned.m8n8.x4.shared.b16 {%0,%1,%2,%3}, [%4];"
                 : "=r"(r[0]), "=r"(r[1]), "=r"(r[2]), "=r"(r[3]) : "r"(addr) : "memory");
}
__device__ __forceinline__ void mma_bf16(float* c, const uint32_t* a,
                                         uint32_t b0, uint32_t b1) {
    asm volatile(
        "mma.sync.aligned.m16n8k16.row.col.f32.bf16.bf16.f32 "
        "{%0,%1,%2,%3}, {%4,%5,%6,%7}, {%8,%9}, {%0,%1,%2,%3};"
        : "+f"(c[0]), "+f"(c[1]), "+f"(c[2]), "+f"(c[3])
        : "r"(a[0]), "r"(a[1]), "r"(a[2]), "r"(a[3]), "r"(b0), "r"(b1));
}
__device__ __forceinline__ uint32_t bf2u(__nv_bfloat162 v) {
    return *reinterpret_cast<uint32_t*>(&v);
}

// ---------------- fused prep + degree-zero ---------------------------------------
__global__ void prep_zero_kernel(const float* __restrict__ W0, const float* __restrict__ W1,
                                 const float* __restrict__ Wmu, const float* __restrict__ Wls,
                                 int* sdeg, int* rdeg, int n)
{
    int idx = blockIdx.x * blockDim.x + threadIdx.x;
    if (idx < n) { sdeg[idx] = 0; rdeg[idx] = 0; }
    if (idx >= 65536) return;
    float v; uint8_t *bh, *bl; int row, col;
    if (idx < 16384) {
        int k = idx >> 7, nn = idx & 127;
        v = W0[idx]; row = nn; col = k; bh = g_w0p[0]; bl = g_w0p[1];
    } else if (idx < 32768) {
        int r = idx - 16384;
        int k = r >> 7, nn = r & 127;
        v = W1[r]; row = nn; col = k; bh = g_w1p[0]; bl = g_w1p[1];
    } else {
        int r = idx - 32768;
        int half = r >> 14, r2 = r & 16383;
        int kl = r2 >> 7, nn = r2 & 127;
        int kg = half * 128 + kl;
        v = (nn < 64) ? Wmu[kg * 64 + nn] : Wls[kg * 64 + (nn - 64)];
        row = nn; col = kl; bh = g_wfp[half][0]; bl = g_wfp[half][1];
    }
    __nv_bfloat16 h = __float2bfloat16(v);
    __nv_bfloat16 l = __float2bfloat16(v - __bfloat162float(h));
    *(__nv_bfloat16*)(bh + row * PKB + col * 2) = h;
    *(__nv_bfloat16*)(bl + row * PKB + col * 2) = l;
}

__global__ void count_deg_kernel(const int* __restrict__ snd, const int* __restrict__ rcv,
                                 int* sdeg, int* rdeg, int E) {
    int t = blockIdx.x * blockDim.x + threadIdx.x;
    if (t < E) {
        atomicAdd(&sdeg[snd[t]], 1);
        atomicAdd(&rdeg[rcv[t]], 1);
    }
}

// ---------------- multi-block scan (3 phases, 2048 elems/block) -------------------
__global__ __launch_bounds__(256) void scan_reduce_kernel(
    const int* __restrict__ deg, int* __restrict__ bsum, int n)
{
    __shared__ int wsum[8];
    const int tid = threadIdx.x, lane = tid & 31, warp = tid >> 5;
    int base = blockIdx.x * 2048 + tid * 8;
    int s = 0;
    if (base + 7 < n) {
        int4 a = *(const int4*)(deg + base);
        int4 b = *(const int4*)(deg + base + 4);
        s = a.x + a.y + a.z + a.w + b.x + b.y + b.z + b.w;
    } else {
        for (int q = 0; q < 8; ++q) if (base + q < n) s += deg[base + q];
    }
    #pragma unroll
    for (int o = 16; o; o >>= 1) s += __shfl_xor_sync(0xffffffffu, s, o);
    if (lane == 0) wsum[warp] = s;
    __syncthreads();
    if (tid == 0) {
        int t = 0;
        #pragma unroll
        for (int w = 0; w < 8; ++w) t += wsum[w];
        bsum[blockIdx.x] = t;
    }
}

// single warp: exclusive-scan block sums in place, write offs[n] = total
__global__ void scan_bsums_kernel(int* bsum, int nb, int* offs, int n)
{
    int lane = threadIdx.x;
    int v = (lane < nb) ? bsum[lane] : 0;
    int inc = v;
    #pragma unroll
    for (int o = 1; o < 32; o <<= 1) {
        int t = __shfl_up_sync(0xffffffffu, inc, o);
        if (lane >= o) inc += t;
    }
    // support nb up to 128 via sequential warp chunks
    __shared__ int carry;
    if (threadIdx.x == 0) carry = 0;
    __syncwarp();
    int total = 0;
    for (int cbase = 0; cbase < nb; cbase += 32) {
        int idx = cbase + lane;
        int vv = (idx < nb) ? bsum[idx] : 0;
        int ii = vv;
        #pragma unroll
        for (int o = 1; o < 32; o <<= 1) {
            int t = __shfl_up_sync(0xffffffffu, ii, o);
            if (lane >= o) ii += t;
        }
        int c = carry;
        if (idx < nb) bsum[idx] = c + ii - vv;   // exclusive
        int chunk_total = __shfl_sync(0xffffffffu, ii, 31);
        if (lane == 0) carry = c + chunk_total;
        __syncwarp();
        total = carry;
    }
    if (lane == 0) offs[n] = total;
    (void)inc; (void)v;
}

__global__ __launch_bounds__(256) void scan_apply_kernel(
    const int* __restrict__ deg, const int* __restrict__ bexcl,
    int* __restrict__ offs, int* __restrict__ cursor, int n)
{
    __shared__ int wsum[8];
    const int tid = threadIdx.x, lane = tid & 31, warp = tid >> 5;
    int base = blockIdx.x * 2048 + tid * 8;
    int v[8];
    if (base + 7 < n) {
        int4 a = *(const int4*)(deg + base);
        int4 b = *(const int4*)(deg + base + 4);
        v[0] = a.x; v[1] = a.y; v[2] = a.z; v[3] = a.w;
        v[4] = b.x; v[5] = b.y; v[6] = b.z; v[7] = b.w;
    } else {
        #pragma unroll
        for (int q = 0; q < 8; ++q) v[q] = (base + q < n) ? deg[base + q] : 0;
    }
    int s[8]; int run = 0;
    #pragma unroll
    for (int q = 0; q < 8; ++q) { s[q] = run; run += v[q]; }
    int inc = run;
    #pragma unroll
    for (int o = 1; o < 32; o <<= 1) {
        int t = __shfl_up_sync(0xffffffffu, inc, o);
        if (lane >= o) inc += t;
    }
    if (lane == 31) wsum[warp] = inc;
    __syncthreads();
    if (warp == 0 && lane < 8) {
        int w = wsum[lane];
        int wi = w;
        #pragma unroll
        for (int o = 1; o < 8; o <<= 1) {
            int t = __shfl_up_sync(0xffu, wi, o);
            if (lane >= o) wi += t;
        }
        wsum[lane] = wi - w;
    }
    __syncthreads();
    int off = bexcl[blockIdx.x] + wsum[warp] + inc - run;
    if (base + 7 < n) {
        int4 o1 = make_int4(off + s[0], off + s[1], off + s[2], off + s[3]);
        int4 o2 = make_int4(off + s[4], off + s[5], off + s[6], off + s[7]);
        *(int4*)(offs + base) = o1;   *(int4*)(offs + base + 4) = o2;
        *(int4*)(cursor + base) = o1; *(int4*)(cursor + base + 4) = o2;
    } else {
        #pragma unroll
        for (int q = 0; q < 8; ++q)
            if (base + q < n) { offs[base + q] = off + s[q]; cursor[base + q] = off + s[q]; }
    }
}

__global__ void fill_kernel(const int* __restrict__ snd, const int* __restrict__ rcv,
                            int* cursor, int* __restrict__ csr, int E)
{
    int t = blockIdx.x * blockDim.x + threadIdx.x;
    if (t < E) {
        int r = rcv[t];
        int p = atomicAdd(&cursor[r], 1);
        csr[p] = snd[t];
    }
}

// ---------------- staging: coalesced rows (NW warps stage NW*16 rows) ---------------
template <int NW>
__device__ __forceinline__ void stage_rows_mma(
    const float4* __restrict__ X4, uint8_t* a_hi, uint8_t* a_lo,
    int row0, int n, int wid, int lane)
{
    #pragma unroll 4
    for (int rr = 0; rr < 16; ++rr) {
        int r = wid * 16 + rr;
        int i = row0 + r;
        float4 v = make_float4(0.f, 0.f, 0.f, 0.f);
        if (i < n) v = X4[(size_t)i * 32 + lane];
        __nv_bfloat162 h01 = __floats2bfloat162_rn(v.x, v.y);
        __nv_bfloat162 h23 = __floats2bfloat162_rn(v.z, v.w);
        float2 f01 = __bfloat1622float2(h01);
        float2 f23 = __bfloat1622float2(h23);
        __nv_bfloat162 l01 = __floats2bfloat162_rn(v.x - f01.x, v.y - f01.y);
        __nv_bfloat162 l23 = __floats2bfloat162_rn(v.z - f23.x, v.w - f23.y);
        uint32_t off = (uint32_t)r * PKB + lane * 8;
        *(uint2*)(a_hi + off) = make_uint2(bf2u(h01), bf2u(h23));
        *(uint2*)(a_lo + off) = make_uint2(bf2u(l01), bf2u(l23));
    }
}

// 8-rows-per-warp variant (512 threads staging only 128 rows).
__device__ __forceinline__ void stage_rows_half(
    const float4* __restrict__ X4, uint8_t* a_hi, uint8_t* a_lo,
    int row0, int n, int wid, int lane)
{
    #pragma unroll 4
    for (int rr = 0; rr < 8; ++rr) {
        int r = wid * 8 + rr;
        int i = row0 + r;
        float4 v = make_float4(0.f, 0.f, 0.f, 0.f);
        if (i < n) v = X4[(size_t)i * 32 + lane];
        __nv_bfloat162 h01 = __floats2bfloat162_rn(v.x, v.y);
        __nv_bfloat162 h23 = __floats2bfloat162_rn(v.z, v.w);
        float2 f01 = __bfloat1622float2(h01);
        float2 f23 = __bfloat1622float2(h23);
        __nv_bfloat162 l01 = __floats2bfloat162_rn(v.x - f01.x, v.y - f01.y);
        __nv_bfloat162 l23 = __floats2bfloat162_rn(v.z - f23.x, v.w - f23.y);
        uint32_t off = (uint32_t)r * PKB + lane * 8;
        *(uint2*)(a_hi + off) = make_uint2(bf2u(h01), bf2u(h23));
        *(uint2*)(a_lo + off) = make_uint2(bf2u(l01), bf2u(l23));
    }
}

// ---------------- staging: CSR gather, 8 threads/row, interleaved loads -------------
template <int NW, int ROWS>
__device__ __forceinline__ void stage_gather_mma(
    const float4* __restrict__ H4, const int* __restrict__ offs,
    const int* __restrict__ csr, uint8_t* a_hi, uint8_t* a_lo,
    int row0, int n, int wid, int lane)
{
    const int cseg = lane & 7;
    #pragma unroll
    for (int pass = 0; pass < ROWS / (NW * 4); ++pass) {
        int r = pass * (NW * 4) + wid * 4 + (lane >> 3);
        int i = row0 + r;
        float acc[16];
        #pragma unroll
        for (int q = 0; q < 16; ++q) acc[q] = 0.f;
        float scl = 1.f;
        if (i < n) {
            int beg = __ldg(&offs[i]), end = __ldg(&offs[i + 1]);
            if (beg < end) {
                const float4* p = H4 + (size_t)__ldg(&csr[beg]) * 32 + cseg;
                float4 c0 = __ldg(p), c1 = __ldg(p + 8), c2 = __ldg(p + 16), c3 = __ldg(p + 24);
                for (int e = beg + 1; e < end; ++e) {
                    const float4* np = H4 + (size_t)__ldg(&csr[e]) * 32 + cseg;
                    float4 n0 = __ldg(np), n1 = __ldg(np + 8),
                           n2 = __ldg(np + 16), n3 = __ldg(np + 24);
                    acc[0]  += c0.x; acc[1]  += c0.y; acc[2]  += c0.z; acc[3]  += c0.w;
                    acc[4]  += c1.x; acc[5]  += c1.y; acc[6]  += c1.z; acc[7]  += c1.w;
                    acc[8]  += c2.x; acc[9]  += c2.y; acc[10] += c2.z; acc[11] += c2.w;
                    acc[12] += c3.x; acc[13] += c3.y; acc[14] += c3.z; acc[15] += c3.w;
                    c0 = n0; c1 = n1; c2 = n2; c3 = n3;
                }
                acc[0]  += c0.x; acc[1]  += c0.y; acc[2]  += c0.z; acc[3]  += c0.w;
                acc[4]  += c1.x; acc[5]  += c1.y; acc[6]  += c1.z; acc[7]  += c1.w;
                acc[8]  += c2.x; acc[9]  += c2.y; acc[10] += c2.z; acc[11] += c2.w;
                acc[12] += c3.x; acc[13] += c3.y; acc[14] += c3.z; acc[15] += c3.w;
            }
            scl = rsqrtf(fmaxf((float)(end - beg), 1.f));
        }
        #pragma unroll
        for (int q = 0; q < 16; ++q) acc[q] *= scl;

        #pragma unroll
        for (int qq = 0; qq < 4; ++qq) {
            float x0 = acc[4 * qq], x1 = acc[4 * qq + 1];
            float x2 = acc[4 * qq + 2], x3 = acc[4 * qq + 3];
            __nv_bfloat162 h01 = __floats2bfloat162_rn(x0, x1);
            __nv_bfloat162 h23 = __floats2bfloat162_rn(x2, x3);
            float2 f01 = __bfloat1622float2(h01);
            float2 f23 = __bfloat1622float2(h23);
            __nv_bfloat162 l01 = __floats2bfloat162_rn(x0 - f01.x, x1 - f01.y);
            __nv_bfloat162 l23 = __floats2bfloat162_rn(x2 - f23.x, x3 - f23.y);
            uint32_t off = (uint32_t)r * PKB + (cseg + 8 * qq) * 8;
            *(uint2*)(a_hi + off) = make_uint2(bf2u(h01), bf2u(h23));
            *(uint2*)(a_lo + off) = make_uint2(bf2u(l01), bf2u(l23));
        }
    }
}

// ---------------- 3-term bf16 MMA, one K=128 block, m32 x (NF16*16) per warp ---------
template <int NF16>
__device__ __forceinline__ void mma_block_t(
    float acc[2][NF16 * 2][4], uint32_t aH, uint32_t aL, uint32_t bH, uint32_t bL)
{
    #pragma unroll
    for (int k16 = 0; k16 < 8; ++k16) {
        const uint32_t kb = k16 * 32;
        uint32_t ah0[4], ah1[4], al0[4], al1[4];
        ldsm4(ah0, aH + kb);
        ldsm4(ah1, aH + 16 * PKB + kb);
        ldsm4(al0, aL + kb);
        ldsm4(al1, aL + 16 * PKB + kb);
        #pragma unroll
        for (int nf16 = 0; nf16 < NF16; ++nf16) {
            uint32_t bh[4], bl[4];
            ldsm4(bh, bH + nf16 * 16 * PKB + kb);
            ldsm4(bl, bL + nf16 * 16 * PKB + kb);
            const int nf = nf16 * 2;
            mma_bf16(acc[0][nf],     ah0, bh[0], bh[1]);
            mma_bf16(acc[0][nf],     ah0, bl[0], bl[1]);
            mma_bf16(acc[0][nf],     al0, bh[0], bh[1]);
            mma_bf16(acc[0][nf + 1], ah0, bh[2], bh[3]);
            mma_bf16(acc[0][nf + 1], ah0, bl[2], bl[3]);
            mma_bf16(acc[0][nf + 1], al0, bh[2], bh[3]);
            mma_bf16(acc[1][nf],     ah1, bh[0], bh[1]);
            mma_bf16(acc[1][nf],     ah1, bl[0], bl[1]);
            mma_bf16(acc[1][nf],     al1, bh[0], bh[1]);
            mma_bf16(acc[1][nf + 1], ah1, bh[2], bh[3]);
            mma_bf16(acc[1][nf + 1], ah1, bl[2], bl[3]);
            mma_bf16(acc[1][nf + 1], al1, bh[2], bh[3]);
        }
    }
}

// ---------------- dense GC layer: 512 threads, 256-row tiles ------------------------
#define MMA_SMEM 213504
__global__ __launch_bounds__(512, 1) void mma_dense_kernel(
    const float4* __restrict__ X4, const float4* __restrict__ Hin,
    const int* __restrict__ offs, const int* __restrict__ csr,
    const uint8_t* __restrict__ whi, const uint8_t* __restrict__ wlo,
    const float* __restrict__ bias, const int* __restrict__ sdeg,
    float* __restrict__ Hout, int n, int tiles)
{
    extern __shared__ uint8_t sm[];
    uint8_t* a_hi = sm;
    uint8_t* a_lo = sm + 69632;
    float* bias_sm = (float*)(sm + 208896);
    float* red1    = (float*)(sm + 209408);
    float* red2    = (float*)(sm + 211456);

    const int tid = threadIdx.x, wid = tid >> 5, lane = tid & 31;
    const int sub  = wid >> 3;
    const int mrow = (wid & 3) * 32 + sub * 128;
    const int ch   = (wid >> 2) & 1;
    const int ncol = ch * 64;
    const int q2   = (lane & 3) * 2;

    for (int idx = tid; idx < 2176; idx += 512) {
        ((uint4*)(sm + 139264))[idx] = ((const uint4*)whi)[idx];
        ((uint4*)(sm + 174080))[idx] = ((const uint4*)wlo)[idx];
    }
    if (tid < 128) bias_sm[tid] = bias[tid];
    __syncthreads();

    float brg[16];
    #pragma unroll
    for (int nf = 0; nf < 8; ++nf) {
        brg[2 * nf]     = bias_sm[ncol + nf * 8 + q2];
        brg[2 * nf + 1] = bias_sm[ncol + nf * 8 + q2 + 1];
    }
    int rl[4];
    #pragma unroll
    for (int ri = 0; ri < 4; ++ri)
        rl[ri] = mrow + (ri >> 1) * 16 + (ri & 1) * 8 + (lane >> 2);

    const uint32_t smb  = smem_u32(sm);
    const uint32_t aoff = (lane & 15) * PKB + (lane >> 4) * 16;
    const uint32_t boff = ((lane >> 4) * 8 + (lane & 7)) * PKB + ((lane >> 3) & 1) * 16;
    const uint32_t aH = smb + mrow * PKB + aoff;
    const uint32_t aL = smb + 69632 + mrow * PKB + aoff;
    const uint32_t bH = smb + 139264 + ncol * PKB + boff;
    const uint32_t bL = smb + 174080 + ncol * PKB + boff;

    for (int t = blockIdx.x; t < tiles; t += gridDim.x) {
        const int row0 = t * 256;
        __syncthreads();
        if (csr) stage_gather_mma<16, 256>(Hin, offs, csr, a_hi, a_lo, row0, n, wid, lane);
        else     stage_rows_mma<16>(X4, a_hi, a_lo, row0, n, wid, lane);
        __syncthreads();

        float acc[2][8][4];
        #pragma unroll
        for (int a = 0; a < 2; ++a)
            #pragma unroll
            for (int b = 0; b < 8; ++b)
                #pragma unroll
                for (int c = 0; c < 4; ++c) acc[a][b][c] = 0.f;

        mma_block_t<4>(acc, aH, aL, bH, bL);

        float rmax[4];
        #pragma unroll
        for (int ri = 0; ri < 4; ++ri) {
            const int mt = ri >> 1, h8 = (ri & 1) * 2;
            float m = -3.4e38f;
            #pragma unroll
            for (int nf = 0; nf < 8; ++nf) {
                float x0 = fmaxf(acc[mt][nf][h8]     + brg[2 * nf],     0.f);
                float x1 = fmaxf(acc[mt][nf][h8 + 1] + brg[2 * nf + 1], 0.f);
                acc[mt][nf][h8] = x0; acc[mt][nf][h8 + 1] = x1;
                m = fmaxf(m, fmaxf(x0, x1));
            }
            m = fmaxf(m, __shfl_xor_sync(0xffffffffu, m, 1));
            m = fmaxf(m, __shfl_xor_sync(0xffffffffu, m, 2));
            rmax[ri] = m;
            red1[ch * 256 + rl[ri]] = m;
        }
        __syncthreads();
        #pragma unroll
        for (int ri = 0; ri < 4; ++ri) {
            const int mt = ri >> 1, h8 = (ri & 1) * 2;
            float m = fmaxf(rmax[ri], red1[(ch ^ 1) * 256 + rl[ri]]);
            float s = 0.f;
            #pragma unroll
            for (int nf = 0; nf < 8; ++nf) {
                float v0 = __expf(acc[mt][nf][h8] - m);
                float v1 = __expf(acc[mt][nf][h8 + 1] - m);
                acc[mt][nf][h8] = v0; acc[mt][nf][h8 + 1] = v1;
                s += v0 + v1;
            }
            s += __shfl_xor_sync(0xffffffffu, s, 1);
            s += __shfl_xor_sync(0xffffffffu, s, 2);
            red2[ch * 256 + rl[ri]] = s;
        }
        __syncthreads();
        #pragma unroll
        for (int ri = 0; ri < 4; ++ri) {
            const int mt = ri >> 1, h8 = (ri & 1) * 2;
            const int i = row0 + rl[ri];
            if (i >= n) continue;
            float s = red2[rl[ri]] + red2[256 + rl[ri]];
            float scl = rsqrtf(fmaxf((float)__ldg(&sdeg[i]), 1.f)) / s;
            float* op = Hout + (size_t)i * HID + ncol;
            #pragma unroll
            for (int nf = 0; nf < 8; ++nf)
                *(float2*)(op + nf * 8 + q2) =
                    make_float2(acc[mt][nf][h8] * scl, acc[mt][nf][h8 + 1] * scl);
        }
    }
}

// ---------------- final: 512 threads, m32xn32 warps, K=256 two-pass ------------------
#define FINAL_SMEM 209408
__global__ __launch_bounds__(512, 1) void mma_final_kernel(
    const float4* __restrict__ Hin, const int* __restrict__ offs,
    const int* __restrict__ csr, const float4* __restrict__ nodes4,
    const uint8_t* __restrict__ w0hi, const uint8_t* __restrict__ w0lo,
    const uint8_t* __restrict__ w1hi, const uint8_t* __restrict__ w1lo,
    const float* __restrict__ bmu, const float* __restrict__ bls,
    float* __restrict__ out, int n, int tiles)
{
    extern __shared__ uint8_t sm[];
    uint8_t* a_hi = sm;
    uint8_t* a_lo = sm + 34816;
    float* bias_sm = (float*)(sm + 208896);

    const int tid = threadIdx.x, wid = tid >> 5, lane = tid & 31;
    const int mrow = (wid & 3) * 32;
    const int nsub = (wid >> 2) & 1;
    const int ch   = wid >> 3;
    const int ncol = ch * 64 + nsub * 32;
    const int q2   = (lane & 3) * 2;

    for (int idx = tid; idx < 2176; idx += 512) {
        ((uint4*)(sm + 69632))[idx]  = ((const uint4*)w0hi)[idx];
        ((uint4*)(sm + 104448))[idx] = ((const uint4*)w0lo)[idx];
        ((uint4*)(sm + 139264))[idx] = ((const uint4*)w1hi)[idx];
        ((uint4*)(sm + 174080))[idx] = ((const uint4*)w1lo)[idx];
    }
    if (tid < 64) bias_sm[tid] = bmu[tid];
    else if (tid < 128) bias_sm[tid] = bls[tid - 64];
    __syncthreads();

    float brg[8];
    #pragma unroll
    for (int nf = 0; nf < 4; ++nf) {
        brg[2 * nf]     = bias_sm[ncol + nf * 8 + q2];
        brg[2 * nf + 1] = bias_sm[ncol + nf * 8 + q2 + 1];
    }
    int rl[4];
    #pragma unroll
    for (int ri = 0; ri < 4; ++ri)
        rl[ri] = mrow + (ri >> 1) * 16 + (ri & 1) * 8 + (lane >> 2);

    const uint32_t smb  = smem_u32(sm);
    const uint32_t aoff = (lane & 15) * PKB + (lane >> 4) * 16;
    const uint32_t boff = ((lane >> 4) * 8 + (lane & 7)) * PKB + ((lane >> 3) & 1) * 16;
    const uint32_t aH  = smb + mrow * PKB + aoff;
    const uint32_t aL  = smb + 34816 + mrow * PKB + aoff;
    const uint32_t b0H = smb + 69632 + ncol * PKB + boff;
    const uint32_t b0L = smb + 104448 + ncol * PKB + boff;
    const uint32_t b1H = smb + 139264 + ncol * PKB + boff;
    const uint32_t b1L = smb + 174080 + ncol * PKB + boff;

    const int cc0 = nsub * 32;

    for (int t = blockIdx.x; t < tiles; t += gridDim.x) {
        const int row0 = t * 128;

        float acc[2][4][4];
        #pragma unroll
        for (int a = 0; a < 2; ++a)
            #pragma unroll
            for (int b = 0; b < 4; ++b)
                #pragma unroll
                for (int c = 0; c < 4; ++c) acc[a][b][c] = 0.f;

        __syncthreads();
        stage_gather_mma<16, 128>(Hin, offs, csr, a_hi, a_lo, row0, n, wid, lane);
        __syncthreads();
        mma_block_t<2>(acc, aH, aL, b0H, b0L);

        __syncthreads();
        stage_rows_half(nodes4, a_hi, a_lo, row0, n, wid, lane);
        __syncthreads();
        mma_block_t<2>(acc, aH, aL, b1H, b1L);

        #pragma unroll
        for (int ri = 0; ri < 4; ++ri) {
            const int mt = ri >> 1, h8 = (ri & 1) * 2;
            const int i = row0 + rl[ri];
            if (i >= n) continue;
            float* op = out + (ch ? (size_t)n * ZDIM : 0) + (size_t)i * ZDIM + cc0;
            #pragma unroll
            for (int nf = 0; nf < 4; ++nf)
                *(float2*)(op + nf * 8 + q2) =
                    make_float2(acc[mt][nf][h8]     + brg[2 * nf],
                                acc[mt][nf][h8 + 1] + brg[2 * nf + 1]);
        }
    }
}

// ---------------- launch -------------------------------------------------------------
extern "C" void kernel_launch(void* const* d_in, const int* in_sizes, int n_in,
                              void* d_out, int out_size)
{
    const float* nodes = (const float*)d_in[0];
    const int*   snd   = (const int*)d_in[1];
    const int*   rcv   = (const int*)d_in[2];
    const float* W0    = (const float*)d_in[3];
    const float* b0    = (const float*)d_in[4];
    const float* W1    = (const float*)d_in[5];
    const float* b1    = (const float*)d_in[6];
    const float* Wmu   = (const float*)d_in[7];
    const float* bmu   = (const float*)d_in[8];
    const float* Wls   = (const float*)d_in[9];
    const float* bls   = (const float*)d_in[10];
    float* out = (float*)d_out;

    const int n = in_sizes[0] / FIN;
    const int E = in_sizes[1];

    float *h, *h2;
    int *sdeg, *rdeg, *offs, *cursor, *csr, *bsum;
    uint8_t *w0p, *w1p, *wfp;
    cudaGetSymbolAddress((void**)&h,      g_h);
    cudaGetSymbolAddress((void**)&h2,     g_h2);
    cudaGetSymbolAddress((void**)&sdeg,   g_sdeg);
    cudaGetSymbolAddress((void**)&rdeg,   g_rdeg);
    cudaGetSymbolAddress((void**)&offs,   g_offs);
    cudaGetSymbolAddress((void**)&cursor, g_cursor);
    cudaGetSymbolAddress((void**)&csr,    g_csr);
    cudaGetSymbolAddress((void**)&bsum,   g_bsum);
    cudaGetSymbolAddress((void**)&w0p,    g_w0p);
    cudaGetSymbolAddress((void**)&w1p,    g_w1p);
    cudaGetSymbolAddress((void**)&wfp,    g_wfp);

    cudaFuncSetAttribute(mma_dense_kernel, cudaFuncAttributeMaxDynamicSharedMemorySize, MMA_SMEM);
    cudaFuncSetAttribute(mma_final_kernel, cudaFuncAttributeMaxDynamicSharedMemorySize, FINAL_SMEM);

    const int tiles256 = (n + 255) / 256;
    const int tiles128 = (n + 127) / 128;
    const int IMG = 128 * PKB;
    const int pzBlocks = ((n > 65536 ? n : 65536) + 255) / 256;
    const int NB = (n + 2047) / 2048;    // scan blocks (<=128 for n<=262144)

    // 0: fused prep + degree-zero
    prep_zero_kernel<<<pzBlocks, 256>>>(W0, W1, Wmu, Wls, sdeg, rdeg, n);
    // 1: degree count
    count_deg_kernel<<<(E + 255) / 256, 256>>>(snd, rcv, sdeg, rdeg, E);

    // 2-4: multi-block scan of rdeg -> offs/cursor
    scan_reduce_kernel<<<NB, 256>>>(rdeg, bsum, n);
    scan_bsums_kernel<<<1, 32>>>(bsum, NB, offs, n);
    scan_apply_kernel<<<NB, 256>>>(rdeg, bsum, offs, cursor, n);

    // 5: CSR fill
    fill_kernel<<<(E + 255) / 256, 256>>>(snd, rcv, cursor, csr, E);

    // 6: layer-1 dense (coalesced staging)
    mma_dense_kernel<<<148, 512, MMA_SMEM>>>(
        (const float4*)nodes, nullptr, nullptr, nullptr,
        w0p, w0p + IMG, b0, sdeg, h, n, tiles256);

    // 7: layer-2 dense (fused interleaved gather) — reads h, writes h2
    mma_dense_kernel<<<148, 512, MMA_SMEM>>>(
        nullptr, (const float4*)h, offs, csr,
        w1p, w1p + IMG, b1, sdeg, h2, n, tiles256);

    // 8: final heads (fused gather + concat)
    mma_final_kernel<<<148, 512, FINAL_SMEM>>>(
        (const float4*)h2, offs, csr, (const float4*)nodes,
        wfp, wfp + IMG, wfp + 2 * IMG, wfp + 3 * IMG,
        bmu, bls, out, n, tiles128);
}